// round 2
// baseline (speedup 1.0000x reference)
#include <cuda_runtime.h>
#include <math.h>

#define NN 30
#define FF 4
#define HH 64
#define EE 870
#define CC 64
#define NSAMP 2048          // 32 * 64
#define TOUT 127
#define VAROFF (32*127*30*4)

// Scratch (allocation-free rule: __device__ globals)
__device__ float g_agg[(size_t)NSAMP * NN * HH];   // 15.7 MB
__device__ float g_mu [(size_t)NSAMP * NN * FF];   // 0.98 MB

// ---------------------------------------------------------------------------
// Edge kernel: per sample, compute agg[i] = (sum_j g_ij * relu(A_i + B_j)) @ W2
//                                           + (sum_j g_ij) * b2
// A = x @ W1[0:4] + b1 ; B = x @ W1[4:8]
// ---------------------------------------------------------------------------
__global__ __launch_bounds__(256) void edge_kernel(
    const float* __restrict__ data, int mode,
    const float* __restrict__ graph,
    const float* __restrict__ W1, const float* __restrict__ b1,
    const float* __restrict__ W2, const float* __restrict__ b2)
{
    __shared__ float sW1[8*64];
    __shared__ float sb1[64];
    __shared__ float sW2[64*64];
    __shared__ float sb2[64];
    __shared__ float sx[NN*FF];
    __shared__ float sA[NN][HH];
    __shared__ float sB[NN][HH];
    __shared__ float sH[NN][HH];
    __shared__ float sg[EE];
    __shared__ float scnt[NN];

    const int tid = threadIdx.x;
    const int s   = blockIdx.x;
    const int bs  = s >> 6;
    const int c   = s & 63;

    for (int i = tid; i < 8*64;  i += 256) sW1[i] = W1[i];
    for (int i = tid; i < 64*64; i += 256) sW2[i] = W2[i];
    if (tid < 64) { sb1[tid] = b1[tid]; sb2[tid] = b2[tid]; }
    for (int i = tid; i < EE; i += 256) sg[i] = graph[bs*EE + i];
    if (tid < NN*FF) {
        sx[tid] = (mode == 0)
            ? data[((size_t)bs*128 + 2*c) * (NN*FF) + tid]   // data[:, ::2]
            : g_mu[(size_t)s * (NN*FF) + tid];
    }
    __syncthreads();

    // Per-node projections
    for (int idx = tid; idx < NN*HH; idx += 256) {
        int n = idx >> 6, o = idx & 63;
        float x0 = sx[n*4+0], x1 = sx[n*4+1], x2 = sx[n*4+2], x3 = sx[n*4+3];
        float a = sb1[o];
        a = fmaf(x0, sW1[0*64+o], a);
        a = fmaf(x1, sW1[1*64+o], a);
        a = fmaf(x2, sW1[2*64+o], a);
        a = fmaf(x3, sW1[3*64+o], a);
        float bb = x0 * sW1[4*64+o];
        bb = fmaf(x1, sW1[5*64+o], bb);
        bb = fmaf(x2, sW1[6*64+o], bb);
        bb = fmaf(x3, sW1[7*64+o], bb);
        sA[n][o] = a;
        sB[n][o] = bb;
    }
    __syncthreads();

    // Masked-ReLU aggregation over the 29 senders of each recv node.
    // 240 threads: (node i, 8-wide output group og). No atomics.
    if (tid < 240) {
        const int i  = tid >> 3;
        const int og = (tid & 7) << 3;
        float a[8], acc[8];
        #pragma unroll
        for (int u = 0; u < 8; u++) { a[u] = sA[i][og+u]; acc[u] = 0.f; }
        float cnt = 0.f;
        const int ebase = i * 29;
        #pragma unroll 4
        for (int jj = 0; jj < 29; jj++) {
            int j = jj + (jj >= i);
            float g = sg[ebase + jj];
            cnt += g;
            const float4* bp = reinterpret_cast<const float4*>(&sB[j][og]);
            float4 b0 = bp[0], b1v = bp[1];
            acc[0] = fmaf(g, fmaxf(a[0]+b0.x, 0.f), acc[0]);
            acc[1] = fmaf(g, fmaxf(a[1]+b0.y, 0.f), acc[1]);
            acc[2] = fmaf(g, fmaxf(a[2]+b0.z, 0.f), acc[2]);
            acc[3] = fmaf(g, fmaxf(a[3]+b0.w, 0.f), acc[3]);
            acc[4] = fmaf(g, fmaxf(a[4]+b1v.x, 0.f), acc[4]);
            acc[5] = fmaf(g, fmaxf(a[5]+b1v.y, 0.f), acc[5]);
            acc[6] = fmaf(g, fmaxf(a[6]+b1v.z, 0.f), acc[6]);
            acc[7] = fmaf(g, fmaxf(a[7]+b1v.w, 0.f), acc[7]);
        }
        #pragma unroll
        for (int u = 0; u < 8; u++) sH[i][og+u] = acc[u];
        if ((tid & 7) == 0) scnt[i] = cnt;
    }
    __syncthreads();

    // agg = H @ W2 + cnt * b2  (per node, 30x64 @ 64x64)
    if (tid < 240) {
        const int i  = tid >> 3;
        const int og = (tid & 7) << 3;
        const float cnt = scnt[i];
        float acc[8];
        #pragma unroll
        for (int u = 0; u < 8; u++) acc[u] = cnt * sb2[og+u];
        #pragma unroll 4
        for (int k = 0; k < 64; k++) {
            float h = sH[i][k];
            const float4* wp = reinterpret_cast<const float4*>(&sW2[k*64+og]);
            float4 w0 = wp[0], w1 = wp[1];
            acc[0] = fmaf(h, w0.x, acc[0]);
            acc[1] = fmaf(h, w0.y, acc[1]);
            acc[2] = fmaf(h, w0.z, acc[2]);
            acc[3] = fmaf(h, w0.w, acc[3]);
            acc[4] = fmaf(h, w1.x, acc[4]);
            acc[5] = fmaf(h, w1.y, acc[5]);
            acc[6] = fmaf(h, w1.z, acc[6]);
            acc[7] = fmaf(h, w1.w, acc[7]);
        }
        float* out = &g_agg[((size_t)s*NN + i) * HH + og];
        #pragma unroll
        for (int u = 0; u < 8; u++) out[u] = acc[u];
    }
}

// ---------------------------------------------------------------------------
// Node MLP kernel: 64 ->relu-> 64 ->relu-> 64 -> 4 (+ optional softplus/clip)
// One CTA per sample. W3/b3 read through L1 (smem budget).
// ---------------------------------------------------------------------------
__global__ __launch_bounds__(256) void node_kernel(
    const float* __restrict__ W1, const float* __restrict__ b1,
    const float* __restrict__ W2, const float* __restrict__ b2,
    const float* __restrict__ W3, const float* __restrict__ b3,
    float* __restrict__ out, int t, int is_var, int write_prev)
{
    __shared__ float sW1[64*64];
    __shared__ float sW2[64*64];
    __shared__ float sb1[64], sb2[64];
    __shared__ float bufA[NN][HH];
    __shared__ float bufB[NN][HH];

    const int tid = threadIdx.x;
    const int s   = blockIdx.x;
    const int bs  = s >> 6;
    const int c   = s & 63;

    for (int i = tid; i < 64*64; i += 256) { sW1[i] = W1[i]; sW2[i] = W2[i]; }
    if (tid < 64) { sb1[tid] = b1[tid]; sb2[tid] = b2[tid]; }
    for (int i = tid; i < NN*HH; i += 256)
        bufA[i >> 6][i & 63] = g_agg[(size_t)s * (NN*HH) + i];
    __syncthreads();

    // Layer 1: bufB = relu(bufA @ W1 + b1)
    if (tid < 240) {
        const int i  = tid >> 3;
        const int og = (tid & 7) << 3;
        float acc[8];
        #pragma unroll
        for (int u = 0; u < 8; u++) acc[u] = sb1[og+u];
        #pragma unroll 4
        for (int k = 0; k < 64; k++) {
            float h = bufA[i][k];
            const float4* wp = reinterpret_cast<const float4*>(&sW1[k*64+og]);
            float4 w0 = wp[0], w1 = wp[1];
            acc[0] = fmaf(h, w0.x, acc[0]);
            acc[1] = fmaf(h, w0.y, acc[1]);
            acc[2] = fmaf(h, w0.z, acc[2]);
            acc[3] = fmaf(h, w0.w, acc[3]);
            acc[4] = fmaf(h, w1.x, acc[4]);
            acc[5] = fmaf(h, w1.y, acc[5]);
            acc[6] = fmaf(h, w1.z, acc[6]);
            acc[7] = fmaf(h, w1.w, acc[7]);
        }
        #pragma unroll
        for (int u = 0; u < 8; u++) bufB[i][og+u] = fmaxf(acc[u], 0.f);
    }
    __syncthreads();

    // Layer 2: bufA = relu(bufB @ W2 + b2)
    if (tid < 240) {
        const int i  = tid >> 3;
        const int og = (tid & 7) << 3;
        float acc[8];
        #pragma unroll
        for (int u = 0; u < 8; u++) acc[u] = sb2[og+u];
        #pragma unroll 4
        for (int k = 0; k < 64; k++) {
            float h = bufB[i][k];
            const float4* wp = reinterpret_cast<const float4*>(&sW2[k*64+og]);
            float4 w0 = wp[0], w1 = wp[1];
            acc[0] = fmaf(h, w0.x, acc[0]);
            acc[1] = fmaf(h, w0.y, acc[1]);
            acc[2] = fmaf(h, w0.z, acc[2]);
            acc[3] = fmaf(h, w0.w, acc[3]);
            acc[4] = fmaf(h, w1.x, acc[4]);
            acc[5] = fmaf(h, w1.y, acc[5]);
            acc[6] = fmaf(h, w1.z, acc[6]);
            acc[7] = fmaf(h, w1.w, acc[7]);
        }
        #pragma unroll
        for (int u = 0; u < 8; u++) bufA[i][og+u] = fmaxf(acc[u], 0.f);
    }
    __syncthreads();

    // Layer 3: 64 -> 4, write outputs
    if (tid < NN*FF) {
        const int n = tid >> 2, f = tid & 3;
        float acc = __ldg(&b3[f]);
        #pragma unroll 8
        for (int k = 0; k < 64; k++)
            acc = fmaf(bufA[n][k], __ldg(&W3[k*4 + f]), acc);
        if (is_var) {
            float sp = (acc > 20.f) ? acc : log1pf(expf(acc));
            acc = fminf(fmaxf(sp, 1e-8f), 100.f);
        }
        if (write_prev) g_mu[(size_t)s * (NN*FF) + tid] = acc;
        const int kt = 2*c + t;
        if (kt < TOUT) {
            size_t o = (((size_t)bs*TOUT + kt)*NN + n)*FF + f;
            out[o + (is_var ? (size_t)VAROFF : 0)] = acc;
        }
    }
}

// ---------------------------------------------------------------------------
extern "C" void kernel_launch(void* const* d_in, const int* in_sizes, int n_in,
                              void* d_out, int out_size) {
    const float* data    = (const float*)d_in[0];
    const float* graph   = (const float*)d_in[1];
    const float* msg_W1  = (const float*)d_in[2];
    const float* msg_b1  = (const float*)d_in[3];
    const float* msg_W2  = (const float*)d_in[4];
    const float* msg_b2  = (const float*)d_in[5];
    const float* mean_W1 = (const float*)d_in[6];
    const float* mean_b1 = (const float*)d_in[7];
    const float* mean_W2 = (const float*)d_in[8];
    const float* mean_b2 = (const float*)d_in[9];
    const float* mean_W3 = (const float*)d_in[10];
    const float* mean_b3 = (const float*)d_in[11];
    const float* var_W1  = (const float*)d_in[12];
    const float* var_b1  = (const float*)d_in[13];
    const float* var_W2  = (const float*)d_in[14];
    const float* var_b2  = (const float*)d_in[15];
    const float* var_W3  = (const float*)d_in[16];
    const float* var_b3  = (const float*)d_in[17];
    float* out = (float*)d_out;

    for (int t = 0; t < 2; t++) {
        edge_kernel<<<NSAMP, 256>>>(data, t, graph,
                                    msg_W1, msg_b1, msg_W2, msg_b2);
        node_kernel<<<NSAMP, 256>>>(mean_W1, mean_b1, mean_W2, mean_b2,
                                    mean_W3, mean_b3, out, t, 0, (t == 0) ? 1 : 0);
        node_kernel<<<NSAMP, 256>>>(var_W1, var_b1, var_W2, var_b2,
                                    var_W3, var_b3, out, t, 1, 0);
    }
}

// round 3
// speedup vs baseline: 1.7471x; 1.7471x over previous
#include <cuda_runtime.h>
#include <math.h>

#define NN 30
#define FF 4
#define HH 64
#define EE 870
#define NSAMP 2048          // 32 * 64
#define TOUT 127
#define VAROFF (32*127*30*4)

// Scratch (allocation-free rule: __device__ globals)
__device__ float g_agg[(size_t)NSAMP * NN * HH];   // 15.7 MB
__device__ float g_mu [(size_t)NSAMP * NN * FF];   // 0.98 MB

// ---------------------------------------------------------------------------
// Edge kernel: per sample, agg[i] = (sum_j g_ij * relu(A_i + B_j)) @ W2
//                                   + (sum_j g_ij) * b2
// A = x @ W1[0:4] + b1 ; B = x @ W1[4:8]
// 128 threads; compute stages use 120 threads = 15 row-pairs x 8 col-groups.
// ---------------------------------------------------------------------------
__global__ __launch_bounds__(128) void edge_kernel(
    const float* __restrict__ data, int mode,
    const float* __restrict__ graph,
    const float* __restrict__ W1, const float* __restrict__ b1,
    const float* __restrict__ W2, const float* __restrict__ b2)
{
    __shared__ float sW1[8*64];
    __shared__ float sb1[64];
    __shared__ float sW2[64*64];
    __shared__ float sb2[64];
    __shared__ float sx[NN*FF];
    __shared__ float sA[NN][HH];
    __shared__ float sB[NN][HH];
    __shared__ float sH[NN][HH];
    __shared__ float sg[EE];
    __shared__ float scnt[NN];

    const int tid = threadIdx.x;
    const int s   = blockIdx.x;
    const int bs  = s >> 6;
    const int c   = s & 63;

    for (int i = tid; i < 8*64; i += 128) sW1[i] = W1[i];
    {
        const float4* w2v = reinterpret_cast<const float4*>(W2);
        float4* sw2v = reinterpret_cast<float4*>(sW2);
        for (int i = tid; i < 1024; i += 128) sw2v[i] = w2v[i];
    }
    if (tid < 64) { sb1[tid] = b1[tid]; sb2[tid] = b2[tid]; }
    for (int i = tid; i < EE; i += 128) sg[i] = graph[bs*EE + i];
    if (tid < NN*FF) {
        sx[tid] = (mode == 0)
            ? data[((size_t)bs*128 + 2*c) * (NN*FF) + tid]   // data[:, ::2]
            : g_mu[(size_t)s * (NN*FF) + tid];
    }
    __syncthreads();

    // Per-node projections: 120 threads = 30 nodes x 4 groups of 16 outputs
    if (tid < 120) {
        const int n   = tid >> 2;
        const int o16 = (tid & 3) << 4;
        float4 xv = *reinterpret_cast<const float4*>(&sx[n*4]);
        float x[4] = {xv.x, xv.y, xv.z, xv.w};
        float a[16], bb[16];
        #pragma unroll
        for (int u = 0; u < 16; u++) { a[u] = sb1[o16+u]; bb[u] = 0.f; }
        #pragma unroll
        for (int r = 0; r < 4; r++) {
            float xr = x[r];
            #pragma unroll
            for (int u = 0; u < 16; u++)
                a[u] = fmaf(xr, sW1[r*64 + o16 + u], a[u]);
        }
        #pragma unroll
        for (int r = 0; r < 4; r++) {
            float xr = x[r];
            #pragma unroll
            for (int u = 0; u < 16; u++)
                bb[u] = fmaf(xr, sW1[(r+4)*64 + o16 + u], bb[u]);
        }
        #pragma unroll
        for (int u = 0; u < 16; u += 4) {
            *reinterpret_cast<float4*>(&sA[n][o16+u]) =
                make_float4(a[u], a[u+1], a[u+2], a[u+3]);
            *reinterpret_cast<float4*>(&sB[n][o16+u]) =
                make_float4(bb[u], bb[u+1], bb[u+2], bb[u+3]);
        }
    }
    __syncthreads();

    // Masked-ReLU aggregation. 120 threads = 15 row-pairs x 8 col-groups.
    // Each thread handles recv nodes {i0, i0+1}, 8 outputs; B[j] load shared.
    if (tid < 120) {
        const int ig = tid >> 3, cg = tid & 7;
        const int i0 = ig << 1, i1 = i0 + 1;
        const int og = cg << 3;
        float a0[8], a1[8], acc0[8], acc1[8];
        #pragma unroll
        for (int u = 0; u < 8; u++) {
            a0[u] = sA[i0][og+u]; a1[u] = sA[i1][og+u];
            acc0[u] = 0.f; acc1[u] = 0.f;
        }
        float cnt0 = 0.f, cnt1 = 0.f;
        #pragma unroll 6
        for (int j = 0; j < NN; j++) {
            float4 b0 = *reinterpret_cast<const float4*>(&sB[j][og]);
            float4 b1v = *reinterpret_cast<const float4*>(&sB[j][og+4]);
            float bb[8] = {b0.x, b0.y, b0.z, b0.w, b1v.x, b1v.y, b1v.z, b1v.w};
            float g0 = (j != i0) ? sg[i0*29 + j - (j > i0)] : 0.f;
            float g1 = (j != i1) ? sg[i1*29 + j - (j > i1)] : 0.f;
            cnt0 += g0; cnt1 += g1;
            #pragma unroll
            for (int u = 0; u < 8; u++) {
                acc0[u] = fmaf(g0, fmaxf(a0[u] + bb[u], 0.f), acc0[u]);
                acc1[u] = fmaf(g1, fmaxf(a1[u] + bb[u], 0.f), acc1[u]);
            }
        }
        *reinterpret_cast<float4*>(&sH[i0][og])   = make_float4(acc0[0],acc0[1],acc0[2],acc0[3]);
        *reinterpret_cast<float4*>(&sH[i0][og+4]) = make_float4(acc0[4],acc0[5],acc0[6],acc0[7]);
        *reinterpret_cast<float4*>(&sH[i1][og])   = make_float4(acc1[0],acc1[1],acc1[2],acc1[3]);
        *reinterpret_cast<float4*>(&sH[i1][og+4]) = make_float4(acc1[4],acc1[5],acc1[6],acc1[7]);
        if (cg == 0) { scnt[i0] = cnt0; scnt[i1] = cnt1; }
    }
    __syncthreads();

    // agg = H @ W2 + cnt * b2  (30x64 @ 64x64), 2-row x 8-col register tile
    if (tid < 120) {
        const int ig = tid >> 3, cg = tid & 7;
        const int i0 = ig << 1, i1 = i0 + 1;
        const int og = cg << 3;
        const float cnt0 = scnt[i0], cnt1 = scnt[i1];
        float acc0[8], acc1[8];
        #pragma unroll
        for (int u = 0; u < 8; u++) {
            float bv = sb2[og+u];
            acc0[u] = cnt0 * bv; acc1[u] = cnt1 * bv;
        }
        #pragma unroll 4
        for (int k4 = 0; k4 < 64; k4 += 4) {
            float4 h0v = *reinterpret_cast<const float4*>(&sH[i0][k4]);
            float4 h1v = *reinterpret_cast<const float4*>(&sH[i1][k4]);
            float h0a[4] = {h0v.x, h0v.y, h0v.z, h0v.w};
            float h1a[4] = {h1v.x, h1v.y, h1v.z, h1v.w};
            #pragma unroll
            for (int kk = 0; kk < 4; kk++) {
                const float4* wp = reinterpret_cast<const float4*>(&sW2[(k4+kk)*64 + og]);
                float4 w0 = wp[0], w1 = wp[1];
                float wv[8] = {w0.x, w0.y, w0.z, w0.w, w1.x, w1.y, w1.z, w1.w};
                #pragma unroll
                for (int u = 0; u < 8; u++) {
                    acc0[u] = fmaf(h0a[kk], wv[u], acc0[u]);
                    acc1[u] = fmaf(h1a[kk], wv[u], acc1[u]);
                }
            }
        }
        float* o0 = &g_agg[((size_t)s*NN + i0) * HH + og];
        float* o1 = &g_agg[((size_t)s*NN + i1) * HH + og];
        *reinterpret_cast<float4*>(o0)   = make_float4(acc0[0],acc0[1],acc0[2],acc0[3]);
        *reinterpret_cast<float4*>(o0+4) = make_float4(acc0[4],acc0[5],acc0[6],acc0[7]);
        *reinterpret_cast<float4*>(o1)   = make_float4(acc1[0],acc1[1],acc1[2],acc1[3]);
        *reinterpret_cast<float4*>(o1+4) = make_float4(acc1[4],acc1[5],acc1[6],acc1[7]);
    }
}

// ---------------------------------------------------------------------------
// Node MLP kernel: 64 ->relu-> 64 ->relu-> 64 -> 4 (+ optional softplus/clip)
// One CTA per sample, 128 threads, 2-row x 8-col register tiles.
// ---------------------------------------------------------------------------
__global__ __launch_bounds__(128) void node_kernel(
    const float* __restrict__ W1, const float* __restrict__ b1,
    const float* __restrict__ W2, const float* __restrict__ b2,
    const float* __restrict__ W3, const float* __restrict__ b3,
    float* __restrict__ out, int t, int is_var, int write_prev)
{
    __shared__ float sW1[64*64];
    __shared__ float sW2[64*64];
    __shared__ float sb1[64], sb2[64];
    __shared__ float bufA[NN][HH];
    __shared__ float bufB[NN][HH];

    const int tid = threadIdx.x;
    const int s   = blockIdx.x;
    const int bs  = s >> 6;
    const int c   = s & 63;

    {
        const float4* w1v = reinterpret_cast<const float4*>(W1);
        const float4* w2v = reinterpret_cast<const float4*>(W2);
        float4* s1 = reinterpret_cast<float4*>(sW1);
        float4* s2 = reinterpret_cast<float4*>(sW2);
        for (int i = tid; i < 1024; i += 128) { s1[i] = w1v[i]; s2[i] = w2v[i]; }
    }
    if (tid < 64) { sb1[tid] = b1[tid]; sb2[tid] = b2[tid]; }
    {
        const float4* av = reinterpret_cast<const float4*>(&g_agg[(size_t)s * (NN*HH)]);
        float4* ba = reinterpret_cast<float4*>(&bufA[0][0]);
        for (int i = tid; i < NN*HH/4; i += 128) ba[i] = av[i];
    }
    __syncthreads();

    const int ig = tid >> 3, cg = tid & 7;
    const int i0 = ig << 1, i1 = i0 + 1;
    const int og = cg << 3;

    // Layer 1: bufB = relu(bufA @ W1 + b1)
    if (tid < 120) {
        float acc0[8], acc1[8];
        #pragma unroll
        for (int u = 0; u < 8; u++) { acc0[u] = sb1[og+u]; acc1[u] = sb1[og+u]; }
        #pragma unroll 4
        for (int k4 = 0; k4 < 64; k4 += 4) {
            float4 h0v = *reinterpret_cast<const float4*>(&bufA[i0][k4]);
            float4 h1v = *reinterpret_cast<const float4*>(&bufA[i1][k4]);
            float h0a[4] = {h0v.x, h0v.y, h0v.z, h0v.w};
            float h1a[4] = {h1v.x, h1v.y, h1v.z, h1v.w};
            #pragma unroll
            for (int kk = 0; kk < 4; kk++) {
                const float4* wp = reinterpret_cast<const float4*>(&sW1[(k4+kk)*64 + og]);
                float4 w0 = wp[0], w1 = wp[1];
                float wv[8] = {w0.x, w0.y, w0.z, w0.w, w1.x, w1.y, w1.z, w1.w};
                #pragma unroll
                for (int u = 0; u < 8; u++) {
                    acc0[u] = fmaf(h0a[kk], wv[u], acc0[u]);
                    acc1[u] = fmaf(h1a[kk], wv[u], acc1[u]);
                }
            }
        }
        *reinterpret_cast<float4*>(&bufB[i0][og])   = make_float4(fmaxf(acc0[0],0.f),fmaxf(acc0[1],0.f),fmaxf(acc0[2],0.f),fmaxf(acc0[3],0.f));
        *reinterpret_cast<float4*>(&bufB[i0][og+4]) = make_float4(fmaxf(acc0[4],0.f),fmaxf(acc0[5],0.f),fmaxf(acc0[6],0.f),fmaxf(acc0[7],0.f));
        *reinterpret_cast<float4*>(&bufB[i1][og])   = make_float4(fmaxf(acc1[0],0.f),fmaxf(acc1[1],0.f),fmaxf(acc1[2],0.f),fmaxf(acc1[3],0.f));
        *reinterpret_cast<float4*>(&bufB[i1][og+4]) = make_float4(fmaxf(acc1[4],0.f),fmaxf(acc1[5],0.f),fmaxf(acc1[6],0.f),fmaxf(acc1[7],0.f));
    }
    __syncthreads();

    // Layer 2: bufA = relu(bufB @ W2 + b2)
    if (tid < 120) {
        float acc0[8], acc1[8];
        #pragma unroll
        for (int u = 0; u < 8; u++) { acc0[u] = sb2[og+u]; acc1[u] = sb2[og+u]; }
        #pragma unroll 4
        for (int k4 = 0; k4 < 64; k4 += 4) {
            float4 h0v = *reinterpret_cast<const float4*>(&bufB[i0][k4]);
            float4 h1v = *reinterpret_cast<const float4*>(&bufB[i1][k4]);
            float h0a[4] = {h0v.x, h0v.y, h0v.z, h0v.w};
            float h1a[4] = {h1v.x, h1v.y, h1v.z, h1v.w};
            #pragma unroll
            for (int kk = 0; kk < 4; kk++) {
                const float4* wp = reinterpret_cast<const float4*>(&sW2[(k4+kk)*64 + og]);
                float4 w0 = wp[0], w1 = wp[1];
                float wv[8] = {w0.x, w0.y, w0.z, w0.w, w1.x, w1.y, w1.z, w1.w};
                #pragma unroll
                for (int u = 0; u < 8; u++) {
                    acc0[u] = fmaf(h0a[kk], wv[u], acc0[u]);
                    acc1[u] = fmaf(h1a[kk], wv[u], acc1[u]);
                }
            }
        }
        *reinterpret_cast<float4*>(&bufA[i0][og])   = make_float4(fmaxf(acc0[0],0.f),fmaxf(acc0[1],0.f),fmaxf(acc0[2],0.f),fmaxf(acc0[3],0.f));
        *reinterpret_cast<float4*>(&bufA[i0][og+4]) = make_float4(fmaxf(acc0[4],0.f),fmaxf(acc0[5],0.f),fmaxf(acc0[6],0.f),fmaxf(acc0[7],0.f));
        *reinterpret_cast<float4*>(&bufA[i1][og])   = make_float4(fmaxf(acc1[0],0.f),fmaxf(acc1[1],0.f),fmaxf(acc1[2],0.f),fmaxf(acc1[3],0.f));
        *reinterpret_cast<float4*>(&bufA[i1][og+4]) = make_float4(fmaxf(acc1[4],0.f),fmaxf(acc1[5],0.f),fmaxf(acc1[6],0.f),fmaxf(acc1[7],0.f));
    }
    __syncthreads();

    // Layer 3: 64 -> 4, write outputs
    if (tid < NN*FF) {
        const int n = tid >> 2, f = tid & 3;
        float acc = __ldg(&b3[f]);
        #pragma unroll 8
        for (int k = 0; k < 64; k++)
            acc = fmaf(bufA[n][k], __ldg(&W3[k*4 + f]), acc);
        if (is_var) {
            float sp = (acc > 20.f) ? acc : log1pf(expf(acc));
            acc = fminf(fmaxf(sp, 1e-8f), 100.f);
        }
        if (write_prev) g_mu[(size_t)s * (NN*FF) + tid] = acc;
        const int kt = 2*c + t;
        if (kt < TOUT) {
            size_t o = (((size_t)bs*TOUT + kt)*NN + n)*FF + f;
            out[o + (is_var ? (size_t)VAROFF : 0)] = acc;
        }
    }
}

// ---------------------------------------------------------------------------
extern "C" void kernel_launch(void* const* d_in, const int* in_sizes, int n_in,
                              void* d_out, int out_size) {
    const float* data    = (const float*)d_in[0];
    const float* graph   = (const float*)d_in[1];
    const float* msg_W1  = (const float*)d_in[2];
    const float* msg_b1  = (const float*)d_in[3];
    const float* msg_W2  = (const float*)d_in[4];
    const float* msg_b2  = (const float*)d_in[5];
    const float* mean_W1 = (const float*)d_in[6];
    const float* mean_b1 = (const float*)d_in[7];
    const float* mean_W2 = (const float*)d_in[8];
    const float* mean_b2 = (const float*)d_in[9];
    const float* mean_W3 = (const float*)d_in[10];
    const float* mean_b3 = (const float*)d_in[11];
    const float* var_W1  = (const float*)d_in[12];
    const float* var_b1  = (const float*)d_in[13];
    const float* var_W2  = (const float*)d_in[14];
    const float* var_b2  = (const float*)d_in[15];
    const float* var_W3  = (const float*)d_in[16];
    const float* var_b3  = (const float*)d_in[17];
    float* out = (float*)d_out;

    for (int t = 0; t < 2; t++) {
        edge_kernel<<<NSAMP, 128>>>(data, t, graph,
                                    msg_W1, msg_b1, msg_W2, msg_b2);
        node_kernel<<<NSAMP, 128>>>(mean_W1, mean_b1, mean_W2, mean_b2,
                                    mean_W3, mean_b3, out, t, 0, (t == 0) ? 1 : 0);
        node_kernel<<<NSAMP, 128>>>(var_W1, var_b1, var_W2, var_b2,
                                    var_W3, var_b3, out, t, 1, 0);
    }
}

// round 4
// speedup vs baseline: 1.7882x; 1.0235x over previous
#include <cuda_runtime.h>
#include <math.h>

typedef unsigned long long ull;

#define NN 30
#define FF 4
#define HH 64
#define EE 870
#define NSAMP 2048          // 32 * 64
#define TOUT 127
#define VAROFF (32*127*30*4)

// Scratch (allocation-free rule: __device__ globals)
__device__ float g_agg[(size_t)NSAMP * NN * HH];   // 15.7 MB
__device__ float g_mu [(size_t)NSAMP * NN * FF];   // 0.98 MB

// ---- packed f32x2 helpers (sm_103a) ---------------------------------------
#define FFMA2(acc, a, b) \
    asm("fma.rn.f32x2 %0, %1, %2, %0;" : "+l"(acc) : "l"(a), "l"(b))
#define PACKDUP(d, x) \
    asm("mov.b64 %0, {%1, %1};" : "=l"(d) : "r"(__float_as_uint(x)))
#define PACK2(d, x, y) \
    asm("mov.b64 %0, {%1, %2};" : "=l"(d) : "r"(__float_as_uint(x)), "r"(__float_as_uint(y)))
#define UNPACK2(x, y, p) \
    asm("mov.b64 {%0, %1}, %2;" : "=f"(x), "=f"(y) : "l"(p))
// acc += gdup * relu(apair + bpair)   (packed, relu via scalar max on halves)
#define AGG_STEP(acc, apair, bpair, gdup) \
    asm("{\n\t.reg .b32 lo, hi;\n\t.reg .b64 t;\n\t" \
        "add.rn.f32x2 t, %1, %2;\n\t" \
        "mov.b64 {lo, hi}, t;\n\t" \
        "max.f32 lo, lo, 0f00000000;\n\t" \
        "max.f32 hi, hi, 0f00000000;\n\t" \
        "mov.b64 t, {lo, hi};\n\t" \
        "fma.rn.f32x2 %0, %3, t, %0;\n\t}" \
        : "+l"(acc) : "l"(apair), "l"(bpair), "l"(gdup))

// ---------------------------------------------------------------------------
// Edge kernel: 2 samples per CTA (same bs -> shared graph row + weights).
// agg[i] = (sum_j g_ij * relu(A_i + B_j)) @ W2 + (sum_j g_ij) * b2
// ---------------------------------------------------------------------------
struct EdgeSmem {
    float sW1[8*64];
    float sW2[64*64];
    float sA[2][NN][HH];
    float sB[2][NN][HH];
    float sH[2][NN][HH];
    float sx[2][NN*FF];
    float sg[872];          // padded to 16B multiple
    float scnt[2][32];
    float sb1[64];
    float sb2[64];
};

__global__ __launch_bounds__(256) void edge_kernel(
    const float* __restrict__ data, int mode,
    const float* __restrict__ graph,
    const float* __restrict__ W1, const float* __restrict__ b1,
    const float* __restrict__ W2, const float* __restrict__ b2)
{
    extern __shared__ char smem_raw[];
    EdgeSmem& S = *reinterpret_cast<EdgeSmem*>(smem_raw);

    const int tid = threadIdx.x;
    const int p   = blockIdx.x;
    const int bs  = p >> 5;
    const int c0  = p & 31;

    // cooperative loads (256 threads)
    for (int i = tid; i < 512; i += 256) S.sW1[i] = W1[i];
    {
        const float4* w2v = reinterpret_cast<const float4*>(W2);
        float4* d = reinterpret_cast<float4*>(S.sW2);
        #pragma unroll
        for (int i = tid; i < 1024; i += 256) d[i] = w2v[i];
    }
    if (tid < 64) { S.sb1[tid] = b1[tid]; S.sb2[tid] = b2[tid]; }
    for (int i = tid; i < EE; i += 256) S.sg[i] = graph[bs*EE + i];
    if (tid < 240) {
        const int hh  = (tid >= 120) ? 1 : 0;
        const int idx = tid - 120*hh;
        const int cc  = c0 + 32*hh;
        const int ss  = bs*64 + cc;
        S.sx[hh][idx] = (mode == 0)
            ? data[((size_t)bs*128 + 2*cc) * (NN*FF) + idx]
            : g_mu[(size_t)ss * (NN*FF) + idx];
    }
    __syncthreads();

    const int half = tid >> 7;          // sample within CTA
    const int wt   = tid & 127;
    const int s    = bs*64 + c0 + 32*half;

    // Per-node projections: 120 threads/half = 30 nodes x 4 groups of 16
    if (wt < 120) {
        const int n   = wt >> 2;
        const int o16 = (wt & 3) << 4;
        float4 xv = *reinterpret_cast<const float4*>(&S.sx[half][n*4]);
        float x[4] = {xv.x, xv.y, xv.z, xv.w};
        float a[16], bb[16];
        #pragma unroll
        for (int u = 0; u < 16; u++) { a[u] = S.sb1[o16+u]; bb[u] = 0.f; }
        #pragma unroll
        for (int r = 0; r < 4; r++) {
            float xr = x[r];
            #pragma unroll
            for (int u = 0; u < 16; u++)
                a[u] = fmaf(xr, S.sW1[r*64 + o16 + u], a[u]);
        }
        #pragma unroll
        for (int r = 0; r < 4; r++) {
            float xr = x[r];
            #pragma unroll
            for (int u = 0; u < 16; u++)
                bb[u] = fmaf(xr, S.sW1[(r+4)*64 + o16 + u], bb[u]);
        }
        #pragma unroll
        for (int u = 0; u < 16; u += 4) {
            *reinterpret_cast<float4*>(&S.sA[half][n][o16+u]) =
                make_float4(a[u], a[u+1], a[u+2], a[u+3]);
            *reinterpret_cast<float4*>(&S.sB[half][n][o16+u]) =
                make_float4(bb[u], bb[u+1], bb[u+2], bb[u+3]);
        }
    }
    __syncthreads();

    const int ig = wt >> 3, cg = wt & 7;
    const int i0 = ig << 1, i1 = i0 + 1;
    const int og = cg << 3;

    // Masked-ReLU aggregation (packed f32x2)
    if (wt < 120) {
        ull a0[4], a1[4], acc0[4] = {0,0,0,0}, acc1[4] = {0,0,0,0};
        {
            const ulonglong2* pa0 = reinterpret_cast<const ulonglong2*>(&S.sA[half][i0][og]);
            const ulonglong2* pa1 = reinterpret_cast<const ulonglong2*>(&S.sA[half][i1][og]);
            ulonglong2 t0 = pa0[0], t1 = pa0[1];
            a0[0]=t0.x; a0[1]=t0.y; a0[2]=t1.x; a0[3]=t1.y;
            ulonglong2 u0 = pa1[0], u1 = pa1[1];
            a1[0]=u0.x; a1[1]=u0.y; a1[2]=u1.x; a1[3]=u1.y;
        }
        float cnt0 = 0.f, cnt1 = 0.f;
        #pragma unroll 6
        for (int j = 0; j < NN; j++) {
            const ulonglong2* bp = reinterpret_cast<const ulonglong2*>(&S.sB[half][j][og]);
            ulonglong2 bA = bp[0], bB = bp[1];
            float g0 = (j != i0) ? S.sg[i0*29 + j - (j > i0)] : 0.f;
            float g1 = (j != i1) ? S.sg[i1*29 + j - (j > i1)] : 0.f;
            cnt0 += g0; cnt1 += g1;
            ull gd0, gd1; PACKDUP(gd0, g0); PACKDUP(gd1, g1);
            AGG_STEP(acc0[0], a0[0], bA.x, gd0);
            AGG_STEP(acc0[1], a0[1], bA.y, gd0);
            AGG_STEP(acc0[2], a0[2], bB.x, gd0);
            AGG_STEP(acc0[3], a0[3], bB.y, gd0);
            AGG_STEP(acc1[0], a1[0], bA.x, gd1);
            AGG_STEP(acc1[1], a1[1], bA.y, gd1);
            AGG_STEP(acc1[2], a1[2], bB.x, gd1);
            AGG_STEP(acc1[3], a1[3], bB.y, gd1);
        }
        ull* ph0 = reinterpret_cast<ull*>(&S.sH[half][i0][og]);
        ull* ph1 = reinterpret_cast<ull*>(&S.sH[half][i1][og]);
        #pragma unroll
        for (int u = 0; u < 4; u++) { ph0[u] = acc0[u]; ph1[u] = acc1[u]; }
        if (cg == 0) { S.scnt[half][i0] = cnt0; S.scnt[half][i1] = cnt1; }
    }
    __syncthreads();

    // agg = H @ W2 + cnt * b2  (packed f32x2, w pairs load native from smem)
    if (wt < 120) {
        const float cnt0 = S.scnt[half][i0], cnt1 = S.scnt[half][i1];
        ull acc0[4], acc1[4];
        #pragma unroll
        for (int u = 0; u < 4; u++) {
            float be = S.sb2[og+2*u], bo = S.sb2[og+2*u+1];
            PACK2(acc0[u], cnt0*be, cnt0*bo);
            PACK2(acc1[u], cnt1*be, cnt1*bo);
        }
        #pragma unroll 4
        for (int k4 = 0; k4 < 64; k4 += 4) {
            float4 h0v = *reinterpret_cast<const float4*>(&S.sH[half][i0][k4]);
            float4 h1v = *reinterpret_cast<const float4*>(&S.sH[half][i1][k4]);
            float h0a[4] = {h0v.x, h0v.y, h0v.z, h0v.w};
            float h1a[4] = {h1v.x, h1v.y, h1v.z, h1v.w};
            #pragma unroll
            for (int kk = 0; kk < 4; kk++) {
                ull hd0, hd1; PACKDUP(hd0, h0a[kk]); PACKDUP(hd1, h1a[kk]);
                const ulonglong2* wp =
                    reinterpret_cast<const ulonglong2*>(&S.sW2[(k4+kk)*64 + og]);
                ulonglong2 wA = wp[0], wB = wp[1];
                FFMA2(acc0[0], hd0, wA.x); FFMA2(acc0[1], hd0, wA.y);
                FFMA2(acc0[2], hd0, wB.x); FFMA2(acc0[3], hd0, wB.y);
                FFMA2(acc1[0], hd1, wA.x); FFMA2(acc1[1], hd1, wA.y);
                FFMA2(acc1[2], hd1, wB.x); FFMA2(acc1[3], hd1, wB.y);
            }
        }
        ull* o0 = reinterpret_cast<ull*>(&g_agg[((size_t)s*NN + i0) * HH + og]);
        ull* o1 = reinterpret_cast<ull*>(&g_agg[((size_t)s*NN + i1) * HH + og]);
        #pragma unroll
        for (int u = 0; u < 4; u++) { o0[u] = acc0[u]; o1[u] = acc1[u]; }
    }
}

// ---------------------------------------------------------------------------
// Node MLP kernel: 64 ->relu-> 64 ->relu-> 64 -> 4 (+ optional softplus/clip)
// 2 samples per CTA, 256 threads, packed f32x2 GEMMs.
// ---------------------------------------------------------------------------
struct NodeSmem {
    float sW1[64*64];
    float sW2[64*64];
    float sW3[64*4];
    float bufA[2][NN][HH];
    float bufB[2][NN][HH];
    float sb1[64];
    float sb2[64];
    float sb3[4];
};

__device__ __forceinline__ void gemm_relu_2row(
    const float (*in)[HH], float (*outb)[HH],
    const float* __restrict__ sW, const float* __restrict__ sb,
    int i0, int i1, int og)
{
    ull acc0[4], acc1[4];
    {
        const ull* bp = reinterpret_cast<const ull*>(&sb[og]);
        #pragma unroll
        for (int u = 0; u < 4; u++) { acc0[u] = bp[u]; acc1[u] = bp[u]; }
    }
    #pragma unroll 4
    for (int k4 = 0; k4 < 64; k4 += 4) {
        float4 h0v = *reinterpret_cast<const float4*>(&in[i0][k4]);
        float4 h1v = *reinterpret_cast<const float4*>(&in[i1][k4]);
        float h0a[4] = {h0v.x, h0v.y, h0v.z, h0v.w};
        float h1a[4] = {h1v.x, h1v.y, h1v.z, h1v.w};
        #pragma unroll
        for (int kk = 0; kk < 4; kk++) {
            ull hd0, hd1; PACKDUP(hd0, h0a[kk]); PACKDUP(hd1, h1a[kk]);
            const ulonglong2* wp =
                reinterpret_cast<const ulonglong2*>(&sW[(k4+kk)*64 + og]);
            ulonglong2 wA = wp[0], wB = wp[1];
            FFMA2(acc0[0], hd0, wA.x); FFMA2(acc0[1], hd0, wA.y);
            FFMA2(acc0[2], hd0, wB.x); FFMA2(acc0[3], hd0, wB.y);
            FFMA2(acc1[0], hd1, wA.x); FFMA2(acc1[1], hd1, wA.y);
            FFMA2(acc1[2], hd1, wB.x); FFMA2(acc1[3], hd1, wB.y);
        }
    }
    {
        float x0,x1,x2,x3,x4,x5,x6,x7;
        UNPACK2(x0,x1,acc0[0]); UNPACK2(x2,x3,acc0[1]);
        UNPACK2(x4,x5,acc0[2]); UNPACK2(x6,x7,acc0[3]);
        *reinterpret_cast<float4*>(&outb[i0][og]) =
            make_float4(fmaxf(x0,0.f),fmaxf(x1,0.f),fmaxf(x2,0.f),fmaxf(x3,0.f));
        *reinterpret_cast<float4*>(&outb[i0][og+4]) =
            make_float4(fmaxf(x4,0.f),fmaxf(x5,0.f),fmaxf(x6,0.f),fmaxf(x7,0.f));
        UNPACK2(x0,x1,acc1[0]); UNPACK2(x2,x3,acc1[1]);
        UNPACK2(x4,x5,acc1[2]); UNPACK2(x6,x7,acc1[3]);
        *reinterpret_cast<float4*>(&outb[i1][og]) =
            make_float4(fmaxf(x0,0.f),fmaxf(x1,0.f),fmaxf(x2,0.f),fmaxf(x3,0.f));
        *reinterpret_cast<float4*>(&outb[i1][og+4]) =
            make_float4(fmaxf(x4,0.f),fmaxf(x5,0.f),fmaxf(x6,0.f),fmaxf(x7,0.f));
    }
}

__global__ __launch_bounds__(256) void node_kernel(
    const float* __restrict__ W1, const float* __restrict__ b1,
    const float* __restrict__ W2, const float* __restrict__ b2,
    const float* __restrict__ W3, const float* __restrict__ b3,
    float* __restrict__ out, int t, int is_var, int write_prev)
{
    extern __shared__ char smem_raw[];
    NodeSmem& S = *reinterpret_cast<NodeSmem*>(smem_raw);

    const int tid = threadIdx.x;
    const int p   = blockIdx.x;
    const int bs  = p >> 5;
    const int c0  = p & 31;

    {
        const float4* w1v = reinterpret_cast<const float4*>(W1);
        const float4* w2v = reinterpret_cast<const float4*>(W2);
        float4* s1 = reinterpret_cast<float4*>(S.sW1);
        float4* s2 = reinterpret_cast<float4*>(S.sW2);
        #pragma unroll
        for (int i = tid; i < 1024; i += 256) { s1[i] = w1v[i]; s2[i] = w2v[i]; }
    }
    S.sW3[tid] = W3[tid];                         // 256 floats exactly
    if (tid < 64) { S.sb1[tid] = b1[tid]; S.sb2[tid] = b2[tid]; }
    if (tid < 4)  S.sb3[tid] = b3[tid];

    const int half = tid >> 7;
    const int wt   = tid & 127;
    const int c    = c0 + 32*half;
    const int s    = bs*64 + c;
    {
        const float4* av = reinterpret_cast<const float4*>(&g_agg[(size_t)s * (NN*HH)]);
        float4* bp = reinterpret_cast<float4*>(&S.bufA[half][0][0]);
        for (int i = wt; i < NN*HH/4; i += 128) bp[i] = av[i];
    }
    __syncthreads();

    const int ig = wt >> 3, cg = wt & 7;
    const int i0 = ig << 1, i1 = i0 + 1;
    const int og = cg << 3;

    if (wt < 120)
        gemm_relu_2row(S.bufA[half], S.bufB[half], S.sW1, S.sb1, i0, i1, og);
    __syncthreads();
    if (wt < 120)
        gemm_relu_2row(S.bufB[half], S.bufA[half], S.sW2, S.sb2, i0, i1, og);
    __syncthreads();

    // Layer 3: 64 -> 4
    if (wt < NN*FF) {
        const int n = wt >> 2, f = wt & 3;
        float acc = S.sb3[f];
        #pragma unroll 4
        for (int k4 = 0; k4 < 64; k4 += 4) {
            float4 h = *reinterpret_cast<const float4*>(&S.bufA[half][n][k4]);
            acc = fmaf(h.x, S.sW3[(k4+0)*4 + f], acc);
            acc = fmaf(h.y, S.sW3[(k4+1)*4 + f], acc);
            acc = fmaf(h.z, S.sW3[(k4+2)*4 + f], acc);
            acc = fmaf(h.w, S.sW3[(k4+3)*4 + f], acc);
        }
        if (is_var) {
            float sp = (acc > 20.f) ? acc : log1pf(expf(acc));
            acc = fminf(fmaxf(sp, 1e-8f), 100.f);
        }
        if (write_prev) g_mu[(size_t)s * (NN*FF) + wt] = acc;
        const int kt = 2*c + t;
        if (kt < TOUT) {
            size_t o = (((size_t)bs*TOUT + kt)*NN + n)*FF + f;
            out[o + (is_var ? (size_t)VAROFF : 0)] = acc;
        }
    }
}

// ---------------------------------------------------------------------------
extern "C" void kernel_launch(void* const* d_in, const int* in_sizes, int n_in,
                              void* d_out, int out_size) {
    const float* data    = (const float*)d_in[0];
    const float* graph   = (const float*)d_in[1];
    const float* msg_W1  = (const float*)d_in[2];
    const float* msg_b1  = (const float*)d_in[3];
    const float* msg_W2  = (const float*)d_in[4];
    const float* msg_b2  = (const float*)d_in[5];
    const float* mean_W1 = (const float*)d_in[6];
    const float* mean_b1 = (const float*)d_in[7];
    const float* mean_W2 = (const float*)d_in[8];
    const float* mean_b2 = (const float*)d_in[9];
    const float* mean_W3 = (const float*)d_in[10];
    const float* mean_b3 = (const float*)d_in[11];
    const float* var_W1  = (const float*)d_in[12];
    const float* var_b1  = (const float*)d_in[13];
    const float* var_W2  = (const float*)d_in[14];
    const float* var_b2  = (const float*)d_in[15];
    const float* var_W3  = (const float*)d_in[16];
    const float* var_b3  = (const float*)d_in[17];
    float* out = (float*)d_out;

    cudaFuncSetAttribute(edge_kernel, cudaFuncAttributeMaxDynamicSharedMemorySize,
                         (int)sizeof(EdgeSmem));
    cudaFuncSetAttribute(node_kernel, cudaFuncAttributeMaxDynamicSharedMemorySize,
                         (int)sizeof(NodeSmem));

    for (int t = 0; t < 2; t++) {
        edge_kernel<<<NSAMP/2, 256, sizeof(EdgeSmem)>>>(data, t, graph,
                                    msg_W1, msg_b1, msg_W2, msg_b2);
        node_kernel<<<NSAMP/2, 256, sizeof(NodeSmem)>>>(mean_W1, mean_b1, mean_W2, mean_b2,
                                    mean_W3, mean_b3, out, t, 0, (t == 0) ? 1 : 0);
        node_kernel<<<NSAMP/2, 256, sizeof(NodeSmem)>>>(var_W1, var_b1, var_W2, var_b2,
                                    var_W3, var_b3, out, t, 1, 0);
    }
}

// round 5
// speedup vs baseline: 2.7065x; 1.5135x over previous
#include <cuda_runtime.h>
#include <math.h>

typedef unsigned long long ull;

#define NN 30
#define FF 4
#define HH 64
#define NSAMP 2048          // 32 * 64
#define TOUT 127
#define VAROFF (32*127*30*4)
#define AST 68              // activation row stride (floats), bank-staggered
#define GST 44              // dense-graph row stride (floats), bank-staggered

// Scratch (allocation-free rule: __device__ globals)
__device__ float g_agg[(size_t)NSAMP * NN * HH];   // 15.7 MB
__device__ float g_mu [(size_t)NSAMP * NN * FF];   // 0.98 MB

// ---- packed f32x2 helpers (sm_103a) ---------------------------------------
#define FFMA2(acc, a, b) \
    asm("fma.rn.f32x2 %0, %1, %2, %0;" : "+l"(acc) : "l"(a), "l"(b))
#define MUL2(d, a, b) \
    asm("mul.rn.f32x2 %0, %1, %2;" : "=l"(d) : "l"(a), "l"(b))
#define PACKDUP(d, x) \
    asm("mov.b64 %0, {%1, %1};" : "=l"(d) : "r"(__float_as_uint(x)))
#define UNPACK2(x, y, p) \
    asm("mov.b64 {%0, %1}, %2;" : "=f"(x), "=f"(y) : "l"(p))
// acc += gdup * relu(apair + bpair)
#define AGG_STEP(acc, apair, bpair, gdup) \
    asm("{\n\t.reg .b32 lo, hi;\n\t.reg .b64 t;\n\t" \
        "add.rn.f32x2 t, %1, %2;\n\t" \
        "mov.b64 {lo, hi}, t;\n\t" \
        "max.f32 lo, lo, 0f00000000;\n\t" \
        "max.f32 hi, hi, 0f00000000;\n\t" \
        "mov.b64 t, {lo, hi};\n\t" \
        "fma.rn.f32x2 %0, %3, t, %0;\n\t}" \
        : "+l"(acc) : "l"(apair), "l"(bpair), "l"(gdup))

// ---------------------------------------------------------------------------
// Edge kernel: 2 samples per CTA, 128 threads, 120 active (15 row-pairs x 8
// col-groups), each thread handles 4 row-instances (2 rows x 2 samples).
// ---------------------------------------------------------------------------
struct EdgeSmem {
    float sW2[64*64];           // 16 KB
    float sW1[8*64];            //  2 KB
    float sB[2][32][AST];       // 17 KB (rows 30,31 zero-padded)
    float sH[2][NN][AST];       // 16 KB
    float sgm[NN][GST];         //  5 KB dense graph, zero diagonal
    float sx[2][128];           //  1 KB
    float sb1[64];
    float sb2[64];
};

__global__ __launch_bounds__(128, 3) void edge_kernel(
    const float* __restrict__ data, int mode,
    const float* __restrict__ graph,
    const float* __restrict__ W1, const float* __restrict__ b1,
    const float* __restrict__ W2, const float* __restrict__ b2)
{
    extern __shared__ char smem_raw[];
    EdgeSmem& S = *reinterpret_cast<EdgeSmem*>(smem_raw);

    const int tid = threadIdx.x;
    const int p   = blockIdx.x;
    const int bs  = p >> 5;
    const int c0  = p & 31;

    {
        const float4* w2v = reinterpret_cast<const float4*>(W2);
        float4* d2 = reinterpret_cast<float4*>(S.sW2);
        #pragma unroll
        for (int i = tid; i < 1024; i += 128) d2[i] = w2v[i];
        const float4* w1v = reinterpret_cast<const float4*>(W1);
        float4* d1 = reinterpret_cast<float4*>(S.sW1);
        d1[tid] = w1v[tid];                      // 512 floats = 128 float4
    }
    if (tid < 64) { S.sb1[tid] = b1[tid]; S.sb2[tid] = b2[tid]; }
    // dense 30x30 graph with zero diagonal (+zero pad cols 30,31)
    for (int e = tid; e < 900; e += 128) {
        int i = e / 30, j = e - i*30;
        S.sgm[i][j] = (i == j) ? 0.f
                      : graph[(size_t)bs*870 + i*29 + j - (j > i)];
    }
    if (tid < 30) { S.sgm[tid][30] = 0.f; S.sgm[tid][31] = 0.f; }
    if (tid < 68) {
        S.sB[0][30][tid] = 0.f; S.sB[0][31][tid] = 0.f;
        S.sB[1][30][tid] = 0.f; S.sB[1][31][tid] = 0.f;
    }
    for (int v = tid; v < 240; v += 128) {
        int h = v >= 120, idx = v - 120*h;
        int cc = c0 + 32*h, ss = bs*64 + cc;
        S.sx[h][idx] = (mode == 0)
            ? data[((size_t)bs*128 + 2*cc)*120 + idx]
            : g_mu[(size_t)ss*120 + idx];
    }
    __syncthreads();

    const int ig = tid >> 3, cg = tid & 7;
    const int i0 = ig*2, i1 = i0+1, og = cg*8;

    ull aA[4][4];               // A-projection, stays in registers
    float cnt0 = 0.f, cnt1 = 0.f;

    // ---- projections: A (own rows, registers) + B (smem) ----
    if (tid < 120) {
        float xr[4][4];
        #pragma unroll
        for (int inst = 0; inst < 4; inst++) {
            int h = inst >> 1, row = (inst & 1) ? i1 : i0;
            float4 xv = *reinterpret_cast<const float4*>(&S.sx[h][row*4]);
            xr[inst][0]=xv.x; xr[inst][1]=xv.y; xr[inst][2]=xv.z; xr[inst][3]=xv.w;
        }
        ull aB[4][4];
        {
            ulonglong2 bq0 = *reinterpret_cast<const ulonglong2*>(&S.sb1[og]);
            ulonglong2 bq1 = *reinterpret_cast<const ulonglong2*>(&S.sb1[og+4]);
            ull bp[4] = {bq0.x, bq0.y, bq1.x, bq1.y};
            #pragma unroll
            for (int inst = 0; inst < 4; inst++)
                #pragma unroll
                for (int q = 0; q < 4; q++) { aA[inst][q] = bp[q]; aB[inst][q] = 0ULL; }
        }
        #pragma unroll
        for (int r = 0; r < 4; r++) {
            ulonglong2 wa0 = *reinterpret_cast<const ulonglong2*>(&S.sW1[r*64+og]);
            ulonglong2 wa1 = *reinterpret_cast<const ulonglong2*>(&S.sW1[r*64+og+4]);
            ulonglong2 wb0 = *reinterpret_cast<const ulonglong2*>(&S.sW1[(r+4)*64+og]);
            ulonglong2 wb1 = *reinterpret_cast<const ulonglong2*>(&S.sW1[(r+4)*64+og+4]);
            ull wa[4] = {wa0.x, wa0.y, wa1.x, wa1.y};
            ull wb[4] = {wb0.x, wb0.y, wb1.x, wb1.y};
            #pragma unroll
            for (int inst = 0; inst < 4; inst++) {
                ull xd; PACKDUP(xd, xr[inst][r]);
                #pragma unroll
                for (int q = 0; q < 4; q++) {
                    FFMA2(aA[inst][q], xd, wa[q]);
                    FFMA2(aB[inst][q], xd, wb[q]);
                }
            }
        }
        #pragma unroll
        for (int inst = 0; inst < 4; inst++) {
            int h = inst >> 1, row = (inst & 1) ? i1 : i0;
            ulonglong2 s0; s0.x = aB[inst][0]; s0.y = aB[inst][1];
            ulonglong2 s1; s1.x = aB[inst][2]; s1.y = aB[inst][3];
            *reinterpret_cast<ulonglong2*>(&S.sB[h][row][og])   = s0;
            *reinterpret_cast<ulonglong2*>(&S.sB[h][row][og+4]) = s1;
        }
    }
    __syncthreads();

    // ---- masked-ReLU aggregation ----
    if (tid < 120) {
        ull acc[4][4];
        #pragma unroll
        for (int inst = 0; inst < 4; inst++)
            #pragma unroll
            for (int q = 0; q < 4; q++) acc[inst][q] = 0ULL;

        #pragma unroll 2
        for (int j4 = 0; j4 < 32; j4 += 4) {
            float4 gA = *reinterpret_cast<const float4*>(&S.sgm[i0][j4]);
            float4 gB = *reinterpret_cast<const float4*>(&S.sgm[i1][j4]);
            cnt0 += gA.x + gA.y + gA.z + gA.w;
            cnt1 += gB.x + gB.y + gB.z + gB.w;
            float g0a[4] = {gA.x, gA.y, gA.z, gA.w};
            float g1a[4] = {gB.x, gB.y, gB.z, gB.w};
            #pragma unroll
            for (int jj = 0; jj < 4; jj++) {
                int j = j4 + jj;
                ulonglong2 bh00 = *reinterpret_cast<const ulonglong2*>(&S.sB[0][j][og]);
                ulonglong2 bh01 = *reinterpret_cast<const ulonglong2*>(&S.sB[0][j][og+4]);
                ulonglong2 bh10 = *reinterpret_cast<const ulonglong2*>(&S.sB[1][j][og]);
                ulonglong2 bh11 = *reinterpret_cast<const ulonglong2*>(&S.sB[1][j][og+4]);
                ull b0v[4] = {bh00.x, bh00.y, bh01.x, bh01.y};
                ull b1v[4] = {bh10.x, bh10.y, bh11.x, bh11.y};
                ull gd0, gd1; PACKDUP(gd0, g0a[jj]); PACKDUP(gd1, g1a[jj]);
                #pragma unroll
                for (int q = 0; q < 4; q++) {
                    AGG_STEP(acc[0][q], aA[0][q], b0v[q], gd0);
                    AGG_STEP(acc[1][q], aA[1][q], b0v[q], gd1);
                    AGG_STEP(acc[2][q], aA[2][q], b1v[q], gd0);
                    AGG_STEP(acc[3][q], aA[3][q], b1v[q], gd1);
                }
            }
        }
        #pragma unroll
        for (int inst = 0; inst < 4; inst++) {
            int h = inst >> 1, row = (inst & 1) ? i1 : i0;
            ulonglong2 s0; s0.x = acc[inst][0]; s0.y = acc[inst][1];
            ulonglong2 s1; s1.x = acc[inst][2]; s1.y = acc[inst][3];
            *reinterpret_cast<ulonglong2*>(&S.sH[h][row][og])   = s0;
            *reinterpret_cast<ulonglong2*>(&S.sH[h][row][og+4]) = s1;
        }
    }
    __syncthreads();

    // ---- agg = H @ W2 + cnt * b2 ----
    if (tid < 120) {
        ull acc2[4][4];
        {
            ulonglong2 bq0 = *reinterpret_cast<const ulonglong2*>(&S.sb2[og]);
            ulonglong2 bq1 = *reinterpret_cast<const ulonglong2*>(&S.sb2[og+4]);
            ull bp[4] = {bq0.x, bq0.y, bq1.x, bq1.y};
            ull cd0, cd1; PACKDUP(cd0, cnt0); PACKDUP(cd1, cnt1);
            #pragma unroll
            for (int q = 0; q < 4; q++) {
                MUL2(acc2[0][q], cd0, bp[q]);
                MUL2(acc2[1][q], cd1, bp[q]);
                MUL2(acc2[2][q], cd0, bp[q]);
                MUL2(acc2[3][q], cd1, bp[q]);
            }
        }
        const float* rp[4] = { &S.sH[0][i0][0], &S.sH[0][i1][0],
                               &S.sH[1][i0][0], &S.sH[1][i1][0] };
        #pragma unroll 2
        for (int k4 = 0; k4 < 64; k4 += 4) {
            float ha[4][4];
            #pragma unroll
            for (int inst = 0; inst < 4; inst++) {
                float4 hv = *reinterpret_cast<const float4*>(rp[inst] + k4);
                ha[inst][0]=hv.x; ha[inst][1]=hv.y; ha[inst][2]=hv.z; ha[inst][3]=hv.w;
            }
            #pragma unroll
            for (int kk = 0; kk < 4; kk++) {
                ulonglong2 w0 = *reinterpret_cast<const ulonglong2*>(&S.sW2[(k4+kk)*64+og]);
                ulonglong2 w1 = *reinterpret_cast<const ulonglong2*>(&S.sW2[(k4+kk)*64+og+4]);
                ull wv[4] = {w0.x, w0.y, w1.x, w1.y};
                #pragma unroll
                for (int inst = 0; inst < 4; inst++) {
                    ull hd; PACKDUP(hd, ha[inst][kk]);
                    #pragma unroll
                    for (int q = 0; q < 4; q++) FFMA2(acc2[inst][q], hd, wv[q]);
                }
            }
        }
        const int sb0 = bs*64 + c0;
        #pragma unroll
        for (int inst = 0; inst < 4; inst++) {
            int h = inst >> 1, row = (inst & 1) ? i1 : i0;
            size_t base = ((size_t)(sb0 + 32*h)*NN + row)*HH + og;
            ulonglong2 s0; s0.x = acc2[inst][0]; s0.y = acc2[inst][1];
            ulonglong2 s1; s1.x = acc2[inst][2]; s1.y = acc2[inst][3];
            *reinterpret_cast<ulonglong2*>(&g_agg[base])   = s0;
            *reinterpret_cast<ulonglong2*>(&g_agg[base+4]) = s1;
        }
    }
}

// ---------------------------------------------------------------------------
// Node MLP kernel: 64 ->relu-> 64 ->relu-> 64 -> 4, 2 samples/CTA, 128 thr.
// ---------------------------------------------------------------------------
struct NodeSmem {
    float sW1[64*64];
    float sW2[64*64];
    float sW3[64*4];
    float bufA[2][NN][AST];
    float bufB[2][NN][AST];
    float sb1[64];
    float sb2[64];
    float sb3[8];
};

__device__ __forceinline__ void gemm4_relu(
    const float* __restrict__ in, float* __restrict__ op,
    const float* __restrict__ sW, const float* __restrict__ sb,
    int i0, int i1, int og)
{
    const int HOFF = NN*AST;
    const float* rp[4] = { in + i0*AST, in + i1*AST,
                           in + HOFF + i0*AST, in + HOFF + i1*AST };
    float* wp4[4] = { op + i0*AST, op + i1*AST,
                      op + HOFF + i0*AST, op + HOFF + i1*AST };
    ull acc[4][4];
    {
        ulonglong2 bq0 = *reinterpret_cast<const ulonglong2*>(&sb[og]);
        ulonglong2 bq1 = *reinterpret_cast<const ulonglong2*>(&sb[og+4]);
        ull bp[4] = {bq0.x, bq0.y, bq1.x, bq1.y};
        #pragma unroll
        for (int inst = 0; inst < 4; inst++)
            #pragma unroll
            for (int q = 0; q < 4; q++) acc[inst][q] = bp[q];
    }
    #pragma unroll 2
    for (int k4 = 0; k4 < 64; k4 += 4) {
        float ha[4][4];
        #pragma unroll
        for (int inst = 0; inst < 4; inst++) {
            float4 hv = *reinterpret_cast<const float4*>(rp[inst] + k4);
            ha[inst][0]=hv.x; ha[inst][1]=hv.y; ha[inst][2]=hv.z; ha[inst][3]=hv.w;
        }
        #pragma unroll
        for (int kk = 0; kk < 4; kk++) {
            ulonglong2 w0 = *reinterpret_cast<const ulonglong2*>(&sW[(k4+kk)*64+og]);
            ulonglong2 w1 = *reinterpret_cast<const ulonglong2*>(&sW[(k4+kk)*64+og+4]);
            ull wv[4] = {w0.x, w0.y, w1.x, w1.y};
            #pragma unroll
            for (int inst = 0; inst < 4; inst++) {
                ull hd; PACKDUP(hd, ha[inst][kk]);
                #pragma unroll
                for (int q = 0; q < 4; q++) FFMA2(acc[inst][q], hd, wv[q]);
            }
        }
    }
    #pragma unroll
    for (int inst = 0; inst < 4; inst++) {
        float x0,x1,x2,x3,x4,x5,x6,x7;
        UNPACK2(x0,x1,acc[inst][0]); UNPACK2(x2,x3,acc[inst][1]);
        UNPACK2(x4,x5,acc[inst][2]); UNPACK2(x6,x7,acc[inst][3]);
        *reinterpret_cast<float4*>(wp4[inst]+og) =
            make_float4(fmaxf(x0,0.f),fmaxf(x1,0.f),fmaxf(x2,0.f),fmaxf(x3,0.f));
        *reinterpret_cast<float4*>(wp4[inst]+og+4) =
            make_float4(fmaxf(x4,0.f),fmaxf(x5,0.f),fmaxf(x6,0.f),fmaxf(x7,0.f));
    }
}

__global__ __launch_bounds__(128, 3) void node_kernel(
    const float* __restrict__ W1, const float* __restrict__ b1,
    const float* __restrict__ W2, const float* __restrict__ b2,
    const float* __restrict__ W3, const float* __restrict__ b3,
    float* __restrict__ out, int t, int is_var, int write_prev)
{
    extern __shared__ char smem_raw[];
    NodeSmem& S = *reinterpret_cast<NodeSmem*>(smem_raw);

    const int tid = threadIdx.x;
    const int p   = blockIdx.x;
    const int bs  = p >> 5;
    const int c0  = p & 31;

    {
        const float4* w1v = reinterpret_cast<const float4*>(W1);
        const float4* w2v = reinterpret_cast<const float4*>(W2);
        float4* s1 = reinterpret_cast<float4*>(S.sW1);
        float4* s2 = reinterpret_cast<float4*>(S.sW2);
        #pragma unroll
        for (int i = tid; i < 1024; i += 128) { s1[i] = w1v[i]; s2[i] = w2v[i]; }
        S.sW3[tid] = W3[tid]; S.sW3[tid+128] = W3[tid+128];
    }
    if (tid < 64) { S.sb1[tid] = b1[tid]; S.sb2[tid] = b2[tid]; }
    if (tid < 4)  S.sb3[tid] = b3[tid];
    if (tid >= 4 && tid < 8) S.sb3[tid] = 0.f;

    const int sbase = bs*64 + c0;
    {
        for (int v = tid; v < 960; v += 128) {
            int h = v >= 480, vv = v - 480*h;
            const float4* src = reinterpret_cast<const float4*>(g_agg)
                                + (size_t)(sbase + 32*h)*480 + vv;
            int row = vv >> 4, cp = vv & 15;
            *reinterpret_cast<float4*>(&S.bufA[h][row][cp*4]) = *src;
        }
    }
    __syncthreads();

    const int ig = tid >> 3, cg = tid & 7;
    const int i0 = ig*2, i1 = i0+1, og = cg*8;

    if (tid < 120)
        gemm4_relu(&S.bufA[0][0][0], &S.bufB[0][0][0], S.sW1, S.sb1, i0, i1, og);
    __syncthreads();
    if (tid < 120)
        gemm4_relu(&S.bufB[0][0][0], &S.bufA[0][0][0], S.sW2, S.sb2, i0, i1, og);
    __syncthreads();

    // Layer 3: 64 -> 4 (60 threads: (half, node))
    if (tid < 60) {
        const int h = (tid >= 30) ? 1 : 0, n = tid - 30*h;
        const float* hr = &S.bufA[h][n][0];
        ulonglong2 b3q = *reinterpret_cast<const ulonglong2*>(&S.sb3[0]);
        ull a01 = b3q.x, a23 = b3q.y;
        #pragma unroll 4
        for (int k4 = 0; k4 < 64; k4 += 4) {
            float4 hv = *reinterpret_cast<const float4*>(hr + k4);
            float ha[4] = {hv.x, hv.y, hv.z, hv.w};
            #pragma unroll
            for (int kk = 0; kk < 4; kk++) {
                ulonglong2 w = *reinterpret_cast<const ulonglong2*>(&S.sW3[(k4+kk)*4]);
                ull hd; PACKDUP(hd, ha[kk]);
                FFMA2(a01, hd, w.x);
                FFMA2(a23, hd, w.y);
            }
        }
        float v0,v1,v2,v3;
        UNPACK2(v0,v1,a01); UNPACK2(v2,v3,a23);
        float v[4] = {v0,v1,v2,v3};
        if (is_var) {
            #pragma unroll
            for (int q = 0; q < 4; q++) {
                float x = v[q];
                float sp = (x > 20.f) ? x : log1pf(expf(x));
                v[q] = fminf(fmaxf(sp, 1e-8f), 100.f);
            }
        }
        const int c = c0 + 32*h;
        const int s = bs*64 + c;
        if (write_prev)
            *reinterpret_cast<float4*>(&g_mu[(size_t)s*120 + n*4]) =
                make_float4(v[0],v[1],v[2],v[3]);
        const int kt = 2*c + t;
        if (kt < TOUT) {
            size_t o = (((size_t)bs*TOUT + kt)*NN + n)*FF;
            *reinterpret_cast<float4*>(&out[o + (is_var ? (size_t)VAROFF : 0)]) =
                make_float4(v[0],v[1],v[2],v[3]);
        }
    }
}

// ---------------------------------------------------------------------------
extern "C" void kernel_launch(void* const* d_in, const int* in_sizes, int n_in,
                              void* d_out, int out_size) {
    const float* data    = (const float*)d_in[0];
    const float* graph   = (const float*)d_in[1];
    const float* msg_W1  = (const float*)d_in[2];
    const float* msg_b1  = (const float*)d_in[3];
    const float* msg_W2  = (const float*)d_in[4];
    const float* msg_b2  = (const float*)d_in[5];
    const float* mean_W1 = (const float*)d_in[6];
    const float* mean_b1 = (const float*)d_in[7];
    const float* mean_W2 = (const float*)d_in[8];
    const float* mean_b2 = (const float*)d_in[9];
    const float* mean_W3 = (const float*)d_in[10];
    const float* mean_b3 = (const float*)d_in[11];
    const float* var_W1  = (const float*)d_in[12];
    const float* var_b1  = (const float*)d_in[13];
    const float* var_W2  = (const float*)d_in[14];
    const float* var_b2  = (const float*)d_in[15];
    const float* var_W3  = (const float*)d_in[16];
    const float* var_b3  = (const float*)d_in[17];
    float* out = (float*)d_out;

    cudaFuncSetAttribute(edge_kernel, cudaFuncAttributeMaxDynamicSharedMemorySize,
                         (int)sizeof(EdgeSmem));
    cudaFuncSetAttribute(node_kernel, cudaFuncAttributeMaxDynamicSharedMemorySize,
                         (int)sizeof(NodeSmem));

    for (int t = 0; t < 2; t++) {
        edge_kernel<<<NSAMP/2, 128, sizeof(EdgeSmem)>>>(data, t, graph,
                                    msg_W1, msg_b1, msg_W2, msg_b2);
        node_kernel<<<NSAMP/2, 128, sizeof(NodeSmem)>>>(mean_W1, mean_b1, mean_W2, mean_b2,
                                    mean_W3, mean_b3, out, t, 0, (t == 0) ? 1 : 0);
        node_kernel<<<NSAMP/2, 128, sizeof(NodeSmem)>>>(var_W1, var_b1, var_W2, var_b2,
                                    var_W3, var_b3, out, t, 1, 0);
    }
}

// round 6
// speedup vs baseline: 3.2268x; 1.1922x over previous
#include <cuda_runtime.h>
#include <math.h>

typedef unsigned long long ull;

#define NN 30
#define FF 4
#define HH 64
#define NSAMP 2048          // 32 * 64
#define TOUT 127
#define VAROFF (32*127*30*4)
#define AST 68              // activation row stride (floats), bank-staggered
#define GST 44              // dense-graph row stride (floats), bank-staggered

// Scratch (allocation-free rule: __device__ globals)
__device__ float g_agg[(size_t)NSAMP * NN * HH];   // 15.7 MB
__device__ float g_mu [(size_t)NSAMP * NN * FF];   // 0.98 MB

// ---- packed f32x2 helpers (sm_103a) ---------------------------------------
#define FFMA2(acc, a, b) \
    asm("fma.rn.f32x2 %0, %1, %2, %0;" : "+l"(acc) : "l"(a), "l"(b))
#define MUL2(d, a, b) \
    asm("mul.rn.f32x2 %0, %1, %2;" : "=l"(d) : "l"(a), "l"(b))
#define PACKDUP(d, x) \
    asm("mov.b64 %0, {%1, %1};" : "=l"(d) : "r"(__float_as_uint(x)))
#define UNPACK2(x, y, p) \
    asm("mov.b64 {%0, %1}, %2;" : "=f"(x), "=f"(y) : "l"(p))
// acc += gdup * relu(apair + bpair)
#define AGG_STEP(acc, apair, bpair, gdup) \
    asm("{\n\t.reg .b32 lo, hi;\n\t.reg .b64 t;\n\t" \
        "add.rn.f32x2 t, %1, %2;\n\t" \
        "mov.b64 {lo, hi}, t;\n\t" \
        "max.f32 lo, lo, 0f00000000;\n\t" \
        "max.f32 hi, hi, 0f00000000;\n\t" \
        "mov.b64 t, {lo, hi};\n\t" \
        "fma.rn.f32x2 %0, %3, t, %0;\n\t}" \
        : "+l"(acc) : "l"(apair), "l"(bpair), "l"(gdup))

// ---------------------------------------------------------------------------
// Edge kernel: 2 samples per CTA, 128 threads, 120 active. H overwrites sB
// in place after a barrier (saves 16KB smem -> higher occupancy).
// ---------------------------------------------------------------------------
struct EdgeSmem {
    float sW2[64*64];           // 16 KB
    float sW1[8*64];            //  2 KB
    float sB[2][32][AST];       // 17.4 KB (rows 30,31 zero) ; becomes H
    float sgm[NN][GST];         //  5.3 KB dense graph, zero diagonal
    float sx[2][128];           //  1 KB
    float sb1[64];
    float sb2[64];
};

__global__ __launch_bounds__(128, 4) void edge_kernel(
    const float* __restrict__ data, int mode,
    const float* __restrict__ graph,
    const float* __restrict__ W1, const float* __restrict__ b1,
    const float* __restrict__ W2, const float* __restrict__ b2)
{
    extern __shared__ char smem_raw[];
    EdgeSmem& S = *reinterpret_cast<EdgeSmem*>(smem_raw);

    const int tid = threadIdx.x;
    const int p   = blockIdx.x;
    const int bs  = p >> 5;
    const int c0  = p & 31;

    {
        const float4* w2v = reinterpret_cast<const float4*>(W2);
        float4* d2 = reinterpret_cast<float4*>(S.sW2);
        #pragma unroll
        for (int i = tid; i < 1024; i += 128) d2[i] = w2v[i];
        const float4* w1v = reinterpret_cast<const float4*>(W1);
        float4* d1 = reinterpret_cast<float4*>(S.sW1);
        d1[tid] = w1v[tid];
    }
    if (tid < 64) { S.sb1[tid] = b1[tid]; S.sb2[tid] = b2[tid]; }
    for (int e = tid; e < 900; e += 128) {
        int i = e / 30, j = e - i*30;
        S.sgm[i][j] = (i == j) ? 0.f
                      : graph[(size_t)bs*870 + i*29 + j - (j > i)];
    }
    if (tid < 30) { S.sgm[tid][30] = 0.f; S.sgm[tid][31] = 0.f; }
    if (tid < 68) {
        S.sB[0][30][tid] = 0.f; S.sB[0][31][tid] = 0.f;
        S.sB[1][30][tid] = 0.f; S.sB[1][31][tid] = 0.f;
    }
    for (int v = tid; v < 240; v += 128) {
        int h = v >= 120, idx = v - 120*h;
        int cc = c0 + 32*h, ss = bs*64 + cc;
        S.sx[h][idx] = (mode == 0)
            ? data[((size_t)bs*128 + 2*cc)*120 + idx]
            : g_mu[(size_t)ss*120 + idx];
    }
    __syncthreads();

    const int ig = tid >> 3, cg = tid & 7;
    const int i0 = ig*2, i1 = i0+1, og = cg*8;

    ull aA[4][4];               // A-projection, registers
    float cnt0 = 0.f, cnt1 = 0.f;

    // ---- projections: A (registers) + B (smem) ----
    if (tid < 120) {
        float xr[4][4];
        #pragma unroll
        for (int inst = 0; inst < 4; inst++) {
            int h = inst >> 1, row = (inst & 1) ? i1 : i0;
            float4 xv = *reinterpret_cast<const float4*>(&S.sx[h][row*4]);
            xr[inst][0]=xv.x; xr[inst][1]=xv.y; xr[inst][2]=xv.z; xr[inst][3]=xv.w;
        }
        ull aB[4][4];
        {
            ulonglong2 bq0 = *reinterpret_cast<const ulonglong2*>(&S.sb1[og]);
            ulonglong2 bq1 = *reinterpret_cast<const ulonglong2*>(&S.sb1[og+4]);
            ull bp[4] = {bq0.x, bq0.y, bq1.x, bq1.y};
            #pragma unroll
            for (int inst = 0; inst < 4; inst++)
                #pragma unroll
                for (int q = 0; q < 4; q++) { aA[inst][q] = bp[q]; aB[inst][q] = 0ULL; }
        }
        #pragma unroll
        for (int r = 0; r < 4; r++) {
            ulonglong2 wa0 = *reinterpret_cast<const ulonglong2*>(&S.sW1[r*64+og]);
            ulonglong2 wa1 = *reinterpret_cast<const ulonglong2*>(&S.sW1[r*64+og+4]);
            ulonglong2 wb0 = *reinterpret_cast<const ulonglong2*>(&S.sW1[(r+4)*64+og]);
            ulonglong2 wb1 = *reinterpret_cast<const ulonglong2*>(&S.sW1[(r+4)*64+og+4]);
            ull wa[4] = {wa0.x, wa0.y, wa1.x, wa1.y};
            ull wb[4] = {wb0.x, wb0.y, wb1.x, wb1.y};
            #pragma unroll
            for (int inst = 0; inst < 4; inst++) {
                ull xd; PACKDUP(xd, xr[inst][r]);
                #pragma unroll
                for (int q = 0; q < 4; q++) {
                    FFMA2(aA[inst][q], xd, wa[q]);
                    FFMA2(aB[inst][q], xd, wb[q]);
                }
            }
        }
        #pragma unroll
        for (int inst = 0; inst < 4; inst++) {
            int h = inst >> 1, row = (inst & 1) ? i1 : i0;
            ulonglong2 s0; s0.x = aB[inst][0]; s0.y = aB[inst][1];
            ulonglong2 s1; s1.x = aB[inst][2]; s1.y = aB[inst][3];
            *reinterpret_cast<ulonglong2*>(&S.sB[h][row][og])   = s0;
            *reinterpret_cast<ulonglong2*>(&S.sB[h][row][og+4]) = s1;
        }
    }
    __syncthreads();

    // ---- masked-ReLU aggregation (acc stays in regs across barrier) ----
    ull acc[4][4];
    if (tid < 120) {
        #pragma unroll
        for (int inst = 0; inst < 4; inst++)
            #pragma unroll
            for (int q = 0; q < 4; q++) acc[inst][q] = 0ULL;

        #pragma unroll 2
        for (int j4 = 0; j4 < 32; j4 += 4) {
            float4 gA = *reinterpret_cast<const float4*>(&S.sgm[i0][j4]);
            float4 gB = *reinterpret_cast<const float4*>(&S.sgm[i1][j4]);
            cnt0 += gA.x + gA.y + gA.z + gA.w;
            cnt1 += gB.x + gB.y + gB.z + gB.w;
            float g0a[4] = {gA.x, gA.y, gA.z, gA.w};
            float g1a[4] = {gB.x, gB.y, gB.z, gB.w};
            #pragma unroll
            for (int jj = 0; jj < 4; jj++) {
                int j = j4 + jj;
                ulonglong2 bh00 = *reinterpret_cast<const ulonglong2*>(&S.sB[0][j][og]);
                ulonglong2 bh01 = *reinterpret_cast<const ulonglong2*>(&S.sB[0][j][og+4]);
                ulonglong2 bh10 = *reinterpret_cast<const ulonglong2*>(&S.sB[1][j][og]);
                ulonglong2 bh11 = *reinterpret_cast<const ulonglong2*>(&S.sB[1][j][og+4]);
                ull b0v[4] = {bh00.x, bh00.y, bh01.x, bh01.y};
                ull b1v[4] = {bh10.x, bh10.y, bh11.x, bh11.y};
                ull gd0, gd1; PACKDUP(gd0, g0a[jj]); PACKDUP(gd1, g1a[jj]);
                #pragma unroll
                for (int q = 0; q < 4; q++) {
                    AGG_STEP(acc[0][q], aA[0][q], b0v[q], gd0);
                    AGG_STEP(acc[1][q], aA[1][q], b0v[q], gd1);
                    AGG_STEP(acc[2][q], aA[2][q], b1v[q], gd0);
                    AGG_STEP(acc[3][q], aA[3][q], b1v[q], gd1);
                }
            }
        }
    }
    __syncthreads();            // all sB reads complete
    if (tid < 120) {
        #pragma unroll
        for (int inst = 0; inst < 4; inst++) {   // H overwrites sB
            int h = inst >> 1, row = (inst & 1) ? i1 : i0;
            ulonglong2 s0; s0.x = acc[inst][0]; s0.y = acc[inst][1];
            ulonglong2 s1; s1.x = acc[inst][2]; s1.y = acc[inst][3];
            *reinterpret_cast<ulonglong2*>(&S.sB[h][row][og])   = s0;
            *reinterpret_cast<ulonglong2*>(&S.sB[h][row][og+4]) = s1;
        }
    }
    __syncthreads();

    // ---- agg = H @ W2 + cnt * b2 (H lives in sB now) ----
    if (tid < 120) {
        ull acc2[4][4];
        {
            ulonglong2 bq0 = *reinterpret_cast<const ulonglong2*>(&S.sb2[og]);
            ulonglong2 bq1 = *reinterpret_cast<const ulonglong2*>(&S.sb2[og+4]);
            ull bp[4] = {bq0.x, bq0.y, bq1.x, bq1.y};
            ull cd0, cd1; PACKDUP(cd0, cnt0); PACKDUP(cd1, cnt1);
            #pragma unroll
            for (int q = 0; q < 4; q++) {
                MUL2(acc2[0][q], cd0, bp[q]);
                MUL2(acc2[1][q], cd1, bp[q]);
                MUL2(acc2[2][q], cd0, bp[q]);
                MUL2(acc2[3][q], cd1, bp[q]);
            }
        }
        const float* rp[4] = { &S.sB[0][i0][0], &S.sB[0][i1][0],
                               &S.sB[1][i0][0], &S.sB[1][i1][0] };
        #pragma unroll 2
        for (int k4 = 0; k4 < 64; k4 += 4) {
            float ha[4][4];
            #pragma unroll
            for (int inst = 0; inst < 4; inst++) {
                float4 hv = *reinterpret_cast<const float4*>(rp[inst] + k4);
                ha[inst][0]=hv.x; ha[inst][1]=hv.y; ha[inst][2]=hv.z; ha[inst][3]=hv.w;
            }
            #pragma unroll
            for (int kk = 0; kk < 4; kk++) {
                ulonglong2 w0 = *reinterpret_cast<const ulonglong2*>(&S.sW2[(k4+kk)*64+og]);
                ulonglong2 w1 = *reinterpret_cast<const ulonglong2*>(&S.sW2[(k4+kk)*64+og+4]);
                ull wv[4] = {w0.x, w0.y, w1.x, w1.y};
                #pragma unroll
                for (int inst = 0; inst < 4; inst++) {
                    ull hd; PACKDUP(hd, ha[inst][kk]);
                    #pragma unroll
                    for (int q = 0; q < 4; q++) FFMA2(acc2[inst][q], hd, wv[q]);
                }
            }
        }
        const int sb0 = bs*64 + c0;
        #pragma unroll
        for (int inst = 0; inst < 4; inst++) {
            int h = inst >> 1, row = (inst & 1) ? i1 : i0;
            size_t base = ((size_t)(sb0 + 32*h)*NN + row)*HH + og;
            ulonglong2 s0; s0.x = acc2[inst][0]; s0.y = acc2[inst][1];
            ulonglong2 s1; s1.x = acc2[inst][2]; s1.y = acc2[inst][3];
            *reinterpret_cast<ulonglong2*>(&g_agg[base])   = s0;
            *reinterpret_cast<ulonglong2*>(&g_agg[base+4]) = s1;
        }
    }
}

// ---------------------------------------------------------------------------
// Node MLP kernel: 64 ->relu-> 64 ->relu-> 64 -> 4. 2 samples/CTA, 128 thr.
// Single in-place activation buffer. blockIdx.y selects mean(0)/var(1).
// ---------------------------------------------------------------------------
struct NodeSmem {
    float sW1[64*64];
    float sW2[64*64];
    float sW3[64*4];
    float buf[2][NN][AST];
    float sb1[64];
    float sb2[64];
    float sb3[8];
};

__device__ __forceinline__ void gemm4_compute(
    const float* __restrict__ in,
    const float* __restrict__ sW, const float* __restrict__ sb,
    int i0, int i1, int og, ull acc[4][4])
{
    const int HOFF = NN*AST;
    const float* rp[4] = { in + i0*AST, in + i1*AST,
                           in + HOFF + i0*AST, in + HOFF + i1*AST };
    {
        ulonglong2 bq0 = *reinterpret_cast<const ulonglong2*>(&sb[og]);
        ulonglong2 bq1 = *reinterpret_cast<const ulonglong2*>(&sb[og+4]);
        ull bp[4] = {bq0.x, bq0.y, bq1.x, bq1.y};
        #pragma unroll
        for (int inst = 0; inst < 4; inst++)
            #pragma unroll
            for (int q = 0; q < 4; q++) acc[inst][q] = bp[q];
    }
    #pragma unroll 2
    for (int k4 = 0; k4 < 64; k4 += 4) {
        float ha[4][4];
        #pragma unroll
        for (int inst = 0; inst < 4; inst++) {
            float4 hv = *reinterpret_cast<const float4*>(rp[inst] + k4);
            ha[inst][0]=hv.x; ha[inst][1]=hv.y; ha[inst][2]=hv.z; ha[inst][3]=hv.w;
        }
        #pragma unroll
        for (int kk = 0; kk < 4; kk++) {
            ulonglong2 w0 = *reinterpret_cast<const ulonglong2*>(&sW[(k4+kk)*64+og]);
            ulonglong2 w1 = *reinterpret_cast<const ulonglong2*>(&sW[(k4+kk)*64+og+4]);
            ull wv[4] = {w0.x, w0.y, w1.x, w1.y};
            #pragma unroll
            for (int inst = 0; inst < 4; inst++) {
                ull hd; PACKDUP(hd, ha[inst][kk]);
                #pragma unroll
                for (int q = 0; q < 4; q++) FFMA2(acc[inst][q], hd, wv[q]);
            }
        }
    }
}

__device__ __forceinline__ void gemm4_store_relu(
    float* __restrict__ op, int i0, int i1, int og, ull acc[4][4])
{
    const int HOFF = NN*AST;
    float* wp4[4] = { op + i0*AST, op + i1*AST,
                      op + HOFF + i0*AST, op + HOFF + i1*AST };
    #pragma unroll
    for (int inst = 0; inst < 4; inst++) {
        float x0,x1,x2,x3,x4,x5,x6,x7;
        UNPACK2(x0,x1,acc[inst][0]); UNPACK2(x2,x3,acc[inst][1]);
        UNPACK2(x4,x5,acc[inst][2]); UNPACK2(x6,x7,acc[inst][3]);
        *reinterpret_cast<float4*>(wp4[inst]+og) =
            make_float4(fmaxf(x0,0.f),fmaxf(x1,0.f),fmaxf(x2,0.f),fmaxf(x3,0.f));
        *reinterpret_cast<float4*>(wp4[inst]+og+4) =
            make_float4(fmaxf(x4,0.f),fmaxf(x5,0.f),fmaxf(x6,0.f),fmaxf(x7,0.f));
    }
}

__global__ __launch_bounds__(128, 4) void node_kernel(
    const float* __restrict__ mW1, const float* __restrict__ mb1,
    const float* __restrict__ mW2, const float* __restrict__ mb2,
    const float* __restrict__ mW3, const float* __restrict__ mb3,
    const float* __restrict__ vW1, const float* __restrict__ vb1,
    const float* __restrict__ vW2, const float* __restrict__ vb2,
    const float* __restrict__ vW3, const float* __restrict__ vb3,
    float* __restrict__ out, int t)
{
    extern __shared__ char smem_raw[];
    NodeSmem& S = *reinterpret_cast<NodeSmem*>(smem_raw);

    const int tid = threadIdx.x;
    const int p   = blockIdx.x;
    const int is_var = blockIdx.y;
    const int bs  = p >> 5;
    const int c0  = p & 31;

    const float* W1 = is_var ? vW1 : mW1;
    const float* W2 = is_var ? vW2 : mW2;
    const float* W3 = is_var ? vW3 : mW3;
    const float* b1 = is_var ? vb1 : mb1;
    const float* b2 = is_var ? vb2 : mb2;
    const float* b3 = is_var ? vb3 : mb3;

    {
        const float4* w1v = reinterpret_cast<const float4*>(W1);
        const float4* w2v = reinterpret_cast<const float4*>(W2);
        float4* s1 = reinterpret_cast<float4*>(S.sW1);
        float4* s2 = reinterpret_cast<float4*>(S.sW2);
        #pragma unroll
        for (int i = tid; i < 1024; i += 128) { s1[i] = w1v[i]; s2[i] = w2v[i]; }
        S.sW3[tid] = W3[tid]; S.sW3[tid+128] = W3[tid+128];
    }
    if (tid < 64) { S.sb1[tid] = b1[tid]; S.sb2[tid] = b2[tid]; }
    if (tid < 4)  S.sb3[tid] = b3[tid];
    if (tid >= 4 && tid < 8) S.sb3[tid] = 0.f;

    const int sbase = bs*64 + c0;
    for (int v = tid; v < 960; v += 128) {
        int h = v >= 480, vv = v - 480*h;
        const float4* src = reinterpret_cast<const float4*>(g_agg)
                            + (size_t)(sbase + 32*h)*480 + vv;
        int row = vv >> 4, cp = vv & 15;
        *reinterpret_cast<float4*>(&S.buf[h][row][cp*4]) = *src;
    }
    __syncthreads();

    const int ig = tid >> 3, cg = tid & 7;
    const int i0 = ig*2, i1 = i0+1, og = cg*8;

    ull acc[4][4];
    if (tid < 120) gemm4_compute(&S.buf[0][0][0], S.sW1, S.sb1, i0, i1, og, acc);
    __syncthreads();
    if (tid < 120) gemm4_store_relu(&S.buf[0][0][0], i0, i1, og, acc);
    __syncthreads();
    if (tid < 120) gemm4_compute(&S.buf[0][0][0], S.sW2, S.sb2, i0, i1, og, acc);
    __syncthreads();
    if (tid < 120) gemm4_store_relu(&S.buf[0][0][0], i0, i1, og, acc);
    __syncthreads();

    // Layer 3: 64 -> 4 (60 threads: (half, node))
    if (tid < 60) {
        const int h = (tid >= 30) ? 1 : 0, n = tid - 30*h;
        const float* hr = &S.buf[h][n][0];
        ulonglong2 b3q = *reinterpret_cast<const ulonglong2*>(&S.sb3[0]);
        ull a01 = b3q.x, a23 = b3q.y;
        #pragma unroll 4
        for (int k4 = 0; k4 < 64; k4 += 4) {
            float4 hv = *reinterpret_cast<const float4*>(hr + k4);
            float ha[4] = {hv.x, hv.y, hv.z, hv.w};
            #pragma unroll
            for (int kk = 0; kk < 4; kk++) {
                ulonglong2 w = *reinterpret_cast<const ulonglong2*>(&S.sW3[(k4+kk)*4]);
                ull hd; PACKDUP(hd, ha[kk]);
                FFMA2(a01, hd, w.x);
                FFMA2(a23, hd, w.y);
            }
        }
        float v0,v1,v2,v3;
        UNPACK2(v0,v1,a01); UNPACK2(v2,v3,a23);
        float v[4] = {v0,v1,v2,v3};
        if (is_var) {
            #pragma unroll
            for (int q = 0; q < 4; q++) {
                float x = v[q];
                float sp = (x > 20.f) ? x : log1pf(expf(x));
                v[q] = fminf(fmaxf(sp, 1e-8f), 100.f);
            }
        }
        const int c = c0 + 32*h;
        const int s = bs*64 + c;
        if (!is_var && t == 0)
            *reinterpret_cast<float4*>(&g_mu[(size_t)s*120 + n*4]) =
                make_float4(v[0],v[1],v[2],v[3]);
        const int kt = 2*c + t;
        if (kt < TOUT) {
            size_t o = (((size_t)bs*TOUT + kt)*NN + n)*FF;
            *reinterpret_cast<float4*>(&out[o + (is_var ? (size_t)VAROFF : 0)]) =
                make_float4(v[0],v[1],v[2],v[3]);
        }
    }
}

// ---------------------------------------------------------------------------
extern "C" void kernel_launch(void* const* d_in, const int* in_sizes, int n_in,
                              void* d_out, int out_size) {
    const float* data    = (const float*)d_in[0];
    const float* graph   = (const float*)d_in[1];
    const float* msg_W1  = (const float*)d_in[2];
    const float* msg_b1  = (const float*)d_in[3];
    const float* msg_W2  = (const float*)d_in[4];
    const float* msg_b2  = (const float*)d_in[5];
    const float* mean_W1 = (const float*)d_in[6];
    const float* mean_b1 = (const float*)d_in[7];
    const float* mean_W2 = (const float*)d_in[8];
    const float* mean_b2 = (const float*)d_in[9];
    const float* mean_W3 = (const float*)d_in[10];
    const float* mean_b3 = (const float*)d_in[11];
    const float* var_W1  = (const float*)d_in[12];
    const float* var_b1  = (const float*)d_in[13];
    const float* var_W2  = (const float*)d_in[14];
    const float* var_b2  = (const float*)d_in[15];
    const float* var_W3  = (const float*)d_in[16];
    const float* var_b3  = (const float*)d_in[17];
    float* out = (float*)d_out;

    cudaFuncSetAttribute(edge_kernel, cudaFuncAttributeMaxDynamicSharedMemorySize,
                         (int)sizeof(EdgeSmem));
    cudaFuncSetAttribute(node_kernel, cudaFuncAttributeMaxDynamicSharedMemorySize,
                         (int)sizeof(NodeSmem));

    dim3 ngrid(NSAMP/2, 2);
    for (int t = 0; t < 2; t++) {
        edge_kernel<<<NSAMP/2, 128, sizeof(EdgeSmem)>>>(data, t, graph,
                                    msg_W1, msg_b1, msg_W2, msg_b2);
        node_kernel<<<ngrid, 128, sizeof(NodeSmem)>>>(
            mean_W1, mean_b1, mean_W2, mean_b2, mean_W3, mean_b3,
            var_W1,  var_b1,  var_W2,  var_b2,  var_W3,  var_b3,
            out, t);
    }
}

// round 7
// speedup vs baseline: 3.2361x; 1.0029x over previous
#include <cuda_runtime.h>
#include <math.h>

typedef unsigned long long ull;

#define NN 30
#define FF 4
#define HH 64
#define NSAMP 2048          // 32 * 64
#define TOUT 127
#define VAROFF (32*127*30*4)
#define AST 68              // activation row stride (floats), bank-staggered
#define GST 36              // dense-graph row stride (floats), bank-staggered

// Scratch (allocation-free rule: __device__ globals)
__device__ float g_agg[(size_t)NSAMP * NN * HH];   // 15.7 MB
__device__ float g_mu [(size_t)NSAMP * NN * FF];   // 0.98 MB

// ---- packed f32x2 helpers (sm_103a) ---------------------------------------
#define FFMA2(acc, a, b) \
    asm("fma.rn.f32x2 %0, %1, %2, %0;" : "+l"(acc) : "l"(a), "l"(b))
#define MUL2(d, a, b) \
    asm("mul.rn.f32x2 %0, %1, %2;" : "=l"(d) : "l"(a), "l"(b))
#define PACKDUP(d, x) \
    asm("mov.b64 %0, {%1, %1};" : "=l"(d) : "r"(__float_as_uint(x)))
#define UNPACK2(x, y, p) \
    asm("mov.b64 {%0, %1}, %2;" : "=f"(x), "=f"(y) : "l"(p))
// acc += gdup * relu(apair + bpair)
#define AGG_STEP(acc, apair, bpair, gdup) \
    asm("{\n\t.reg .b32 lo, hi;\n\t.reg .b64 t;\n\t" \
        "add.rn.f32x2 t, %1, %2;\n\t" \
        "mov.b64 {lo, hi}, t;\n\t" \
        "max.f32 lo, lo, 0f00000000;\n\t" \
        "max.f32 hi, hi, 0f00000000;\n\t" \
        "mov.b64 t, {lo, hi};\n\t" \
        "fma.rn.f32x2 %0, %3, t, %0;\n\t}" \
        : "+l"(acc) : "l"(apair), "l"(bpair), "l"(gdup))

// ---------------------------------------------------------------------------
// Edge kernel: 2 samples per CTA, 128 threads, 120 active. H overwrites sB
// in place after a barrier.
// ---------------------------------------------------------------------------
#define SB_H (32*AST)       // half-stride inside sB (floats)

struct EdgeSmem {
    float sW2[64*64];           // 16 KB
    float sW1[8*64];            //  2 KB
    float sB[2][32][AST];       // 17.4 KB (rows 30,31 zero) ; becomes H
    float sgm[NN][GST];         //  4.3 KB dense graph, zero diagonal
    float sx[2][128];           //  1 KB
    float sb1[64];
    float sb2[64];
};

__global__ __launch_bounds__(128, 5) void edge_kernel(
    const float* __restrict__ data, int mode,
    const float* __restrict__ graph,
    const float* __restrict__ W1, const float* __restrict__ b1,
    const float* __restrict__ W2, const float* __restrict__ b2)
{
    extern __shared__ char smem_raw[];
    EdgeSmem& S = *reinterpret_cast<EdgeSmem*>(smem_raw);

    const int tid = threadIdx.x;
    const int p   = blockIdx.x;
    const int bs  = p >> 5;
    const int c0  = p & 31;

    {
        const float4* w2v = reinterpret_cast<const float4*>(W2);
        float4* d2 = reinterpret_cast<float4*>(S.sW2);
        #pragma unroll
        for (int i = tid; i < 1024; i += 128) d2[i] = w2v[i];
        const float4* w1v = reinterpret_cast<const float4*>(W1);
        float4* d1 = reinterpret_cast<float4*>(S.sW1);
        d1[tid] = w1v[tid];
    }
    if (tid < 64) { S.sb1[tid] = b1[tid]; S.sb2[tid] = b2[tid]; }
    for (int e = tid; e < 900; e += 128) {
        int i = e / 30, j = e - i*30;
        S.sgm[i][j] = (i == j) ? 0.f
                      : graph[(size_t)bs*870 + i*29 + j - (j > i)];
    }
    if (tid < 30) { S.sgm[tid][30] = 0.f; S.sgm[tid][31] = 0.f; }
    if (tid < 68) {
        S.sB[0][30][tid] = 0.f; S.sB[0][31][tid] = 0.f;
        S.sB[1][30][tid] = 0.f; S.sB[1][31][tid] = 0.f;
    }
    for (int v = tid; v < 240; v += 128) {
        int h = v >= 120, idx = v - 120*h;
        int cc = c0 + 32*h, ss = bs*64 + cc;
        S.sx[h][idx] = (mode == 0)
            ? data[((size_t)bs*128 + 2*cc)*120 + idx]
            : g_mu[(size_t)ss*120 + idx];
    }
    __syncthreads();

    const int ig = tid >> 3, cg = tid & 7;
    const int i0 = ig*2, i1 = i0+1, og = cg*8;
    // single base pointer for this thread's 4 row-instances in sB
    float* rb = &S.sB[0][i0][og];     // +0, +AST, +SB_H, +SB_H+AST

    ull aA[4][4];               // A-projection, registers
    float cnt0 = 0.f, cnt1 = 0.f;

    // ---- projections: A (registers) + B (smem) ----
    if (tid < 120) {
        float xr[4][4];
        #pragma unroll
        for (int inst = 0; inst < 4; inst++) {
            int h = inst >> 1, row = (inst & 1) ? i1 : i0;
            float4 xv = *reinterpret_cast<const float4*>(&S.sx[h][row*4]);
            xr[inst][0]=xv.x; xr[inst][1]=xv.y; xr[inst][2]=xv.z; xr[inst][3]=xv.w;
        }
        ull aB[4][4];
        {
            ulonglong2 bq0 = *reinterpret_cast<const ulonglong2*>(&S.sb1[og]);
            ulonglong2 bq1 = *reinterpret_cast<const ulonglong2*>(&S.sb1[og+4]);
            ull bp[4] = {bq0.x, bq0.y, bq1.x, bq1.y};
            #pragma unroll
            for (int inst = 0; inst < 4; inst++)
                #pragma unroll
                for (int q = 0; q < 4; q++) { aA[inst][q] = bp[q]; aB[inst][q] = 0ULL; }
        }
        #pragma unroll
        for (int r = 0; r < 4; r++) {
            ulonglong2 wa0 = *reinterpret_cast<const ulonglong2*>(&S.sW1[r*64+og]);
            ulonglong2 wa1 = *reinterpret_cast<const ulonglong2*>(&S.sW1[r*64+og+4]);
            ulonglong2 wb0 = *reinterpret_cast<const ulonglong2*>(&S.sW1[(r+4)*64+og]);
            ulonglong2 wb1 = *reinterpret_cast<const ulonglong2*>(&S.sW1[(r+4)*64+og+4]);
            ull wa[4] = {wa0.x, wa0.y, wa1.x, wa1.y};
            ull wb[4] = {wb0.x, wb0.y, wb1.x, wb1.y};
            #pragma unroll
            for (int inst = 0; inst < 4; inst++) {
                ull xd; PACKDUP(xd, xr[inst][r]);
                #pragma unroll
                for (int q = 0; q < 4; q++) {
                    FFMA2(aA[inst][q], xd, wa[q]);
                    FFMA2(aB[inst][q], xd, wb[q]);
                }
            }
        }
        #pragma unroll
        for (int inst = 0; inst < 4; inst++) {
            float* dst = rb + (inst >> 1)*SB_H + (inst & 1)*AST;
            ulonglong2 s0; s0.x = aB[inst][0]; s0.y = aB[inst][1];
            ulonglong2 s1; s1.x = aB[inst][2]; s1.y = aB[inst][3];
            *reinterpret_cast<ulonglong2*>(dst)   = s0;
            *reinterpret_cast<ulonglong2*>(dst+4) = s1;
        }
    }
    __syncthreads();

    // ---- masked-ReLU aggregation (acc stays in regs across barrier) ----
    ull acc[4][4];
    if (tid < 120) {
        #pragma unroll
        for (int inst = 0; inst < 4; inst++)
            #pragma unroll
            for (int q = 0; q < 4; q++) acc[inst][q] = 0ULL;

        const float* bbase = &S.sB[0][0][og];
        #pragma unroll 2
        for (int j4 = 0; j4 < 32; j4 += 4) {
            float4 gA = *reinterpret_cast<const float4*>(&S.sgm[i0][j4]);
            float4 gB = *reinterpret_cast<const float4*>(&S.sgm[i1][j4]);
            cnt0 += gA.x + gA.y + gA.z + gA.w;
            cnt1 += gB.x + gB.y + gB.z + gB.w;
            float g0a[4] = {gA.x, gA.y, gA.z, gA.w};
            float g1a[4] = {gB.x, gB.y, gB.z, gB.w};
            #pragma unroll
            for (int jj = 0; jj < 4; jj++) {
                const float* bj = bbase + (j4 + jj)*AST;
                ulonglong2 bh00 = *reinterpret_cast<const ulonglong2*>(bj);
                ulonglong2 bh01 = *reinterpret_cast<const ulonglong2*>(bj+4);
                ulonglong2 bh10 = *reinterpret_cast<const ulonglong2*>(bj+SB_H);
                ulonglong2 bh11 = *reinterpret_cast<const ulonglong2*>(bj+SB_H+4);
                ull b0v[4] = {bh00.x, bh00.y, bh01.x, bh01.y};
                ull b1v[4] = {bh10.x, bh10.y, bh11.x, bh11.y};
                ull gd0, gd1; PACKDUP(gd0, g0a[jj]); PACKDUP(gd1, g1a[jj]);
                #pragma unroll
                for (int q = 0; q < 4; q++) {
                    AGG_STEP(acc[0][q], aA[0][q], b0v[q], gd0);
                    AGG_STEP(acc[1][q], aA[1][q], b0v[q], gd1);
                    AGG_STEP(acc[2][q], aA[2][q], b1v[q], gd0);
                    AGG_STEP(acc[3][q], aA[3][q], b1v[q], gd1);
                }
            }
        }
    }
    __syncthreads();            // all sB reads complete
    if (tid < 120) {
        #pragma unroll
        for (int inst = 0; inst < 4; inst++) {   // H overwrites sB
            float* dst = rb + (inst >> 1)*SB_H + (inst & 1)*AST;
            ulonglong2 s0; s0.x = acc[inst][0]; s0.y = acc[inst][1];
            ulonglong2 s1; s1.x = acc[inst][2]; s1.y = acc[inst][3];
            *reinterpret_cast<ulonglong2*>(dst)   = s0;
            *reinterpret_cast<ulonglong2*>(dst+4) = s1;
        }
    }
    __syncthreads();

    // ---- agg = H @ W2 + cnt * b2 (H lives in sB now) ----
    if (tid < 120) {
        ull acc2[4][4];
        {
            ulonglong2 bq0 = *reinterpret_cast<const ulonglong2*>(&S.sb2[og]);
            ulonglong2 bq1 = *reinterpret_cast<const ulonglong2*>(&S.sb2[og+4]);
            ull bp[4] = {bq0.x, bq0.y, bq1.x, bq1.y};
            ull cd0, cd1; PACKDUP(cd0, cnt0); PACKDUP(cd1, cnt1);
            #pragma unroll
            for (int q = 0; q < 4; q++) {
                MUL2(acc2[0][q], cd0, bp[q]);
                MUL2(acc2[1][q], cd1, bp[q]);
                MUL2(acc2[2][q], cd0, bp[q]);
                MUL2(acc2[3][q], cd1, bp[q]);
            }
        }
        const float* hb = &S.sB[0][i0][0];   // +0,+AST,+SB_H,+SB_H+AST
        #pragma unroll 2
        for (int k4 = 0; k4 < 64; k4 += 4) {
            float4 h0v = *reinterpret_cast<const float4*>(hb + k4);
            float4 h1v = *reinterpret_cast<const float4*>(hb + AST + k4);
            float4 h2v = *reinterpret_cast<const float4*>(hb + SB_H + k4);
            float4 h3v = *reinterpret_cast<const float4*>(hb + SB_H + AST + k4);
            float ha[4][4] = {{h0v.x,h0v.y,h0v.z,h0v.w},{h1v.x,h1v.y,h1v.z,h1v.w},
                              {h2v.x,h2v.y,h2v.z,h2v.w},{h3v.x,h3v.y,h3v.z,h3v.w}};
            #pragma unroll
            for (int kk = 0; kk < 4; kk++) {
                ulonglong2 w0 = *reinterpret_cast<const ulonglong2*>(&S.sW2[(k4+kk)*64+og]);
                ulonglong2 w1 = *reinterpret_cast<const ulonglong2*>(&S.sW2[(k4+kk)*64+og+4]);
                ull wv[4] = {w0.x, w0.y, w1.x, w1.y};
                #pragma unroll
                for (int inst = 0; inst < 4; inst++) {
                    ull hd; PACKDUP(hd, ha[inst][kk]);
                    #pragma unroll
                    for (int q = 0; q < 4; q++) FFMA2(acc2[inst][q], hd, wv[q]);
                }
            }
        }
        const int sb0 = bs*64 + c0;
        #pragma unroll
        for (int inst = 0; inst < 4; inst++) {
            int h = inst >> 1, row = (inst & 1) ? i1 : i0;
            size_t base = ((size_t)(sb0 + 32*h)*NN + row)*HH + og;
            ulonglong2 s0; s0.x = acc2[inst][0]; s0.y = acc2[inst][1];
            ulonglong2 s1; s1.x = acc2[inst][2]; s1.y = acc2[inst][3];
            *reinterpret_cast<ulonglong2*>(&g_agg[base])   = s0;
            *reinterpret_cast<ulonglong2*>(&g_agg[base+4]) = s1;
        }
    }
}

// ---------------------------------------------------------------------------
// Node MLP kernel: 64 ->relu-> 64 ->relu-> 64 -> 4. 2 samples/CTA, 128 thr.
// SINGLE weight buffer: sW holds W1 for layer 1, then is overwritten with W2.
// blockIdx.y selects mean(0)/var(1).
// ---------------------------------------------------------------------------
#define BUF_H (NN*AST)      // half-stride inside buf (floats)

struct NodeSmem {
    float sW[64*64];            // 16 KB, W1 then W2
    float sW3[64*4];
    float buf[2][NN][AST];      // 16.3 KB
    float sb1[64];
    float sb2[64];
    float sb3[8];
};

__device__ __forceinline__ void gemm4_compute(
    const float* __restrict__ r0,      // &buf[0][i0][0]
    const float* __restrict__ sW, const float* __restrict__ sb,
    int og, ull acc[4][4])
{
    {
        ulonglong2 bq0 = *reinterpret_cast<const ulonglong2*>(&sb[og]);
        ulonglong2 bq1 = *reinterpret_cast<const ulonglong2*>(&sb[og+4]);
        ull bp[4] = {bq0.x, bq0.y, bq1.x, bq1.y};
        #pragma unroll
        for (int inst = 0; inst < 4; inst++)
            #pragma unroll
            for (int q = 0; q < 4; q++) acc[inst][q] = bp[q];
    }
    #pragma unroll 2
    for (int k4 = 0; k4 < 64; k4 += 4) {
        float4 h0v = *reinterpret_cast<const float4*>(r0 + k4);
        float4 h1v = *reinterpret_cast<const float4*>(r0 + AST + k4);
        float4 h2v = *reinterpret_cast<const float4*>(r0 + BUF_H + k4);
        float4 h3v = *reinterpret_cast<const float4*>(r0 + BUF_H + AST + k4);
        float ha[4][4] = {{h0v.x,h0v.y,h0v.z,h0v.w},{h1v.x,h1v.y,h1v.z,h1v.w},
                          {h2v.x,h2v.y,h2v.z,h2v.w},{h3v.x,h3v.y,h3v.z,h3v.w}};
        #pragma unroll
        for (int kk = 0; kk < 4; kk++) {
            ulonglong2 w0 = *reinterpret_cast<const ulonglong2*>(&sW[(k4+kk)*64+og]);
            ulonglong2 w1 = *reinterpret_cast<const ulonglong2*>(&sW[(k4+kk)*64+og+4]);
            ull wv[4] = {w0.x, w0.y, w1.x, w1.y};
            #pragma unroll
            for (int inst = 0; inst < 4; inst++) {
                ull hd; PACKDUP(hd, ha[inst][kk]);
                #pragma unroll
                for (int q = 0; q < 4; q++) FFMA2(acc[inst][q], hd, wv[q]);
            }
        }
    }
}

__device__ __forceinline__ void gemm4_store_relu(
    float* __restrict__ w0, int og, ull acc[4][4])   // w0 = &buf[0][i0][og]
{
    #pragma unroll
    for (int inst = 0; inst < 4; inst++) {
        float* dst = w0 + (inst >> 1)*BUF_H + (inst & 1)*AST;
        float x0,x1,x2,x3,x4,x5,x6,x7;
        UNPACK2(x0,x1,acc[inst][0]); UNPACK2(x2,x3,acc[inst][1]);
        UNPACK2(x4,x5,acc[inst][2]); UNPACK2(x6,x7,acc[inst][3]);
        *reinterpret_cast<float4*>(dst) =
            make_float4(fmaxf(x0,0.f),fmaxf(x1,0.f),fmaxf(x2,0.f),fmaxf(x3,0.f));
        *reinterpret_cast<float4*>(dst+4) =
            make_float4(fmaxf(x4,0.f),fmaxf(x5,0.f),fmaxf(x6,0.f),fmaxf(x7,0.f));
    }
}

__global__ __launch_bounds__(128, 6) void node_kernel(
    const float* __restrict__ mW1, const float* __restrict__ mb1,
    const float* __restrict__ mW2, const float* __restrict__ mb2,
    const float* __restrict__ mW3, const float* __restrict__ mb3,
    const float* __restrict__ vW1, const float* __restrict__ vb1,
    const float* __restrict__ vW2, const float* __restrict__ vb2,
    const float* __restrict__ vW3, const float* __restrict__ vb3,
    float* __restrict__ out, int t)
{
    extern __shared__ char smem_raw[];
    NodeSmem& S = *reinterpret_cast<NodeSmem*>(smem_raw);

    const int tid = threadIdx.x;
    const int p   = blockIdx.x;
    const int is_var = blockIdx.y;
    const int bs  = p >> 5;
    const int c0  = p & 31;

    const float* W1 = is_var ? vW1 : mW1;
    const float* W2 = is_var ? vW2 : mW2;
    const float* W3 = is_var ? vW3 : mW3;
    const float* b1 = is_var ? vb1 : mb1;
    const float* b2 = is_var ? vb2 : mb2;
    const float* b3 = is_var ? vb3 : mb3;

    {
        const float4* w1v = reinterpret_cast<const float4*>(W1);
        float4* s1 = reinterpret_cast<float4*>(S.sW);
        #pragma unroll
        for (int i = tid; i < 1024; i += 128) s1[i] = w1v[i];
        S.sW3[tid] = W3[tid]; S.sW3[tid+128] = W3[tid+128];
    }
    if (tid < 64) { S.sb1[tid] = b1[tid]; S.sb2[tid] = b2[tid]; }
    if (tid < 4)  S.sb3[tid] = b3[tid];
    if (tid >= 4 && tid < 8) S.sb3[tid] = 0.f;

    const int sbase = bs*64 + c0;
    for (int v = tid; v < 960; v += 128) {
        int h = v >= 480, vv = v - 480*h;
        const float4* src = reinterpret_cast<const float4*>(g_agg)
                            + (size_t)(sbase + 32*h)*480 + vv;
        int row = vv >> 4, cp = vv & 15;
        *reinterpret_cast<float4*>(&S.buf[h][row][cp*4]) = *src;
    }
    __syncthreads();

    const int ig = tid >> 3, cg = tid & 7;
    const int i0 = ig*2, og = cg*8;
    const float* r0 = &S.buf[0][i0][0];
    float*       w0 = &S.buf[0][i0][og];

    ull acc[4][4];
    // Layer 1 (reads sW = W1)
    if (tid < 120) gemm4_compute(r0, S.sW, S.sb1, og, acc);
    __syncthreads();
    // store relu + overwrite sW with W2
    if (tid < 120) gemm4_store_relu(w0, og, acc);
    {
        const float4* w2v = reinterpret_cast<const float4*>(W2);
        float4* s1 = reinterpret_cast<float4*>(S.sW);
        #pragma unroll
        for (int i = tid; i < 1024; i += 128) s1[i] = w2v[i];
    }
    __syncthreads();
    // Layer 2 (reads sW = W2)
    if (tid < 120) gemm4_compute(r0, S.sW, S.sb2, og, acc);
    __syncthreads();
    if (tid < 120) gemm4_store_relu(w0, og, acc);
    __syncthreads();

    // Layer 3: 64 -> 4 (60 threads: (half, node))
    if (tid < 60) {
        const int h = (tid >= 30) ? 1 : 0, n = tid - 30*h;
        const float* hr = &S.buf[h][n][0];
        ulonglong2 b3q = *reinterpret_cast<const ulonglong2*>(&S.sb3[0]);
        ull a01 = b3q.x, a23 = b3q.y;
        #pragma unroll 4
        for (int k4 = 0; k4 < 64; k4 += 4) {
            float4 hv = *reinterpret_cast<const float4*>(hr + k4);
            float ha[4] = {hv.x, hv.y, hv.z, hv.w};
            #pragma unroll
            for (int kk = 0; kk < 4; kk++) {
                ulonglong2 w = *reinterpret_cast<const ulonglong2*>(&S.sW3[(k4+kk)*4]);
                ull hd; PACKDUP(hd, ha[kk]);
                FFMA2(a01, hd, w.x);
                FFMA2(a23, hd, w.y);
            }
        }
        float v0,v1,v2,v3;
        UNPACK2(v0,v1,a01); UNPACK2(v2,v3,a23);
        float v[4] = {v0,v1,v2,v3};
        if (is_var) {
            #pragma unroll
            for (int q = 0; q < 4; q++) {
                float x = v[q];
                float sp = (x > 20.f) ? x : log1pf(expf(x));
                v[q] = fminf(fmaxf(sp, 1e-8f), 100.f);
            }
        }
        const int c = c0 + 32*h;
        const int s = bs*64 + c;
        if (!is_var && t == 0)
            *reinterpret_cast<float4*>(&g_mu[(size_t)s*120 + n*4]) =
                make_float4(v[0],v[1],v[2],v[3]);
        const int kt = 2*c + t;
        if (kt < TOUT) {
            size_t o = (((size_t)bs*TOUT + kt)*NN + n)*FF;
            *reinterpret_cast<float4*>(&out[o + (is_var ? (size_t)VAROFF : 0)]) =
                make_float4(v[0],v[1],v[2],v[3]);
        }
    }
}

// ---------------------------------------------------------------------------
extern "C" void kernel_launch(void* const* d_in, const int* in_sizes, int n_in,
                              void* d_out, int out_size) {
    const float* data    = (const float*)d_in[0];
    const float* graph   = (const float*)d_in[1];
    const float* msg_W1  = (const float*)d_in[2];
    const float* msg_b1  = (const float*)d_in[3];
    const float* msg_W2  = (const float*)d_in[4];
    const float* msg_b2  = (const float*)d_in[5];
    const float* mean_W1 = (const float*)d_in[6];
    const float* mean_b1 = (const float*)d_in[7];
    const float* mean_W2 = (const float*)d_in[8];
    const float* mean_b2 = (const float*)d_in[9];
    const float* mean_W3 = (const float*)d_in[10];
    const float* mean_b3 = (const float*)d_in[11];
    const float* var_W1  = (const float*)d_in[12];
    const float* var_b1  = (const float*)d_in[13];
    const float* var_W2  = (const float*)d_in[14];
    const float* var_b2  = (const float*)d_in[15];
    const float* var_W3  = (const float*)d_in[16];
    const float* var_b3  = (const float*)d_in[17];
    float* out = (float*)d_out;

    cudaFuncSetAttribute(edge_kernel, cudaFuncAttributeMaxDynamicSharedMemorySize,
                         (int)sizeof(EdgeSmem));
    cudaFuncSetAttribute(node_kernel, cudaFuncAttributeMaxDynamicSharedMemorySize,
                         (int)sizeof(NodeSmem));

    dim3 ngrid(NSAMP/2, 2);
    for (int t = 0; t < 2; t++) {
        edge_kernel<<<NSAMP/2, 128, sizeof(EdgeSmem)>>>(data, t, graph,
                                    msg_W1, msg_b1, msg_W2, msg_b2);
        node_kernel<<<ngrid, 128, sizeof(NodeSmem)>>>(
            mean_W1, mean_b1, mean_W2, mean_b2, mean_W3, mean_b3,
            var_W1,  var_b1,  var_W2,  var_b2,  var_W3,  var_b3,
            out, t);
    }
}

// round 8
// speedup vs baseline: 3.9954x; 1.2346x over previous
#include <cuda_runtime.h>
#include <math.h>

typedef unsigned long long ull;

#define NN 30
#define FF 4
#define HH 64
#define NSAMP 2048          // 32 * 64
#define TOUT 127
#define VAROFF (32*127*30*4)
#define AST 68              // activation row stride (floats), bank-staggered
#define GST 36              // dense-graph row stride (floats), bank-staggered

// Scratch (allocation-free rule: __device__ globals)
__device__ float g_agg[(size_t)NSAMP * NN * HH];   // 15.7 MB
__device__ float g_mu [(size_t)NSAMP * NN * FF];   // 0.98 MB

// ---- packed f32x2 helpers (sm_103a) ---------------------------------------
#define FFMA2(acc, a, b) \
    asm("fma.rn.f32x2 %0, %1, %2, %0;" : "+l"(acc) : "l"(a), "l"(b))
#define MUL2(d, a, b) \
    asm("mul.rn.f32x2 %0, %1, %2;" : "=l"(d) : "l"(a), "l"(b))
#define PACKDUP(d, x) \
    asm("mov.b64 %0, {%1, %1};" : "=l"(d) : "r"(__float_as_uint(x)))
#define UNPACK2(x, y, p) \
    asm("mov.b64 {%0, %1}, %2;" : "=f"(x), "=f"(y) : "l"(p))
// acc += gdup * relu(apair + bpair)
#define AGG_STEP(acc, apair, bpair, gdup) \
    asm("{\n\t.reg .b32 lo, hi;\n\t.reg .b64 t;\n\t" \
        "add.rn.f32x2 t, %1, %2;\n\t" \
        "mov.b64 {lo, hi}, t;\n\t" \
        "max.f32 lo, lo, 0f00000000;\n\t" \
        "max.f32 hi, hi, 0f00000000;\n\t" \
        "mov.b64 t, {lo, hi};\n\t" \
        "fma.rn.f32x2 %0, %3, t, %0;\n\t}" \
        : "+l"(acc) : "l"(apair), "l"(bpair), "l"(gdup))

// ---------------------------------------------------------------------------
// Edge kernel: 2 samples per CTA, 128 threads, 120 active. H overwrites sB
// in place after a barrier. (unchanged from R7)
// ---------------------------------------------------------------------------
#define SB_H (32*AST)       // half-stride inside sB (floats)

struct EdgeSmem {
    float sW2[64*64];           // 16 KB
    float sW1[8*64];            //  2 KB
    float sB[2][32][AST];       // 17.4 KB (rows 30,31 zero) ; becomes H
    float sgm[NN][GST];         //  4.3 KB dense graph, zero diagonal
    float sx[2][128];           //  1 KB
    float sb1[64];
    float sb2[64];
};

__global__ __launch_bounds__(128, 5) void edge_kernel(
    const float* __restrict__ data, int mode,
    const float* __restrict__ graph,
    const float* __restrict__ W1, const float* __restrict__ b1,
    const float* __restrict__ W2, const float* __restrict__ b2)
{
    extern __shared__ char smem_raw[];
    EdgeSmem& S = *reinterpret_cast<EdgeSmem*>(smem_raw);

    const int tid = threadIdx.x;
    const int p   = blockIdx.x;
    const int bs  = p >> 5;
    const int c0  = p & 31;

    {
        const float4* w2v = reinterpret_cast<const float4*>(W2);
        float4* d2 = reinterpret_cast<float4*>(S.sW2);
        #pragma unroll
        for (int i = tid; i < 1024; i += 128) d2[i] = w2v[i];
        const float4* w1v = reinterpret_cast<const float4*>(W1);
        float4* d1 = reinterpret_cast<float4*>(S.sW1);
        d1[tid] = w1v[tid];
    }
    if (tid < 64) { S.sb1[tid] = b1[tid]; S.sb2[tid] = b2[tid]; }
    for (int e = tid; e < 900; e += 128) {
        int i = e / 30, j = e - i*30;
        S.sgm[i][j] = (i == j) ? 0.f
                      : graph[(size_t)bs*870 + i*29 + j - (j > i)];
    }
    if (tid < 30) { S.sgm[tid][30] = 0.f; S.sgm[tid][31] = 0.f; }
    if (tid < 68) {
        S.sB[0][30][tid] = 0.f; S.sB[0][31][tid] = 0.f;
        S.sB[1][30][tid] = 0.f; S.sB[1][31][tid] = 0.f;
    }
    for (int v = tid; v < 240; v += 128) {
        int h = v >= 120, idx = v - 120*h;
        int cc = c0 + 32*h, ss = bs*64 + cc;
        S.sx[h][idx] = (mode == 0)
            ? data[((size_t)bs*128 + 2*cc)*120 + idx]
            : g_mu[(size_t)ss*120 + idx];
    }
    __syncthreads();

    const int ig = tid >> 3, cg = tid & 7;
    const int i0 = ig*2, i1 = i0+1, og = cg*8;
    float* rb = &S.sB[0][i0][og];     // +0, +AST, +SB_H, +SB_H+AST

    ull aA[4][4];               // A-projection, registers
    float cnt0 = 0.f, cnt1 = 0.f;

    // ---- projections: A (registers) + B (smem) ----
    if (tid < 120) {
        float xr[4][4];
        #pragma unroll
        for (int inst = 0; inst < 4; inst++) {
            int h = inst >> 1, row = (inst & 1) ? i1 : i0;
            float4 xv = *reinterpret_cast<const float4*>(&S.sx[h][row*4]);
            xr[inst][0]=xv.x; xr[inst][1]=xv.y; xr[inst][2]=xv.z; xr[inst][3]=xv.w;
        }
        ull aB[4][4];
        {
            ulonglong2 bq0 = *reinterpret_cast<const ulonglong2*>(&S.sb1[og]);
            ulonglong2 bq1 = *reinterpret_cast<const ulonglong2*>(&S.sb1[og+4]);
            ull bp[4] = {bq0.x, bq0.y, bq1.x, bq1.y};
            #pragma unroll
            for (int inst = 0; inst < 4; inst++)
                #pragma unroll
                for (int q = 0; q < 4; q++) { aA[inst][q] = bp[q]; aB[inst][q] = 0ULL; }
        }
        #pragma unroll
        for (int r = 0; r < 4; r++) {
            ulonglong2 wa0 = *reinterpret_cast<const ulonglong2*>(&S.sW1[r*64+og]);
            ulonglong2 wa1 = *reinterpret_cast<const ulonglong2*>(&S.sW1[r*64+og+4]);
            ulonglong2 wb0 = *reinterpret_cast<const ulonglong2*>(&S.sW1[(r+4)*64+og]);
            ulonglong2 wb1 = *reinterpret_cast<const ulonglong2*>(&S.sW1[(r+4)*64+og+4]);
            ull wa[4] = {wa0.x, wa0.y, wa1.x, wa1.y};
            ull wb[4] = {wb0.x, wb0.y, wb1.x, wb1.y};
            #pragma unroll
            for (int inst = 0; inst < 4; inst++) {
                ull xd; PACKDUP(xd, xr[inst][r]);
                #pragma unroll
                for (int q = 0; q < 4; q++) {
                    FFMA2(aA[inst][q], xd, wa[q]);
                    FFMA2(aB[inst][q], xd, wb[q]);
                }
            }
        }
        #pragma unroll
        for (int inst = 0; inst < 4; inst++) {
            float* dst = rb + (inst >> 1)*SB_H + (inst & 1)*AST;
            ulonglong2 s0; s0.x = aB[inst][0]; s0.y = aB[inst][1];
            ulonglong2 s1; s1.x = aB[inst][2]; s1.y = aB[inst][3];
            *reinterpret_cast<ulonglong2*>(dst)   = s0;
            *reinterpret_cast<ulonglong2*>(dst+4) = s1;
        }
    }
    __syncthreads();

    // ---- masked-ReLU aggregation ----
    ull acc[4][4];
    if (tid < 120) {
        #pragma unroll
        for (int inst = 0; inst < 4; inst++)
            #pragma unroll
            for (int q = 0; q < 4; q++) acc[inst][q] = 0ULL;

        const float* bbase = &S.sB[0][0][og];
        #pragma unroll 2
        for (int j4 = 0; j4 < 32; j4 += 4) {
            float4 gA = *reinterpret_cast<const float4*>(&S.sgm[i0][j4]);
            float4 gB = *reinterpret_cast<const float4*>(&S.sgm[i1][j4]);
            cnt0 += gA.x + gA.y + gA.z + gA.w;
            cnt1 += gB.x + gB.y + gB.z + gB.w;
            float g0a[4] = {gA.x, gA.y, gA.z, gA.w};
            float g1a[4] = {gB.x, gB.y, gB.z, gB.w};
            #pragma unroll
            for (int jj = 0; jj < 4; jj++) {
                const float* bj = bbase + (j4 + jj)*AST;
                ulonglong2 bh00 = *reinterpret_cast<const ulonglong2*>(bj);
                ulonglong2 bh01 = *reinterpret_cast<const ulonglong2*>(bj+4);
                ulonglong2 bh10 = *reinterpret_cast<const ulonglong2*>(bj+SB_H);
                ulonglong2 bh11 = *reinterpret_cast<const ulonglong2*>(bj+SB_H+4);
                ull b0v[4] = {bh00.x, bh00.y, bh01.x, bh01.y};
                ull b1v[4] = {bh10.x, bh10.y, bh11.x, bh11.y};
                ull gd0, gd1; PACKDUP(gd0, g0a[jj]); PACKDUP(gd1, g1a[jj]);
                #pragma unroll
                for (int q = 0; q < 4; q++) {
                    AGG_STEP(acc[0][q], aA[0][q], b0v[q], gd0);
                    AGG_STEP(acc[1][q], aA[1][q], b0v[q], gd1);
                    AGG_STEP(acc[2][q], aA[2][q], b1v[q], gd0);
                    AGG_STEP(acc[3][q], aA[3][q], b1v[q], gd1);
                }
            }
        }
    }
    __syncthreads();            // all sB reads complete
    if (tid < 120) {
        #pragma unroll
        for (int inst = 0; inst < 4; inst++) {   // H overwrites sB
            float* dst = rb + (inst >> 1)*SB_H + (inst & 1)*AST;
            ulonglong2 s0; s0.x = acc[inst][0]; s0.y = acc[inst][1];
            ulonglong2 s1; s1.x = acc[inst][2]; s1.y = acc[inst][3];
            *reinterpret_cast<ulonglong2*>(dst)   = s0;
            *reinterpret_cast<ulonglong2*>(dst+4) = s1;
        }
    }
    __syncthreads();

    // ---- agg = H @ W2 + cnt * b2 ----
    if (tid < 120) {
        ull acc2[4][4];
        {
            ulonglong2 bq0 = *reinterpret_cast<const ulonglong2*>(&S.sb2[og]);
            ulonglong2 bq1 = *reinterpret_cast<const ulonglong2*>(&S.sb2[og+4]);
            ull bp[4] = {bq0.x, bq0.y, bq1.x, bq1.y};
            ull cd0, cd1; PACKDUP(cd0, cnt0); PACKDUP(cd1, cnt1);
            #pragma unroll
            for (int q = 0; q < 4; q++) {
                MUL2(acc2[0][q], cd0, bp[q]);
                MUL2(acc2[1][q], cd1, bp[q]);
                MUL2(acc2[2][q], cd0, bp[q]);
                MUL2(acc2[3][q], cd1, bp[q]);
            }
        }
        const float* hb = &S.sB[0][i0][0];
        #pragma unroll 2
        for (int k4 = 0; k4 < 64; k4 += 4) {
            float4 h0v = *reinterpret_cast<const float4*>(hb + k4);
            float4 h1v = *reinterpret_cast<const float4*>(hb + AST + k4);
            float4 h2v = *reinterpret_cast<const float4*>(hb + SB_H + k4);
            float4 h3v = *reinterpret_cast<const float4*>(hb + SB_H + AST + k4);
            float ha[4][4] = {{h0v.x,h0v.y,h0v.z,h0v.w},{h1v.x,h1v.y,h1v.z,h1v.w},
                              {h2v.x,h2v.y,h2v.z,h2v.w},{h3v.x,h3v.y,h3v.z,h3v.w}};
            #pragma unroll
            for (int kk = 0; kk < 4; kk++) {
                ulonglong2 w0 = *reinterpret_cast<const ulonglong2*>(&S.sW2[(k4+kk)*64+og]);
                ulonglong2 w1 = *reinterpret_cast<const ulonglong2*>(&S.sW2[(k4+kk)*64+og+4]);
                ull wv[4] = {w0.x, w0.y, w1.x, w1.y};
                #pragma unroll
                for (int inst = 0; inst < 4; inst++) {
                    ull hd; PACKDUP(hd, ha[inst][kk]);
                    #pragma unroll
                    for (int q = 0; q < 4; q++) FFMA2(acc2[inst][q], hd, wv[q]);
                }
            }
        }
        const int sb0 = bs*64 + c0;
        #pragma unroll
        for (int inst = 0; inst < 4; inst++) {
            int h = inst >> 1, row = (inst & 1) ? i1 : i0;
            size_t base = ((size_t)(sb0 + 32*h)*NN + row)*HH + og;
            ulonglong2 s0; s0.x = acc2[inst][0]; s0.y = acc2[inst][1];
            ulonglong2 s1; s1.x = acc2[inst][2]; s1.y = acc2[inst][3];
            *reinterpret_cast<ulonglong2*>(&g_agg[base])   = s0;
            *reinterpret_cast<ulonglong2*>(&g_agg[base+4]) = s1;
        }
    }
}

// ---------------------------------------------------------------------------
// Node MLP kernel: 64 ->relu-> 64 ->relu-> 64 -> 4. 4 samples/CTA, 128 thr.
// 8-row x 8-col register tiles (B/FMA = 1.0). Single weight buffer.
// blockIdx.y selects mean(0)/var(1).
// ---------------------------------------------------------------------------
struct NodeSmem {
    float sW[64*64];            // 16 KB, W1 then W2
    float sW3[64*4];
    float buf[120][AST];        // 31.9 KB : inst = smp*30 + row
    float sb1[64];
    float sb2[64];
    float sb3[8];
};

__device__ __forceinline__ void gemm8_compute(
    const float* __restrict__ r0,      // &buf[8*ig][0]
    const float* __restrict__ sW, const float* __restrict__ sb,
    int og, ull acc[8][4])
{
    {
        ulonglong2 bq0 = *reinterpret_cast<const ulonglong2*>(&sb[og]);
        ulonglong2 bq1 = *reinterpret_cast<const ulonglong2*>(&sb[og+4]);
        ull bp[4] = {bq0.x, bq0.y, bq1.x, bq1.y};
        #pragma unroll
        for (int r = 0; r < 8; r++)
            #pragma unroll
            for (int q = 0; q < 4; q++) acc[r][q] = bp[q];
    }
    #pragma unroll 2
    for (int k4 = 0; k4 < 64; k4 += 4) {
        float4 hv[8];
        #pragma unroll
        for (int r = 0; r < 8; r++)
            hv[r] = *reinterpret_cast<const float4*>(r0 + r*AST + k4);
        float ha[8][4];
        #pragma unroll
        for (int r = 0; r < 8; r++) {
            ha[r][0]=hv[r].x; ha[r][1]=hv[r].y; ha[r][2]=hv[r].z; ha[r][3]=hv[r].w;
        }
        #pragma unroll
        for (int kk = 0; kk < 4; kk++) {
            ulonglong2 w0 = *reinterpret_cast<const ulonglong2*>(&sW[(k4+kk)*64+og]);
            ulonglong2 w1 = *reinterpret_cast<const ulonglong2*>(&sW[(k4+kk)*64+og+4]);
            ull wv[4] = {w0.x, w0.y, w1.x, w1.y};
            #pragma unroll
            for (int r = 0; r < 8; r++) {
                ull hd; PACKDUP(hd, ha[r][kk]);
                #pragma unroll
                for (int q = 0; q < 4; q++) FFMA2(acc[r][q], hd, wv[q]);
            }
        }
    }
}

__device__ __forceinline__ void gemm8_store_relu(
    float* __restrict__ w0, ull acc[8][4])   // w0 = &buf[8*ig][og]
{
    #pragma unroll
    for (int r = 0; r < 8; r++) {
        float* dst = w0 + r*AST;
        float x0,x1,x2,x3,x4,x5,x6,x7;
        UNPACK2(x0,x1,acc[r][0]); UNPACK2(x2,x3,acc[r][1]);
        UNPACK2(x4,x5,acc[r][2]); UNPACK2(x6,x7,acc[r][3]);
        *reinterpret_cast<float4*>(dst) =
            make_float4(fmaxf(x0,0.f),fmaxf(x1,0.f),fmaxf(x2,0.f),fmaxf(x3,0.f));
        *reinterpret_cast<float4*>(dst+4) =
            make_float4(fmaxf(x4,0.f),fmaxf(x5,0.f),fmaxf(x6,0.f),fmaxf(x7,0.f));
    }
}

__global__ __launch_bounds__(128, 3) void node_kernel(
    const float* __restrict__ mW1, const float* __restrict__ mb1,
    const float* __restrict__ mW2, const float* __restrict__ mb2,
    const float* __restrict__ mW3, const float* __restrict__ mb3,
    const float* __restrict__ vW1, const float* __restrict__ vb1,
    const float* __restrict__ vW2, const float* __restrict__ vb2,
    const float* __restrict__ vW3, const float* __restrict__ vb3,
    float* __restrict__ out, int t)
{
    extern __shared__ char smem_raw[];
    NodeSmem& S = *reinterpret_cast<NodeSmem*>(smem_raw);

    const int tid = threadIdx.x;
    const int p   = blockIdx.x;       // 0..511
    const int is_var = blockIdx.y;
    const int bs  = p >> 4;           // 0..31
    const int c0  = p & 15;           // samples c0 + 16*smp

    const float* W1 = is_var ? vW1 : mW1;
    const float* W2 = is_var ? vW2 : mW2;
    const float* W3 = is_var ? vW3 : mW3;
    const float* b1 = is_var ? vb1 : mb1;
    const float* b2 = is_var ? vb2 : mb2;
    const float* b3 = is_var ? vb3 : mb3;

    {
        const float4* w1v = reinterpret_cast<const float4*>(W1);
        float4* s1 = reinterpret_cast<float4*>(S.sW);
        #pragma unroll
        for (int i = tid; i < 1024; i += 128) s1[i] = w1v[i];
        S.sW3[tid] = W3[tid]; S.sW3[tid+128] = W3[tid+128];
    }
    if (tid < 64) { S.sb1[tid] = b1[tid]; S.sb2[tid] = b2[tid]; }
    if (tid < 4)  S.sb3[tid] = b3[tid];
    if (tid >= 4 && tid < 8) S.sb3[tid] = 0.f;

    // load 4 samples of agg: 1920 float4, 15 per thread
    {
        const float4* ab = reinterpret_cast<const float4*>(g_agg);
        #pragma unroll
        for (int v = tid; v < 1920; v += 128) {
            int smp = v / 480, vv = v - smp*480;
            int row = vv >> 4, cp = vv & 15;
            float4 val = ab[(size_t)(bs*64 + c0 + 16*smp)*480 + vv];
            *reinterpret_cast<float4*>(&S.buf[smp*30 + row][cp*4]) = val;
        }
    }
    __syncthreads();

    const int ig = tid >> 3, cg = tid & 7;
    const int og = cg*8;
    const float* r0 = &S.buf[ig*8][0];
    float*       w0 = &S.buf[ig*8][og];

    ull acc[8][4];
    // Layer 1 (sW = W1)
    if (tid < 120) gemm8_compute(r0, S.sW, S.sb1, og, acc);
    __syncthreads();
    if (tid < 120) gemm8_store_relu(w0, acc);
    {
        const float4* w2v = reinterpret_cast<const float4*>(W2);
        float4* s1 = reinterpret_cast<float4*>(S.sW);
        #pragma unroll
        for (int i = tid; i < 1024; i += 128) s1[i] = w2v[i];
    }
    __syncthreads();
    // Layer 2 (sW = W2)
    if (tid < 120) gemm8_compute(r0, S.sW, S.sb2, og, acc);
    __syncthreads();
    if (tid < 120) gemm8_store_relu(w0, acc);
    __syncthreads();

    // Layer 3: 64 -> 4. 120 threads, one instance each.
    if (tid < 120) {
        const int smp = tid / 30, n = tid - smp*30;
        const float* hr = &S.buf[tid][0];
        ulonglong2 b3q = *reinterpret_cast<const ulonglong2*>(&S.sb3[0]);
        ull a01 = b3q.x, a23 = b3q.y;
        #pragma unroll 4
        for (int k4 = 0; k4 < 64; k4 += 4) {
            float4 hv = *reinterpret_cast<const float4*>(hr + k4);
            float ha[4] = {hv.x, hv.y, hv.z, hv.w};
            #pragma unroll
            for (int kk = 0; kk < 4; kk++) {
                ulonglong2 w = *reinterpret_cast<const ulonglong2*>(&S.sW3[(k4+kk)*4]);
                ull hd; PACKDUP(hd, ha[kk]);
                FFMA2(a01, hd, w.x);
                FFMA2(a23, hd, w.y);
            }
        }
        float v0,v1,v2,v3;
        UNPACK2(v0,v1,a01); UNPACK2(v2,v3,a23);
        float v[4] = {v0,v1,v2,v3};
        if (is_var) {
            #pragma unroll
            for (int q = 0; q < 4; q++) {
                float x = v[q];
                float sp = (x > 20.f) ? x : log1pf(expf(x));
                v[q] = fminf(fmaxf(sp, 1e-8f), 100.f);
            }
        }
        const int c = c0 + 16*smp;
        const int s = bs*64 + c;
        if (!is_var && t == 0)
            *reinterpret_cast<float4*>(&g_mu[(size_t)s*120 + n*4]) =
                make_float4(v[0],v[1],v[2],v[3]);
        const int kt = 2*c + t;
        if (kt < TOUT) {
            size_t o = (((size_t)bs*TOUT + kt)*NN + n)*FF;
            *reinterpret_cast<float4*>(&out[o + (is_var ? (size_t)VAROFF : 0)]) =
                make_float4(v[0],v[1],v[2],v[3]);
        }
    }
}

// ---------------------------------------------------------------------------
extern "C" void kernel_launch(void* const* d_in, const int* in_sizes, int n_in,
                              void* d_out, int out_size) {
    const float* data    = (const float*)d_in[0];
    const float* graph   = (const float*)d_in[1];
    const float* msg_W1  = (const float*)d_in[2];
    const float* msg_b1  = (const float*)d_in[3];
    const float* msg_W2  = (const float*)d_in[4];
    const float* msg_b2  = (const float*)d_in[5];
    const float* mean_W1 = (const float*)d_in[6];
    const float* mean_b1 = (const float*)d_in[7];
    const float* mean_W2 = (const float*)d_in[8];
    const float* mean_b2 = (const float*)d_in[9];
    const float* mean_W3 = (const float*)d_in[10];
    const float* mean_b3 = (const float*)d_in[11];
    const float* var_W1  = (const float*)d_in[12];
    const float* var_b1  = (const float*)d_in[13];
    const float* var_W2  = (const float*)d_in[14];
    const float* var_b2  = (const float*)d_in[15];
    const float* var_W3  = (const float*)d_in[16];
    const float* var_b3  = (const float*)d_in[17];
    float* out = (float*)d_out;

    cudaFuncSetAttribute(edge_kernel, cudaFuncAttributeMaxDynamicSharedMemorySize,
                         (int)sizeof(EdgeSmem));
    cudaFuncSetAttribute(node_kernel, cudaFuncAttributeMaxDynamicSharedMemorySize,
                         (int)sizeof(NodeSmem));

    dim3 ngrid(NSAMP/4, 2);
    for (int t = 0; t < 2; t++) {
        edge_kernel<<<NSAMP/2, 128, sizeof(EdgeSmem)>>>(data, t, graph,
                                    msg_W1, msg_b1, msg_W2, msg_b2);
        node_kernel<<<ngrid, 128, sizeof(NodeSmem)>>>(
            mean_W1, mean_b1, mean_W2, mean_b2, mean_W3, mean_b3,
            var_W1,  var_b1,  var_W2,  var_b2,  var_W3,  var_b3,
            out, t);
    }
}

// round 9
// speedup vs baseline: 4.0002x; 1.0012x over previous
#include <cuda_runtime.h>
#include <math.h>

typedef unsigned long long ull;

#define NN 30
#define FF 4
#define HH 64
#define NSAMP 2048          // 32 * 64
#define TOUT 127
#define VAROFF (32*127*30*4)
#define AST 68              // activation row stride (floats), bank-staggered
#define GST 36              // dense-graph row stride (floats), bank-staggered

// Scratch (allocation-free rule: __device__ globals)
__device__ float g_agg[(size_t)NSAMP * NN * HH];   // 15.7 MB
__device__ float g_mu [(size_t)NSAMP * NN * FF];   // 0.98 MB

// ---- packed f32x2 helpers (sm_103a) ---------------------------------------
#define FFMA2(acc, a, b) \
    asm("fma.rn.f32x2 %0, %1, %2, %0;" : "+l"(acc) : "l"(a), "l"(b))
#define MUL2(d, a, b) \
    asm("mul.rn.f32x2 %0, %1, %2;" : "=l"(d) : "l"(a), "l"(b))
#define PACKDUP(d, x) \
    asm("mov.b64 %0, {%1, %1};" : "=l"(d) : "r"(__float_as_uint(x)))
#define UNPACK2(x, y, p) \
    asm("mov.b64 {%0, %1}, %2;" : "=f"(x), "=f"(y) : "l"(p))
// acc += gdup * relu(apair + bpair)
#define AGG_STEP(acc, apair, bpair, gdup) \
    asm("{\n\t.reg .b32 lo, hi;\n\t.reg .b64 t;\n\t" \
        "add.rn.f32x2 t, %1, %2;\n\t" \
        "mov.b64 {lo, hi}, t;\n\t" \
        "max.f32 lo, lo, 0f00000000;\n\t" \
        "max.f32 hi, hi, 0f00000000;\n\t" \
        "mov.b64 t, {lo, hi};\n\t" \
        "fma.rn.f32x2 %0, %3, t, %0;\n\t}" \
        : "+l"(acc) : "l"(apair), "l"(bpair), "l"(gdup))

// ---------------------------------------------------------------------------
// Edge kernel: 2 samples per CTA, 128 threads (all active).
// Stage A (proj+agg): thread = (smp, 4-row group, 8 cols) -> B loads serve 4 rows.
// Stage B (W2 GEMM):  thread = (8-row group, 4 cols)      -> w loads serve 8 rows.
// H overwrites sB in place between stages.
// ---------------------------------------------------------------------------
struct EdgeSmem {
    float sW2[64*64];           // 16 KB
    float sW1[8*64];            //  2 KB
    float sB[2][32][AST];       // 17.4 KB (rows 30,31 zero) ; becomes H
    float sgm[32][GST];         //  4.5 KB dense graph, zero diag + pad rows
    float sx[2][128];           //  1 KB (tail zeroed)
    float scnt[64];             // flat gr = smp*32 + row
    float sb1[64];
    float sb2[64];
};

__global__ __launch_bounds__(128, 5) void edge_kernel(
    const float* __restrict__ data, int mode,
    const float* __restrict__ graph,
    const float* __restrict__ W1, const float* __restrict__ b1,
    const float* __restrict__ W2, const float* __restrict__ b2)
{
    extern __shared__ char smem_raw[];
    EdgeSmem& S = *reinterpret_cast<EdgeSmem*>(smem_raw);

    const int tid = threadIdx.x;
    const int p   = blockIdx.x;
    const int bs  = p >> 5;
    const int c0  = p & 31;

    {
        const float4* w2v = reinterpret_cast<const float4*>(W2);
        float4* d2 = reinterpret_cast<float4*>(S.sW2);
        #pragma unroll
        for (int i = tid; i < 1024; i += 128) d2[i] = w2v[i];
        const float4* w1v = reinterpret_cast<const float4*>(W1);
        float4* d1 = reinterpret_cast<float4*>(S.sW1);
        d1[tid] = w1v[tid];
    }
    if (tid < 64) { S.sb1[tid] = b1[tid]; S.sb2[tid] = b2[tid]; }
    for (int e = tid; e < 900; e += 128) {
        int i = e / 30, j = e - i*30;
        S.sgm[i][j] = (i == j) ? 0.f
                      : graph[(size_t)bs*870 + i*29 + j - (j > i)];
    }
    if (tid < 30) { S.sgm[tid][30] = 0.f; S.sgm[tid][31] = 0.f; }
    if (tid < 64) S.sgm[30 + (tid >> 5)][tid & 31] = 0.f;      // pad g rows
    if (tid < 68) {
        S.sB[0][30][tid] = 0.f; S.sB[0][31][tid] = 0.f;
        S.sB[1][30][tid] = 0.f; S.sB[1][31][tid] = 0.f;
    }
    if (tid < 16) S.sx[tid >> 3][120 + (tid & 7)] = 0.f;       // pad x tail
    if (tid < 4)  S.scnt[((tid >> 1) << 5) + 30 + (tid & 1)] = 0.f;
    for (int v = tid; v < 240; v += 128) {
        int h = v >= 120, idx = v - 120*h;
        int cc = c0 + 32*h, ss = bs*64 + cc;
        S.sx[h][idx] = (mode == 0)
            ? data[((size_t)bs*128 + 2*cc)*120 + idx]
            : g_mu[(size_t)ss*120 + idx];
    }
    __syncthreads();

    // ---- Stage A mapping: smp, rows r0..r0+3 (same sample), cols og..og+7
    const int smp = tid >> 6;
    const int rg  = (tid >> 3) & 7;
    const int cg  = tid & 7;
    const int r0  = rg * 4;
    const int og  = cg * 8;

    ull aA[4][4];               // A-projection, registers
    // ---- projections: A (registers) + B (smem) ----
    {
        float xr[4][4];
        #pragma unroll
        for (int rr = 0; rr < 4; rr++) {
            float4 xv = *reinterpret_cast<const float4*>(&S.sx[smp][(r0+rr)*4]);
            xr[rr][0]=xv.x; xr[rr][1]=xv.y; xr[rr][2]=xv.z; xr[rr][3]=xv.w;
        }
        ull aB[4][4];
        {
            ulonglong2 bq0 = *reinterpret_cast<const ulonglong2*>(&S.sb1[og]);
            ulonglong2 bq1 = *reinterpret_cast<const ulonglong2*>(&S.sb1[og+4]);
            ull bp[4] = {bq0.x, bq0.y, bq1.x, bq1.y};
            #pragma unroll
            for (int rr = 0; rr < 4; rr++)
                #pragma unroll
                for (int q = 0; q < 4; q++) { aA[rr][q] = bp[q]; aB[rr][q] = 0ULL; }
        }
        #pragma unroll
        for (int f = 0; f < 4; f++) {
            ulonglong2 wa0 = *reinterpret_cast<const ulonglong2*>(&S.sW1[f*64+og]);
            ulonglong2 wa1 = *reinterpret_cast<const ulonglong2*>(&S.sW1[f*64+og+4]);
            ulonglong2 wb0 = *reinterpret_cast<const ulonglong2*>(&S.sW1[(f+4)*64+og]);
            ulonglong2 wb1 = *reinterpret_cast<const ulonglong2*>(&S.sW1[(f+4)*64+og+4]);
            ull wa[4] = {wa0.x, wa0.y, wa1.x, wa1.y};
            ull wb[4] = {wb0.x, wb0.y, wb1.x, wb1.y};
            #pragma unroll
            for (int rr = 0; rr < 4; rr++) {
                ull xd; PACKDUP(xd, xr[rr][f]);
                #pragma unroll
                for (int q = 0; q < 4; q++) {
                    FFMA2(aA[rr][q], xd, wa[q]);
                    FFMA2(aB[rr][q], xd, wb[q]);
                }
            }
        }
        #pragma unroll
        for (int rr = 0; rr < 4; rr++) {
            if (r0 + rr < 30) {
                float* dst = &S.sB[smp][r0+rr][og];
                ulonglong2 s0; s0.x = aB[rr][0]; s0.y = aB[rr][1];
                ulonglong2 s1; s1.x = aB[rr][2]; s1.y = aB[rr][3];
                *reinterpret_cast<ulonglong2*>(dst)   = s0;
                *reinterpret_cast<ulonglong2*>(dst+4) = s1;
            }
        }
    }
    __syncthreads();

    // ---- masked-ReLU aggregation: B[j] load serves 4 rows ----
    ull acc[4][4];
    float cnt[4] = {0.f, 0.f, 0.f, 0.f};
    {
        #pragma unroll
        for (int rr = 0; rr < 4; rr++)
            #pragma unroll
            for (int q = 0; q < 4; q++) acc[rr][q] = 0ULL;

        const float* bb = &S.sB[smp][0][og];
        #pragma unroll 2
        for (int j4 = 0; j4 < 32; j4 += 4) {
            float ga[4][4];
            #pragma unroll
            for (int rr = 0; rr < 4; rr++) {
                float4 gv = *reinterpret_cast<const float4*>(&S.sgm[r0+rr][j4]);
                ga[rr][0]=gv.x; ga[rr][1]=gv.y; ga[rr][2]=gv.z; ga[rr][3]=gv.w;
                cnt[rr] += gv.x + gv.y + gv.z + gv.w;
            }
            #pragma unroll
            for (int jj = 0; jj < 4; jj++) {
                const float* bj = bb + (j4 + jj)*AST;
                ulonglong2 b0 = *reinterpret_cast<const ulonglong2*>(bj);
                ulonglong2 b1v = *reinterpret_cast<const ulonglong2*>(bj+4);
                ull bv[4] = {b0.x, b0.y, b1v.x, b1v.y};
                #pragma unroll
                for (int rr = 0; rr < 4; rr++) {
                    ull gd; PACKDUP(gd, ga[rr][jj]);
                    #pragma unroll
                    for (int q = 0; q < 4; q++)
                        AGG_STEP(acc[rr][q], aA[rr][q], bv[q], gd);
                }
            }
        }
    }
    __syncthreads();            // all sB reads complete
    {
        #pragma unroll
        for (int rr = 0; rr < 4; rr++) {
            if (r0 + rr < 30) {
                float* dst = &S.sB[smp][r0+rr][og];   // H overwrites sB
                ulonglong2 s0; s0.x = acc[rr][0]; s0.y = acc[rr][1];
                ulonglong2 s1; s1.x = acc[rr][2]; s1.y = acc[rr][3];
                *reinterpret_cast<ulonglong2*>(dst)   = s0;
                *reinterpret_cast<ulonglong2*>(dst+4) = s1;
            }
        }
        if (cg == 0) {
            #pragma unroll
            for (int rr = 0; rr < 4; rr++)
                if (r0 + rr < 30) S.scnt[smp*32 + r0 + rr] = cnt[rr];
        }
    }
    __syncthreads();

    // ---- Stage B: agg = H @ W2 + cnt*b2. 8 rows x 4 cols per thread. ----
    {
        const int rg2 = tid >> 4;          // 0..7 : rows rg2*8 .. rg2*8+7
        const int oc  = (tid & 15) * 4;    // 0..60
        const float* hb = &S.sB[0][0][0] + rg2*8*AST;
        ull acc2[8][2];
        {
            ulonglong2 b2p = *reinterpret_cast<const ulonglong2*>(&S.sb2[oc]);
            #pragma unroll
            for (int r = 0; r < 8; r++) {
                ull cd; PACKDUP(cd, S.scnt[rg2*8 + r]);
                MUL2(acc2[r][0], cd, b2p.x);
                MUL2(acc2[r][1], cd, b2p.y);
            }
        }
        #pragma unroll 2
        for (int k4 = 0; k4 < 64; k4 += 4) {
            ulonglong2 w[4];
            #pragma unroll
            for (int kk = 0; kk < 4; kk++)
                w[kk] = *reinterpret_cast<const ulonglong2*>(&S.sW2[(k4+kk)*64 + oc]);
            float4 hv[8];
            #pragma unroll
            for (int r = 0; r < 8; r++)
                hv[r] = *reinterpret_cast<const float4*>(hb + r*AST + k4);
            float ha[8][4];
            #pragma unroll
            for (int r = 0; r < 8; r++) {
                ha[r][0]=hv[r].x; ha[r][1]=hv[r].y; ha[r][2]=hv[r].z; ha[r][3]=hv[r].w;
            }
            #pragma unroll
            for (int kk = 0; kk < 4; kk++) {
                #pragma unroll
                for (int r = 0; r < 8; r++) {
                    ull hd; PACKDUP(hd, ha[r][kk]);
                    FFMA2(acc2[r][0], hd, w[kk].x);
                    FFMA2(acc2[r][1], hd, w[kk].y);
                }
            }
        }
        const int sb0 = bs*64 + c0;
        #pragma unroll
        for (int r = 0; r < 8; r++) {
            int gr = rg2*8 + r;
            int sm2 = gr >> 5, row = gr & 31;
            if (row < 30) {
                size_t base = ((size_t)(sb0 + 32*sm2)*NN + row)*HH + oc;
                ulonglong2 st; st.x = acc2[r][0]; st.y = acc2[r][1];
                *reinterpret_cast<ulonglong2*>(&g_agg[base]) = st;
            }
        }
    }
}

// ---------------------------------------------------------------------------
// Node MLP kernel: 64 ->relu-> 64 ->relu-> 64 -> 4. 4 samples/CTA, 128 thr.
// 8-row x 8-col register tiles; w held in regs across k4, h streamed in
// 4-row batches (reg cap 124 -> 4 CTAs/SM). Single weight buffer.
// ---------------------------------------------------------------------------
struct NodeSmem {
    float sW[64*64];            // 16 KB, W1 then W2
    float sW3[64*4];
    float buf[120][AST];        // 31.9 KB : inst = smp*30 + row
    float sb1[64];
    float sb2[64];
    float sb3[8];
};

__device__ __forceinline__ void gemm8_compute(
    const float* __restrict__ r0,      // &buf[8*ig][0]
    const float* __restrict__ sW, const float* __restrict__ sb,
    int og, ull acc[8][4])
{
    {
        ulonglong2 bq0 = *reinterpret_cast<const ulonglong2*>(&sb[og]);
        ulonglong2 bq1 = *reinterpret_cast<const ulonglong2*>(&sb[og+4]);
        ull bp[4] = {bq0.x, bq0.y, bq1.x, bq1.y};
        #pragma unroll
        for (int r = 0; r < 8; r++)
            #pragma unroll
            for (int q = 0; q < 4; q++) acc[r][q] = bp[q];
    }
    #pragma unroll 2
    for (int k4 = 0; k4 < 64; k4 += 4) {
        // stage all w for this k4 (held across both row batches)
        ull wv[4][4];
        #pragma unroll
        for (int kk = 0; kk < 4; kk++) {
            ulonglong2 w0 = *reinterpret_cast<const ulonglong2*>(&sW[(k4+kk)*64+og]);
            ulonglong2 w1 = *reinterpret_cast<const ulonglong2*>(&sW[(k4+kk)*64+og+4]);
            wv[kk][0]=w0.x; wv[kk][1]=w0.y; wv[kk][2]=w1.x; wv[kk][3]=w1.y;
        }
        #pragma unroll
        for (int rb = 0; rb < 2; rb++) {
            float ha[4][4];
            #pragma unroll
            for (int r = 0; r < 4; r++) {
                float4 hv = *reinterpret_cast<const float4*>(r0 + (rb*4+r)*AST + k4);
                ha[r][0]=hv.x; ha[r][1]=hv.y; ha[r][2]=hv.z; ha[r][3]=hv.w;
            }
            #pragma unroll
            for (int kk = 0; kk < 4; kk++) {
                #pragma unroll
                for (int r = 0; r < 4; r++) {
                    ull hd; PACKDUP(hd, ha[r][kk]);
                    #pragma unroll
                    for (int q = 0; q < 4; q++) FFMA2(acc[rb*4+r][q], hd, wv[kk][q]);
                }
            }
        }
    }
}

__device__ __forceinline__ void gemm8_store_relu(
    float* __restrict__ w0, ull acc[8][4])   // w0 = &buf[8*ig][og]
{
    #pragma unroll
    for (int r = 0; r < 8; r++) {
        float* dst = w0 + r*AST;
        float x0,x1,x2,x3,x4,x5,x6,x7;
        UNPACK2(x0,x1,acc[r][0]); UNPACK2(x2,x3,acc[r][1]);
        UNPACK2(x4,x5,acc[r][2]); UNPACK2(x6,x7,acc[r][3]);
        *reinterpret_cast<float4*>(dst) =
            make_float4(fmaxf(x0,0.f),fmaxf(x1,0.f),fmaxf(x2,0.f),fmaxf(x3,0.f));
        *reinterpret_cast<float4*>(dst+4) =
            make_float4(fmaxf(x4,0.f),fmaxf(x5,0.f),fmaxf(x6,0.f),fmaxf(x7,0.f));
    }
}

__global__ __launch_bounds__(128, 4) void node_kernel(
    const float* __restrict__ mW1, const float* __restrict__ mb1,
    const float* __restrict__ mW2, const float* __restrict__ mb2,
    const float* __restrict__ mW3, const float* __restrict__ mb3,
    const float* __restrict__ vW1, const float* __restrict__ vb1,
    const float* __restrict__ vW2, const float* __restrict__ vb2,
    const float* __restrict__ vW3, const float* __restrict__ vb3,
    float* __restrict__ out, int t)
{
    extern __shared__ char smem_raw[];
    NodeSmem& S = *reinterpret_cast<NodeSmem*>(smem_raw);

    const int tid = threadIdx.x;
    const int p   = blockIdx.x;       // 0..511
    const int is_var = blockIdx.y;
    const int bs  = p >> 4;           // 0..31
    const int c0  = p & 15;           // samples c0 + 16*smp

    const float* W1 = is_var ? vW1 : mW1;
    const float* W2 = is_var ? vW2 : mW2;
    const float* W3 = is_var ? vW3 : mW3;
    const float* b1 = is_var ? vb1 : mb1;
    const float* b2 = is_var ? vb2 : mb2;
    const float* b3 = is_var ? vb3 : mb3;

    {
        const float4* w1v = reinterpret_cast<const float4*>(W1);
        float4* s1 = reinterpret_cast<float4*>(S.sW);
        #pragma unroll
        for (int i = tid; i < 1024; i += 128) s1[i] = w1v[i];
        S.sW3[tid] = W3[tid]; S.sW3[tid+128] = W3[tid+128];
    }
    if (tid < 64) { S.sb1[tid] = b1[tid]; S.sb2[tid] = b2[tid]; }
    if (tid < 4)  S.sb3[tid] = b3[tid];
    if (tid >= 4 && tid < 8) S.sb3[tid] = 0.f;

    // load 4 samples of agg: 1920 float4, 15 per thread
    {
        const float4* ab = reinterpret_cast<const float4*>(g_agg);
        #pragma unroll
        for (int v = tid; v < 1920; v += 128) {
            int smp = v / 480, vv = v - smp*480;
            int row = vv >> 4, cp = vv & 15;
            float4 val = ab[(size_t)(bs*64 + c0 + 16*smp)*480 + vv];
            *reinterpret_cast<float4*>(&S.buf[smp*30 + row][cp*4]) = val;
        }
    }
    __syncthreads();

    const int ig = tid >> 3, cg = tid & 7;
    const int og = cg*8;
    const float* r0 = &S.buf[ig*8][0];
    float*       w0 = &S.buf[ig*8][og];

    ull acc[8][4];
    // Layer 1 (sW = W1)
    if (tid < 120) gemm8_compute(r0, S.sW, S.sb1, og, acc);
    __syncthreads();
    if (tid < 120) gemm8_store_relu(w0, acc);
    {
        const float4* w2v = reinterpret_cast<const float4*>(W2);
        float4* s1 = reinterpret_cast<float4*>(S.sW);
        #pragma unroll
        for (int i = tid; i < 1024; i += 128) s1[i] = w2v[i];
    }
    __syncthreads();
    // Layer 2 (sW = W2)
    if (tid < 120) gemm8_compute(r0, S.sW, S.sb2, og, acc);
    __syncthreads();
    if (tid < 120) gemm8_store_relu(w0, acc);
    __syncthreads();

    // Layer 3: 64 -> 4. 120 threads, one instance each.
    if (tid < 120) {
        const int smp = tid / 30, n = tid - smp*30;
        const float* hr = &S.buf[tid][0];
        ulonglong2 b3q = *reinterpret_cast<const ulonglong2*>(&S.sb3[0]);
        ull a01 = b3q.x, a23 = b3q.y;
        #pragma unroll 4
        for (int k4 = 0; k4 < 64; k4 += 4) {
            float4 hv = *reinterpret_cast<const float4*>(hr + k4);
            float ha[4] = {hv.x, hv.y, hv.z, hv.w};
            #pragma unroll
            for (int kk = 0; kk < 4; kk++) {
                ulonglong2 w = *reinterpret_cast<const ulonglong2*>(&S.sW3[(k4+kk)*4]);
                ull hd; PACKDUP(hd, ha[kk]);
                FFMA2(a01, hd, w.x);
                FFMA2(a23, hd, w.y);
            }
        }
        float v0,v1,v2,v3;
        UNPACK2(v0,v1,a01); UNPACK2(v2,v3,a23);
        float v[4] = {v0,v1,v2,v3};
        if (is_var) {
            #pragma unroll
            for (int q = 0; q < 4; q++) {
                float x = v[q];
                float sp = (x > 20.f) ? x : log1pf(expf(x));
                v[q] = fminf(fmaxf(sp, 1e-8f), 100.f);
            }
        }
        const int c = c0 + 16*smp;
        const int s = bs*64 + c;
        if (!is_var && t == 0)
            *reinterpret_cast<float4*>(&g_mu[(size_t)s*120 + n*4]) =
                make_float4(v[0],v[1],v[2],v[3]);
        const int kt = 2*c + t;
        if (kt < TOUT) {
            size_t o = (((size_t)bs*TOUT + kt)*NN + n)*FF;
            *reinterpret_cast<float4*>(&out[o + (is_var ? (size_t)VAROFF : 0)]) =
                make_float4(v[0],v[1],v[2],v[3]);
        }
    }
}

// ---------------------------------------------------------------------------
extern "C" void kernel_launch(void* const* d_in, const int* in_sizes, int n_in,
                              void* d_out, int out_size) {
    const float* data    = (const float*)d_in[0];
    const float* graph   = (const float*)d_in[1];
    const float* msg_W1  = (const float*)d_in[2];
    const float* msg_b1  = (const float*)d_in[3];
    const float* msg_W2  = (const float*)d_in[4];
    const float* msg_b2  = (const float*)d_in[5];
    const float* mean_W1 = (const float*)d_in[6];
    const float* mean_b1 = (const float*)d_in[7];
    const float* mean_W2 = (const float*)d_in[8];
    const float* mean_b2 = (const float*)d_in[9];
    const float* mean_W3 = (const float*)d_in[10];
    const float* mean_b3 = (const float*)d_in[11];
    const float* var_W1  = (const float*)d_in[12];
    const float* var_b1  = (const float*)d_in[13];
    const float* var_W2  = (const float*)d_in[14];
    const float* var_b2  = (const float*)d_in[15];
    const float* var_W3  = (const float*)d_in[16];
    const float* var_b3  = (const float*)d_in[17];
    float* out = (float*)d_out;

    cudaFuncSetAttribute(edge_kernel, cudaFuncAttributeMaxDynamicSharedMemorySize,
                         (int)sizeof(EdgeSmem));
    cudaFuncSetAttribute(node_kernel, cudaFuncAttributeMaxDynamicSharedMemorySize,
                         (int)sizeof(NodeSmem));

    dim3 ngrid(NSAMP/4, 2);
    for (int t = 0; t < 2; t++) {
        edge_kernel<<<NSAMP/2, 128, sizeof(EdgeSmem)>>>(data, t, graph,
                                    msg_W1, msg_b1, msg_W2, msg_b2);
        node_kernel<<<ngrid, 128, sizeof(NodeSmem)>>>(
            mean_W1, mean_b1, mean_W2, mean_b2, mean_W3, mean_b3,
            var_W1,  var_b1,  var_W2,  var_b2,  var_W3,  var_b3,
            out, t);
    }
}

// round 10
// speedup vs baseline: 4.2761x; 1.0690x over previous
#include <cuda_runtime.h>
#include <math.h>

typedef unsigned long long ull;

#define NN 30
#define FF 4
#define HH 64
#define NSAMP 2048          // 32 * 64
#define TOUT 127
#define VAROFF (32*127*30*4)
#define AST 68              // activation row stride (floats), bank-staggered
#define GST 36              // dense-graph row stride (floats), bank-staggered

// Scratch (allocation-free rule: __device__ globals)
__device__ float g_agg[(size_t)NSAMP * NN * HH];   // 15.7 MB
__device__ float g_mu [(size_t)NSAMP * NN * FF];   // 0.98 MB

// ---- packed f32x2 helpers (sm_103a) ---------------------------------------
#define FFMA2(acc, a, b) \
    asm("fma.rn.f32x2 %0, %1, %2, %0;" : "+l"(acc) : "l"(a), "l"(b))
#define MUL2(d, a, b) \
    asm("mul.rn.f32x2 %0, %1, %2;" : "=l"(d) : "l"(a), "l"(b))
#define PACKDUP(d, x) \
    asm("mov.b64 %0, {%1, %1};" : "=l"(d) : "r"(__float_as_uint(x)))
#define UNPACK2(x, y, p) \
    asm("mov.b64 {%0, %1}, %2;" : "=f"(x), "=f"(y) : "l"(p))
// acc += gdup * relu(apair + bpair)
#define AGG_STEP(acc, apair, bpair, gdup) \
    asm("{\n\t.reg .b32 lo, hi;\n\t.reg .b64 t;\n\t" \
        "add.rn.f32x2 t, %1, %2;\n\t" \
        "mov.b64 {lo, hi}, t;\n\t" \
        "max.f32 lo, lo, 0f00000000;\n\t" \
        "max.f32 hi, hi, 0f00000000;\n\t" \
        "mov.b64 t, {lo, hi};\n\t" \
        "fma.rn.f32x2 %0, %3, t, %0;\n\t}" \
        : "+l"(acc) : "l"(apair), "l"(bpair), "l"(gdup))

// ---------------------------------------------------------------------------
// Edge kernel: 2 samples per CTA, 128 threads (all active). (R9 layout, kept)
// Stage A (proj+agg): thread = (smp, 4-row group, 8 cols).
// Stage B (W2 GEMM):  thread = (8-row group, 4 cols).
// H overwrites sB in place between stages.
// ---------------------------------------------------------------------------
struct EdgeSmem {
    float sW2[64*64];           // 16 KB
    float sW1[8*64];            //  2 KB
    float sB[2][32][AST];       // 17.4 KB (rows 30,31 zero) ; becomes H
    float sgm[32][GST];         //  4.5 KB dense graph, zero diag + pad rows
    float sx[2][128];           //  1 KB (tail zeroed)
    float scnt[64];             // flat gr = smp*32 + row
    float sb1[64];
    float sb2[64];
};

__global__ __launch_bounds__(128, 5) void edge_kernel(
    const float* __restrict__ data, int mode,
    const float* __restrict__ graph,
    const float* __restrict__ W1, const float* __restrict__ b1,
    const float* __restrict__ W2, const float* __restrict__ b2)
{
    extern __shared__ char smem_raw[];
    EdgeSmem& S = *reinterpret_cast<EdgeSmem*>(smem_raw);

    const int tid = threadIdx.x;
    const int p   = blockIdx.x;
    const int bs  = p >> 5;
    const int c0  = p & 31;

    {
        const float4* w2v = reinterpret_cast<const float4*>(W2);
        float4* d2 = reinterpret_cast<float4*>(S.sW2);
        #pragma unroll
        for (int i = tid; i < 1024; i += 128) d2[i] = w2v[i];
        const float4* w1v = reinterpret_cast<const float4*>(W1);
        float4* d1 = reinterpret_cast<float4*>(S.sW1);
        d1[tid] = w1v[tid];
    }
    if (tid < 64) { S.sb1[tid] = b1[tid]; S.sb2[tid] = b2[tid]; }
    for (int e = tid; e < 900; e += 128) {
        int i = e / 30, j = e - i*30;
        S.sgm[i][j] = (i == j) ? 0.f
                      : graph[(size_t)bs*870 + i*29 + j - (j > i)];
    }
    if (tid < 30) { S.sgm[tid][30] = 0.f; S.sgm[tid][31] = 0.f; }
    if (tid < 64) S.sgm[30 + (tid >> 5)][tid & 31] = 0.f;      // pad g rows
    if (tid < 68) {
        S.sB[0][30][tid] = 0.f; S.sB[0][31][tid] = 0.f;
        S.sB[1][30][tid] = 0.f; S.sB[1][31][tid] = 0.f;
    }
    if (tid < 16) S.sx[tid >> 3][120 + (tid & 7)] = 0.f;       // pad x tail
    if (tid < 4)  S.scnt[((tid >> 1) << 5) + 30 + (tid & 1)] = 0.f;
    for (int v = tid; v < 240; v += 128) {
        int h = v >= 120, idx = v - 120*h;
        int cc = c0 + 32*h, ss = bs*64 + cc;
        S.sx[h][idx] = (mode == 0)
            ? data[((size_t)bs*128 + 2*cc)*120 + idx]
            : g_mu[(size_t)ss*120 + idx];
    }
    __syncthreads();

    // ---- Stage A mapping: smp, rows r0..r0+3 (same sample), cols og..og+7
    const int smp = tid >> 6;
    const int rg  = (tid >> 3) & 7;
    const int cg  = tid & 7;
    const int r0  = rg * 4;
    const int og  = cg * 8;

    ull aA[4][4];               // A-projection, registers
    // ---- projections: A (registers) + B (smem) ----
    {
        float xr[4][4];
        #pragma unroll
        for (int rr = 0; rr < 4; rr++) {
            float4 xv = *reinterpret_cast<const float4*>(&S.sx[smp][(r0+rr)*4]);
            xr[rr][0]=xv.x; xr[rr][1]=xv.y; xr[rr][2]=xv.z; xr[rr][3]=xv.w;
        }
        ull aB[4][4];
        {
            ulonglong2 bq0 = *reinterpret_cast<const ulonglong2*>(&S.sb1[og]);
            ulonglong2 bq1 = *reinterpret_cast<const ulonglong2*>(&S.sb1[og+4]);
            ull bp[4] = {bq0.x, bq0.y, bq1.x, bq1.y};
            #pragma unroll
            for (int rr = 0; rr < 4; rr++)
                #pragma unroll
                for (int q = 0; q < 4; q++) { aA[rr][q] = bp[q]; aB[rr][q] = 0ULL; }
        }
        #pragma unroll
        for (int f = 0; f < 4; f++) {
            ulonglong2 wa0 = *reinterpret_cast<const ulonglong2*>(&S.sW1[f*64+og]);
            ulonglong2 wa1 = *reinterpret_cast<const ulonglong2*>(&S.sW1[f*64+og+4]);
            ulonglong2 wb0 = *reinterpret_cast<const ulonglong2*>(&S.sW1[(f+4)*64+og]);
            ulonglong2 wb1 = *reinterpret_cast<const ulonglong2*>(&S.sW1[(f+4)*64+og+4]);
            ull wa[4] = {wa0.x, wa0.y, wa1.x, wa1.y};
            ull wb[4] = {wb0.x, wb0.y, wb1.x, wb1.y};
            #pragma unroll
            for (int rr = 0; rr < 4; rr++) {
                ull xd; PACKDUP(xd, xr[rr][f]);
                #pragma unroll
                for (int q = 0; q < 4; q++) {
                    FFMA2(aA[rr][q], xd, wa[q]);
                    FFMA2(aB[rr][q], xd, wb[q]);
                }
            }
        }
        #pragma unroll
        for (int rr = 0; rr < 4; rr++) {
            if (r0 + rr < 30) {
                float* dst = &S.sB[smp][r0+rr][og];
                ulonglong2 s0; s0.x = aB[rr][0]; s0.y = aB[rr][1];
                ulonglong2 s1; s1.x = aB[rr][2]; s1.y = aB[rr][3];
                *reinterpret_cast<ulonglong2*>(dst)   = s0;
                *reinterpret_cast<ulonglong2*>(dst+4) = s1;
            }
        }
    }
    __syncthreads();

    // ---- masked-ReLU aggregation: B[j] load serves 4 rows ----
    ull acc[4][4];
    float cnt[4] = {0.f, 0.f, 0.f, 0.f};
    {
        #pragma unroll
        for (int rr = 0; rr < 4; rr++)
            #pragma unroll
            for (int q = 0; q < 4; q++) acc[rr][q] = 0ULL;

        const float* bb = &S.sB[smp][0][og];
        #pragma unroll 2
        for (int j4 = 0; j4 < 32; j4 += 4) {
            float ga[4][4];
            #pragma unroll
            for (int rr = 0; rr < 4; rr++) {
                float4 gv = *reinterpret_cast<const float4*>(&S.sgm[r0+rr][j4]);
                ga[rr][0]=gv.x; ga[rr][1]=gv.y; ga[rr][2]=gv.z; ga[rr][3]=gv.w;
                cnt[rr] += gv.x + gv.y + gv.z + gv.w;
            }
            #pragma unroll
            for (int jj = 0; jj < 4; jj++) {
                const float* bj = bb + (j4 + jj)*AST;
                ulonglong2 b0 = *reinterpret_cast<const ulonglong2*>(bj);
                ulonglong2 b1v = *reinterpret_cast<const ulonglong2*>(bj+4);
                ull bv[4] = {b0.x, b0.y, b1v.x, b1v.y};
                #pragma unroll
                for (int rr = 0; rr < 4; rr++) {
                    ull gd; PACKDUP(gd, ga[rr][jj]);
                    #pragma unroll
                    for (int q = 0; q < 4; q++)
                        AGG_STEP(acc[rr][q], aA[rr][q], bv[q], gd);
                }
            }
        }
    }
    __syncthreads();            // all sB reads complete
    {
        #pragma unroll
        for (int rr = 0; rr < 4; rr++) {
            if (r0 + rr < 30) {
                float* dst = &S.sB[smp][r0+rr][og];   // H overwrites sB
                ulonglong2 s0; s0.x = acc[rr][0]; s0.y = acc[rr][1];
                ulonglong2 s1; s1.x = acc[rr][2]; s1.y = acc[rr][3];
                *reinterpret_cast<ulonglong2*>(dst)   = s0;
                *reinterpret_cast<ulonglong2*>(dst+4) = s1;
            }
        }
        if (cg == 0) {
            #pragma unroll
            for (int rr = 0; rr < 4; rr++)
                if (r0 + rr < 30) S.scnt[smp*32 + r0 + rr] = cnt[rr];
        }
    }
    __syncthreads();

    // ---- Stage B: agg = H @ W2 + cnt*b2. 8 rows x 4 cols per thread. ----
    {
        const int rg2 = tid >> 4;          // 0..7 : rows rg2*8 .. rg2*8+7
        const int oc  = (tid & 15) * 4;    // 0..60
        const float* hb = &S.sB[0][0][0] + rg2*8*AST;
        ull acc2[8][2];
        {
            ulonglong2 b2p = *reinterpret_cast<const ulonglong2*>(&S.sb2[oc]);
            #pragma unroll
            for (int r = 0; r < 8; r++) {
                ull cd; PACKDUP(cd, S.scnt[rg2*8 + r]);
                MUL2(acc2[r][0], cd, b2p.x);
                MUL2(acc2[r][1], cd, b2p.y);
            }
        }
        #pragma unroll 2
        for (int k4 = 0; k4 < 64; k4 += 4) {
            ulonglong2 w[4];
            #pragma unroll
            for (int kk = 0; kk < 4; kk++)
                w[kk] = *reinterpret_cast<const ulonglong2*>(&S.sW2[(k4+kk)*64 + oc]);
            float4 hv[8];
            #pragma unroll
            for (int r = 0; r < 8; r++)
                hv[r] = *reinterpret_cast<const float4*>(hb + r*AST + k4);
            float ha[8][4];
            #pragma unroll
            for (int r = 0; r < 8; r++) {
                ha[r][0]=hv[r].x; ha[r][1]=hv[r].y; ha[r][2]=hv[r].z; ha[r][3]=hv[r].w;
            }
            #pragma unroll
            for (int kk = 0; kk < 4; kk++) {
                #pragma unroll
                for (int r = 0; r < 8; r++) {
                    ull hd; PACKDUP(hd, ha[r][kk]);
                    FFMA2(acc2[r][0], hd, w[kk].x);
                    FFMA2(acc2[r][1], hd, w[kk].y);
                }
            }
        }
        const int sb0 = bs*64 + c0;
        #pragma unroll
        for (int r = 0; r < 8; r++) {
            int gr = rg2*8 + r;
            int sm2 = gr >> 5, row = gr & 31;
            if (row < 30) {
                size_t base = ((size_t)(sb0 + 32*sm2)*NN + row)*HH + oc;
                ulonglong2 st; st.x = acc2[r][0]; st.y = acc2[r][1];
                *reinterpret_cast<ulonglong2*>(&g_agg[base]) = st;
            }
        }
    }
}

// ---------------------------------------------------------------------------
// Node MLP kernel: 64 ->relu-> 64 ->relu-> 64 -> 4. 4 samples/CTA, 128 thr.
// 8-row x 8-col register tiles (R8 inner loop — measured best).
// Single weight buffer. blockIdx.y selects mean(0)/var(1).
// ---------------------------------------------------------------------------
struct NodeSmem {
    float sW[64*64];            // 16 KB, W1 then W2
    float sW3[64*4];
    float buf[120][AST];        // 31.9 KB : inst = smp*30 + row
    float sb1[64];
    float sb2[64];
    float sb3[8];
};

__device__ __forceinline__ void gemm8_compute(
    const float* __restrict__ r0,      // &buf[8*ig][0]
    const float* __restrict__ sW, const float* __restrict__ sb,
    int og, ull acc[8][4])
{
    {
        ulonglong2 bq0 = *reinterpret_cast<const ulonglong2*>(&sb[og]);
        ulonglong2 bq1 = *reinterpret_cast<const ulonglong2*>(&sb[og+4]);
        ull bp[4] = {bq0.x, bq0.y, bq1.x, bq1.y};
        #pragma unroll
        for (int r = 0; r < 8; r++)
            #pragma unroll
            for (int q = 0; q < 4; q++) acc[r][q] = bp[q];
    }
    #pragma unroll 2
    for (int k4 = 0; k4 < 64; k4 += 4) {
        float4 hv[8];
        #pragma unroll
        for (int r = 0; r < 8; r++)
            hv[r] = *reinterpret_cast<const float4*>(r0 + r*AST + k4);
        float ha[8][4];
        #pragma unroll
        for (int r = 0; r < 8; r++) {
            ha[r][0]=hv[r].x; ha[r][1]=hv[r].y; ha[r][2]=hv[r].z; ha[r][3]=hv[r].w;
        }
        #pragma unroll
        for (int kk = 0; kk < 4; kk++) {
            ulonglong2 w0 = *reinterpret_cast<const ulonglong2*>(&sW[(k4+kk)*64+og]);
            ulonglong2 w1 = *reinterpret_cast<const ulonglong2*>(&sW[(k4+kk)*64+og+4]);
            ull wv[4] = {w0.x, w0.y, w1.x, w1.y};
            #pragma unroll
            for (int r = 0; r < 8; r++) {
                ull hd; PACKDUP(hd, ha[r][kk]);
                #pragma unroll
                for (int q = 0; q < 4; q++) FFMA2(acc[r][q], hd, wv[q]);
            }
        }
    }
}

__device__ __forceinline__ void gemm8_store_relu(
    float* __restrict__ w0, ull acc[8][4])   // w0 = &buf[8*ig][og]
{
    #pragma unroll
    for (int r = 0; r < 8; r++) {
        float* dst = w0 + r*AST;
        float x0,x1,x2,x3,x4,x5,x6,x7;
        UNPACK2(x0,x1,acc[r][0]); UNPACK2(x2,x3,acc[r][1]);
        UNPACK2(x4,x5,acc[r][2]); UNPACK2(x6,x7,acc[r][3]);
        *reinterpret_cast<float4*>(dst) =
            make_float4(fmaxf(x0,0.f),fmaxf(x1,0.f),fmaxf(x2,0.f),fmaxf(x3,0.f));
        *reinterpret_cast<float4*>(dst+4) =
            make_float4(fmaxf(x4,0.f),fmaxf(x5,0.f),fmaxf(x6,0.f),fmaxf(x7,0.f));
    }
}

__global__ __launch_bounds__(128, 3) void node_kernel(
    const float* __restrict__ mW1, const float* __restrict__ mb1,
    const float* __restrict__ mW2, const float* __restrict__ mb2,
    const float* __restrict__ mW3, const float* __restrict__ mb3,
    const float* __restrict__ vW1, const float* __restrict__ vb1,
    const float* __restrict__ vW2, const float* __restrict__ vb2,
    const float* __restrict__ vW3, const float* __restrict__ vb3,
    float* __restrict__ out, int t)
{
    extern __shared__ char smem_raw[];
    NodeSmem& S = *reinterpret_cast<NodeSmem*>(smem_raw);

    const int tid = threadIdx.x;
    const int p   = blockIdx.x;       // 0..511
    const int is_var = blockIdx.y;
    const int bs  = p >> 4;           // 0..31
    const int c0  = p & 15;           // samples c0 + 16*smp

    const float* W1 = is_var ? vW1 : mW1;
    const float* W2 = is_var ? vW2 : mW2;
    const float* W3 = is_var ? vW3 : mW3;
    const float* b1 = is_var ? vb1 : mb1;
    const float* b2 = is_var ? vb2 : mb2;
    const float* b3 = is_var ? vb3 : mb3;

    {
        const float4* w1v = reinterpret_cast<const float4*>(W1);
        float4* s1 = reinterpret_cast<float4*>(S.sW);
        #pragma unroll
        for (int i = tid; i < 1024; i += 128) s1[i] = w1v[i];
        S.sW3[tid] = W3[tid]; S.sW3[tid+128] = W3[tid+128];
    }
    if (tid < 64) { S.sb1[tid] = b1[tid]; S.sb2[tid] = b2[tid]; }
    if (tid < 4)  S.sb3[tid] = b3[tid];
    if (tid >= 4 && tid < 8) S.sb3[tid] = 0.f;

    // load 4 samples of agg: 1920 float4, 15 per thread
    {
        const float4* ab = reinterpret_cast<const float4*>(g_agg);
        #pragma unroll
        for (int v = tid; v < 1920; v += 128) {
            int smp = v / 480, vv = v - smp*480;
            int row = vv >> 4, cp = vv & 15;
            float4 val = ab[(size_t)(bs*64 + c0 + 16*smp)*480 + vv];
            *reinterpret_cast<float4*>(&S.buf[smp*30 + row][cp*4]) = val;
        }
    }
    __syncthreads();

    const int ig = tid >> 3, cg = tid & 7;
    const int og = cg*8;
    const float* r0 = &S.buf[ig*8][0];
    float*       w0 = &S.buf[ig*8][og];

    ull acc[8][4];
    // Layer 1 (sW = W1)
    if (tid < 120) gemm8_compute(r0, S.sW, S.sb1, og, acc);
    __syncthreads();
    if (tid < 120) gemm8_store_relu(w0, acc);
    {
        const float4* w2v = reinterpret_cast<const float4*>(W2);
        float4* s1 = reinterpret_cast<float4*>(S.sW);
        #pragma unroll
        for (int i = tid; i < 1024; i += 128) s1[i] = w2v[i];
    }
    __syncthreads();
    // Layer 2 (sW = W2)
    if (tid < 120) gemm8_compute(r0, S.sW, S.sb2, og, acc);
    __syncthreads();
    if (tid < 120) gemm8_store_relu(w0, acc);
    __syncthreads();

    // Layer 3: 64 -> 4. 120 threads, one instance each.
    if (tid < 120) {
        const int smp = tid / 30, n = tid - smp*30;
        const float* hr = &S.buf[tid][0];
        ulonglong2 b3q = *reinterpret_cast<const ulonglong2*>(&S.sb3[0]);
        ull a01 = b3q.x, a23 = b3q.y;
        #pragma unroll 4
        for (int k4 = 0; k4 < 64; k4 += 4) {
            float4 hv = *reinterpret_cast<const float4*>(hr + k4);
            float ha[4] = {hv.x, hv.y, hv.z, hv.w};
            #pragma unroll
            for (int kk = 0; kk < 4; kk++) {
                ulonglong2 w = *reinterpret_cast<const ulonglong2*>(&S.sW3[(k4+kk)*4]);
                ull hd; PACKDUP(hd, ha[kk]);
                FFMA2(a01, hd, w.x);
                FFMA2(a23, hd, w.y);
            }
        }
        float v0,v1,v2,v3;
        UNPACK2(v0,v1,a01); UNPACK2(v2,v3,a23);
        float v[4] = {v0,v1,v2,v3};
        if (is_var) {
            #pragma unroll
            for (int q = 0; q < 4; q++) {
                float x = v[q];
                float sp = (x > 20.f) ? x : log1pf(expf(x));
                v[q] = fminf(fmaxf(sp, 1e-8f), 100.f);
            }
        }
        const int c = c0 + 16*smp;
        const int s = bs*64 + c;
        if (!is_var && t == 0)
            *reinterpret_cast<float4*>(&g_mu[(size_t)s*120 + n*4]) =
                make_float4(v[0],v[1],v[2],v[3]);
        const int kt = 2*c + t;
        if (kt < TOUT) {
            size_t o = (((size_t)bs*TOUT + kt)*NN + n)*FF;
            *reinterpret_cast<float4*>(&out[o + (is_var ? (size_t)VAROFF : 0)]) =
                make_float4(v[0],v[1],v[2],v[3]);
        }
    }
}

// ---------------------------------------------------------------------------
extern "C" void kernel_launch(void* const* d_in, const int* in_sizes, int n_in,
                              void* d_out, int out_size) {
    const float* data    = (const float*)d_in[0];
    const float* graph   = (const float*)d_in[1];
    const float* msg_W1  = (const float*)d_in[2];
    const float* msg_b1  = (const float*)d_in[3];
    const float* msg_W2  = (const float*)d_in[4];
    const float* msg_b2  = (const float*)d_in[5];
    const float* mean_W1 = (const float*)d_in[6];
    const float* mean_b1 = (const float*)d_in[7];
    const float* mean_W2 = (const float*)d_in[8];
    const float* mean_b2 = (const float*)d_in[9];
    const float* mean_W3 = (const float*)d_in[10];
    const float* mean_b3 = (const float*)d_in[11];
    const float* var_W1  = (const float*)d_in[12];
    const float* var_b1  = (const float*)d_in[13];
    const float* var_W2  = (const float*)d_in[14];
    const float* var_b2  = (const float*)d_in[15];
    const float* var_W3  = (const float*)d_in[16];
    const float* var_b3  = (const float*)d_in[17];
    float* out = (float*)d_out;

    cudaFuncSetAttribute(edge_kernel, cudaFuncAttributeMaxDynamicSharedMemorySize,
                         (int)sizeof(EdgeSmem));
    cudaFuncSetAttribute(node_kernel, cudaFuncAttributeMaxDynamicSharedMemorySize,
                         (int)sizeof(NodeSmem));

    dim3 ngrid(NSAMP/4, 2);
    for (int t = 0; t < 2; t++) {
        edge_kernel<<<NSAMP/2, 128, sizeof(EdgeSmem)>>>(data, t, graph,
                                    msg_W1, msg_b1, msg_W2, msg_b2);
        node_kernel<<<ngrid, 128, sizeof(NodeSmem)>>>(
            mean_W1, mean_b1, mean_W2, mean_b2, mean_W3, mean_b3,
            var_W1,  var_b1,  var_W2,  var_b2,  var_W3,  var_b3,
            out, t);
    }
}

// round 11
// speedup vs baseline: 4.5637x; 1.0672x over previous
#include <cuda_runtime.h>
#include <math.h>

typedef unsigned long long ull;

#define NN 30
#define FF 4
#define HH 64
#define NSAMP 2048          // 32 * 64
#define TOUT 127
#define VAROFF (32*127*30*4)
#define AST 68              // activation row stride (floats), bank-staggered
#define GS  (8*AST + 4)     // 548: 8-row group stride; +4 staggers groups across banks
#define GST 36              // dense-graph row stride (floats), bank-staggered

// Scratch (allocation-free rule: __device__ globals)
__device__ float g_agg[(size_t)NSAMP * NN * HH];   // 15.7 MB
__device__ float g_mu [(size_t)NSAMP * NN * FF];   // 0.98 MB

// ---- packed f32x2 helpers (sm_103a) ---------------------------------------
#define FFMA2(acc, a, b) \
    asm("fma.rn.f32x2 %0, %1, %2, %0;" : "+l"(acc) : "l"(a), "l"(b))
#define MUL2(d, a, b) \
    asm("mul.rn.f32x2 %0, %1, %2;" : "=l"(d) : "l"(a), "l"(b))
#define PACKDUP(d, x) \
    asm("mov.b64 %0, {%1, %1};" : "=l"(d) : "r"(__float_as_uint(x)))
#define UNPACK2(x, y, p) \
    asm("mov.b64 {%0, %1}, %2;" : "=f"(x), "=f"(y) : "l"(p))
// acc += gdup * relu(apair + bpair)
#define AGG_STEP(acc, apair, bpair, gdup) \
    asm("{\n\t.reg .b32 lo, hi;\n\t.reg .b64 t;\n\t" \
        "add.rn.f32x2 t, %1, %2;\n\t" \
        "mov.b64 {lo, hi}, t;\n\t" \
        "max.f32 lo, lo, 0f00000000;\n\t" \
        "max.f32 hi, hi, 0f00000000;\n\t" \
        "mov.b64 t, {lo, hi};\n\t" \
        "fma.rn.f32x2 %0, %3, t, %0;\n\t}" \
        : "+l"(acc) : "l"(apair), "l"(bpair), "l"(gdup))

// ---------------------------------------------------------------------------
// Edge kernel: 2 samples per CTA, 128 threads (all active).
// sB is flat with group-padded rows: row gr (0..63, = smp*32 + local) lives at
// (gr>>3)*GS + (gr&7)*AST. Stage A: thread = (smp, 4-row group, 8 cols).
// Stage B: thread = (8-row group, 4 cols). H overwrites sB between stages.
// ---------------------------------------------------------------------------
struct EdgeSmem {
    float sW2[64*64];           // 16 KB
    float sW1[8*64];            //  2 KB
    float sB[8*GS];             // 17.5 KB : 64 rows in 8 groups ; becomes H
    float sgm[32][GST];         //  4.5 KB dense graph, zero diag + pad rows
    float sx[2][128];           //  1 KB (tail zeroed)
    float scnt[64];             // flat gr = smp*32 + row
    float sb1[64];
    float sb2[64];
};

__global__ __launch_bounds__(128, 5) void edge_kernel(
    const float* __restrict__ data, int mode,
    const float* __restrict__ graph,
    const float* __restrict__ W1, const float* __restrict__ b1,
    const float* __restrict__ W2, const float* __restrict__ b2)
{
    extern __shared__ char smem_raw[];
    EdgeSmem& S = *reinterpret_cast<EdgeSmem*>(smem_raw);

    const int tid = threadIdx.x;
    const int p   = blockIdx.x;
    const int bs  = p >> 5;
    const int c0  = p & 31;

    {
        const float4* w2v = reinterpret_cast<const float4*>(W2);
        float4* d2 = reinterpret_cast<float4*>(S.sW2);
        #pragma unroll
        for (int i = tid; i < 1024; i += 128) d2[i] = w2v[i];
        const float4* w1v = reinterpret_cast<const float4*>(W1);
        float4* d1 = reinterpret_cast<float4*>(S.sW1);
        d1[tid] = w1v[tid];
    }
    if (tid < 64) { S.sb1[tid] = b1[tid]; S.sb2[tid] = b2[tid]; }
    for (int e = tid; e < 900; e += 128) {
        int i = e / 30, j = e - i*30;
        S.sgm[i][j] = (i == j) ? 0.f
                      : graph[(size_t)bs*870 + i*29 + j - (j > i)];
    }
    if (tid < 30) { S.sgm[tid][30] = 0.f; S.sgm[tid][31] = 0.f; }
    if (tid < 64) S.sgm[30 + (tid >> 5)][tid & 31] = 0.f;      // pad g rows
    if (tid < 68) {                                            // zero pad rows
        S.sB[3*GS + 6*AST + tid] = 0.f;   // gr 30
        S.sB[3*GS + 7*AST + tid] = 0.f;   // gr 31
        S.sB[7*GS + 6*AST + tid] = 0.f;   // gr 62
        S.sB[7*GS + 7*AST + tid] = 0.f;   // gr 63
    }
    if (tid < 16) S.sx[tid >> 3][120 + (tid & 7)] = 0.f;       // pad x tail
    if (tid < 4)  S.scnt[((tid >> 1) << 5) + 30 + (tid & 1)] = 0.f;
    for (int v = tid; v < 240; v += 128) {
        int h = v >= 120, idx = v - 120*h;
        int cc = c0 + 32*h, ss = bs*64 + cc;
        S.sx[h][idx] = (mode == 0)
            ? data[((size_t)bs*128 + 2*cc)*120 + idx]
            : g_mu[(size_t)ss*120 + idx];
    }
    __syncthreads();

    // ---- Stage A mapping: smp, rows r0..r0+3 (same sample), cols og..og+7
    const int smp = tid >> 6;
    const int rg  = (tid >> 3) & 7;
    const int cg  = tid & 7;
    const int r0  = rg * 4;
    const int og  = cg * 8;

    ull aA[4][4];               // A-projection, registers
    // ---- projections: A (registers) + B (smem) ----
    {
        float xr[4][4];
        #pragma unroll
        for (int rr = 0; rr < 4; rr++) {
            float4 xv = *reinterpret_cast<const float4*>(&S.sx[smp][(r0+rr)*4]);
            xr[rr][0]=xv.x; xr[rr][1]=xv.y; xr[rr][2]=xv.z; xr[rr][3]=xv.w;
        }
        ull aB[4][4];
        {
            ulonglong2 bq0 = *reinterpret_cast<const ulonglong2*>(&S.sb1[og]);
            ulonglong2 bq1 = *reinterpret_cast<const ulonglong2*>(&S.sb1[og+4]);
            ull bp[4] = {bq0.x, bq0.y, bq1.x, bq1.y};
            #pragma unroll
            for (int rr = 0; rr < 4; rr++)
                #pragma unroll
                for (int q = 0; q < 4; q++) { aA[rr][q] = bp[q]; aB[rr][q] = 0ULL; }
        }
        #pragma unroll
        for (int f = 0; f < 4; f++) {
            ulonglong2 wa0 = *reinterpret_cast<const ulonglong2*>(&S.sW1[f*64+og]);
            ulonglong2 wa1 = *reinterpret_cast<const ulonglong2*>(&S.sW1[f*64+og+4]);
            ulonglong2 wb0 = *reinterpret_cast<const ulonglong2*>(&S.sW1[(f+4)*64+og]);
            ulonglong2 wb1 = *reinterpret_cast<const ulonglong2*>(&S.sW1[(f+4)*64+og+4]);
            ull wa[4] = {wa0.x, wa0.y, wa1.x, wa1.y};
            ull wb[4] = {wb0.x, wb0.y, wb1.x, wb1.y};
            #pragma unroll
            for (int rr = 0; rr < 4; rr++) {
                ull xd; PACKDUP(xd, xr[rr][f]);
                #pragma unroll
                for (int q = 0; q < 4; q++) {
                    FFMA2(aA[rr][q], xd, wa[q]);
                    FFMA2(aB[rr][q], xd, wb[q]);
                }
            }
        }
        #pragma unroll
        for (int rr = 0; rr < 4; rr++) {
            int lr = r0 + rr;
            if (lr < 30) {
                float* dst = S.sB + (smp*4 + (lr>>3))*GS + (lr&7)*AST + og;
                ulonglong2 s0; s0.x = aB[rr][0]; s0.y = aB[rr][1];
                ulonglong2 s1; s1.x = aB[rr][2]; s1.y = aB[rr][3];
                *reinterpret_cast<ulonglong2*>(dst)   = s0;
                *reinterpret_cast<ulonglong2*>(dst+4) = s1;
            }
        }
    }
    __syncthreads();

    // ---- masked-ReLU aggregation: B[j] load serves 4 rows ----
    ull acc[4][4];
    float cnt[4] = {0.f, 0.f, 0.f, 0.f};
    {
        #pragma unroll
        for (int rr = 0; rr < 4; rr++)
            #pragma unroll
            for (int q = 0; q < 4; q++) acc[rr][q] = 0ULL;

        #pragma unroll
        for (int jg = 0; jg < 4; jg++) {
            const float* bg = S.sB + (smp*4 + jg)*GS + og;
            #pragma unroll
            for (int jh = 0; jh < 2; jh++) {
                const int j4 = jg*8 + jh*4;
                float ga[4][4];
                #pragma unroll
                for (int rr = 0; rr < 4; rr++) {
                    float4 gv = *reinterpret_cast<const float4*>(&S.sgm[r0+rr][j4]);
                    ga[rr][0]=gv.x; ga[rr][1]=gv.y; ga[rr][2]=gv.z; ga[rr][3]=gv.w;
                    cnt[rr] += gv.x + gv.y + gv.z + gv.w;
                }
                #pragma unroll
                for (int jj = 0; jj < 4; jj++) {
                    const float* bj = bg + (jh*4 + jj)*AST;
                    ulonglong2 b0 = *reinterpret_cast<const ulonglong2*>(bj);
                    ulonglong2 b1v = *reinterpret_cast<const ulonglong2*>(bj+4);
                    ull bv[4] = {b0.x, b0.y, b1v.x, b1v.y};
                    #pragma unroll
                    for (int rr = 0; rr < 4; rr++) {
                        ull gd; PACKDUP(gd, ga[rr][jj]);
                        #pragma unroll
                        for (int q = 0; q < 4; q++)
                            AGG_STEP(acc[rr][q], aA[rr][q], bv[q], gd);
                    }
                }
            }
        }
    }
    __syncthreads();            // all sB reads complete
    {
        #pragma unroll
        for (int rr = 0; rr < 4; rr++) {
            int lr = r0 + rr;
            if (lr < 30) {
                float* dst = S.sB + (smp*4 + (lr>>3))*GS + (lr&7)*AST + og;
                ulonglong2 s0; s0.x = acc[rr][0]; s0.y = acc[rr][1];
                ulonglong2 s1; s1.x = acc[rr][2]; s1.y = acc[rr][3];
                *reinterpret_cast<ulonglong2*>(dst)   = s0;
                *reinterpret_cast<ulonglong2*>(dst+4) = s1;
            }
        }
        if (cg == 0) {
            #pragma unroll
            for (int rr = 0; rr < 4; rr++)
                if (r0 + rr < 30) S.scnt[smp*32 + r0 + rr] = cnt[rr];
        }
    }
    __syncthreads();

    // ---- Stage B: agg = H @ W2 + cnt*b2. 8 rows x 4 cols per thread. ----
    {
        const int rg2 = tid >> 4;          // 0..7 : group rg2 = rows rg2*8..+7
        const int oc  = (tid & 15) * 4;    // 0..60
        const float* hb = S.sB + rg2*GS;
        ull acc2[8][2];
        {
            ulonglong2 b2p = *reinterpret_cast<const ulonglong2*>(&S.sb2[oc]);
            #pragma unroll
            for (int r = 0; r < 8; r++) {
                ull cd; PACKDUP(cd, S.scnt[rg2*8 + r]);
                MUL2(acc2[r][0], cd, b2p.x);
                MUL2(acc2[r][1], cd, b2p.y);
            }
        }
        #pragma unroll 2
        for (int k4 = 0; k4 < 64; k4 += 4) {
            ulonglong2 w[4];
            #pragma unroll
            for (int kk = 0; kk < 4; kk++)
                w[kk] = *reinterpret_cast<const ulonglong2*>(&S.sW2[(k4+kk)*64 + oc]);
            float4 hv[8];
            #pragma unroll
            for (int r = 0; r < 8; r++)
                hv[r] = *reinterpret_cast<const float4*>(hb + r*AST + k4);
            float ha[8][4];
            #pragma unroll
            for (int r = 0; r < 8; r++) {
                ha[r][0]=hv[r].x; ha[r][1]=hv[r].y; ha[r][2]=hv[r].z; ha[r][3]=hv[r].w;
            }
            #pragma unroll
            for (int kk = 0; kk < 4; kk++) {
                #pragma unroll
                for (int r = 0; r < 8; r++) {
                    ull hd; PACKDUP(hd, ha[r][kk]);
                    FFMA2(acc2[r][0], hd, w[kk].x);
                    FFMA2(acc2[r][1], hd, w[kk].y);
                }
            }
        }
        const int sb0 = bs*64 + c0;
        #pragma unroll
        for (int r = 0; r < 8; r++) {
            int gr = rg2*8 + r;
            int sm2 = gr >> 5, row = gr & 31;
            if (row < 30) {
                size_t base = ((size_t)(sb0 + 32*sm2)*NN + row)*HH + oc;
                ulonglong2 st; st.x = acc2[r][0]; st.y = acc2[r][1];
                *reinterpret_cast<ulonglong2*>(&g_agg[base]) = st;
            }
        }
    }
}

// ---------------------------------------------------------------------------
// Node MLP kernel: 64 ->relu-> 64 ->relu-> 64 -> 4. 4 samples/CTA, 128 thr.
// 8-row x 8-col register tiles. buf is flat group-padded: row inst (0..119)
// at (inst>>3)*GS + (inst&7)*AST -> ig-groups hit distinct banks.
// Single weight buffer. blockIdx.y selects mean(0)/var(1).
// ---------------------------------------------------------------------------
struct NodeSmem {
    float sW[64*64];            // 16 KB, W1 then W2
    float sW3[64*4];
    float buf[15*GS];           // 32.9 KB : 120 rows in 15 groups of 8
    float sb1[64];
    float sb2[64];
    float sb3[8];
};

__device__ __forceinline__ void gemm8_compute(
    const float* __restrict__ r0,      // &buf[ig*GS]
    const float* __restrict__ sW, const float* __restrict__ sb,
    int og, ull acc[8][4])
{
    {
        ulonglong2 bq0 = *reinterpret_cast<const ulonglong2*>(&sb[og]);
        ulonglong2 bq1 = *reinterpret_cast<const ulonglong2*>(&sb[og+4]);
        ull bp[4] = {bq0.x, bq0.y, bq1.x, bq1.y};
        #pragma unroll
        for (int r = 0; r < 8; r++)
            #pragma unroll
            for (int q = 0; q < 4; q++) acc[r][q] = bp[q];
    }
    #pragma unroll 2
    for (int k4 = 0; k4 < 64; k4 += 4) {
        float4 hv[8];
        #pragma unroll
        for (int r = 0; r < 8; r++)
            hv[r] = *reinterpret_cast<const float4*>(r0 + r*AST + k4);
        float ha[8][4];
        #pragma unroll
        for (int r = 0; r < 8; r++) {
            ha[r][0]=hv[r].x; ha[r][1]=hv[r].y; ha[r][2]=hv[r].z; ha[r][3]=hv[r].w;
        }
        #pragma unroll
        for (int kk = 0; kk < 4; kk++) {
            ulonglong2 w0 = *reinterpret_cast<const ulonglong2*>(&sW[(k4+kk)*64+og]);
            ulonglong2 w1 = *reinterpret_cast<const ulonglong2*>(&sW[(k4+kk)*64+og+4]);
            ull wv[4] = {w0.x, w0.y, w1.x, w1.y};
            #pragma unroll
            for (int r = 0; r < 8; r++) {
                ull hd; PACKDUP(hd, ha[r][kk]);
                #pragma unroll
                for (int q = 0; q < 4; q++) FFMA2(acc[r][q], hd, wv[q]);
            }
        }
    }
}

__device__ __forceinline__ void gemm8_store_relu(
    float* __restrict__ w0, ull acc[8][4])   // w0 = &buf[ig*GS + og]
{
    #pragma unroll
    for (int r = 0; r < 8; r++) {
        float* dst = w0 + r*AST;
        float x0,x1,x2,x3,x4,x5,x6,x7;
        UNPACK2(x0,x1,acc[r][0]); UNPACK2(x2,x3,acc[r][1]);
        UNPACK2(x4,x5,acc[r][2]); UNPACK2(x6,x7,acc[r][3]);
        *reinterpret_cast<float4*>(dst) =
            make_float4(fmaxf(x0,0.f),fmaxf(x1,0.f),fmaxf(x2,0.f),fmaxf(x3,0.f));
        *reinterpret_cast<float4*>(dst+4) =
            make_float4(fmaxf(x4,0.f),fmaxf(x5,0.f),fmaxf(x6,0.f),fmaxf(x7,0.f));
    }
}

__global__ __launch_bounds__(128, 3) void node_kernel(
    const float* __restrict__ mW1, const float* __restrict__ mb1,
    const float* __restrict__ mW2, const float* __restrict__ mb2,
    const float* __restrict__ mW3, const float* __restrict__ mb3,
    const float* __restrict__ vW1, const float* __restrict__ vb1,
    const float* __restrict__ vW2, const float* __restrict__ vb2,
    const float* __restrict__ vW3, const float* __restrict__ vb3,
    float* __restrict__ out, int t)
{
    extern __shared__ char smem_raw[];
    NodeSmem& S = *reinterpret_cast<NodeSmem*>(smem_raw);

    const int tid = threadIdx.x;
    const int p   = blockIdx.x;       // 0..511
    const int is_var = blockIdx.y;
    const int bs  = p >> 4;           // 0..31
    const int c0  = p & 15;           // samples c0 + 16*smp

    const float* W1 = is_var ? vW1 : mW1;
    const float* W2 = is_var ? vW2 : mW2;
    const float* W3 = is_var ? vW3 : mW3;
    const float* b1 = is_var ? vb1 : mb1;
    const float* b2 = is_var ? vb2 : mb2;
    const float* b3 = is_var ? vb3 : mb3;

    {
        const float4* w1v = reinterpret_cast<const float4*>(W1);
        float4* s1 = reinterpret_cast<float4*>(S.sW);
        #pragma unroll
        for (int i = tid; i < 1024; i += 128) s1[i] = w1v[i];
        S.sW3[tid] = W3[tid]; S.sW3[tid+128] = W3[tid+128];
    }
    if (tid < 64) { S.sb1[tid] = b1[tid]; S.sb2[tid] = b2[tid]; }
    if (tid < 4)  S.sb3[tid] = b3[tid];
    if (tid >= 4 && tid < 8) S.sb3[tid] = 0.f;

    // load 4 samples of agg: 1920 float4, 15 per thread
    {
        const float4* ab = reinterpret_cast<const float4*>(g_agg);
        #pragma unroll
        for (int v = tid; v < 1920; v += 128) {
            int smp = v / 480, vv = v - smp*480;
            int row = vv >> 4, cp = vv & 15;
            int inst = smp*30 + row;
            float4 val = ab[(size_t)(bs*64 + c0 + 16*smp)*480 + vv];
            *reinterpret_cast<float4*>(&S.buf[(inst>>3)*GS + (inst&7)*AST + cp*4]) = val;
        }
    }
    __syncthreads();

    const int ig = tid >> 3, cg = tid & 7;
    const int og = cg*8;
    const float* r0 = &S.buf[ig*GS];
    float*       w0 = &S.buf[ig*GS + og];

    ull acc[8][4];
    // Layer 1 (sW = W1)
    if (tid < 120) gemm8_compute(r0, S.sW, S.sb1, og, acc);
    __syncthreads();
    if (tid < 120) gemm8_store_relu(w0, acc);
    {
        const float4* w2v = reinterpret_cast<const float4*>(W2);
        float4* s1 = reinterpret_cast<float4*>(S.sW);
        #pragma unroll
        for (int i = tid; i < 1024; i += 128) s1[i] = w2v[i];
    }
    __syncthreads();
    // Layer 2 (sW = W2)
    if (tid < 120) gemm8_compute(r0, S.sW, S.sb2, og, acc);
    __syncthreads();
    if (tid < 120) gemm8_store_relu(w0, acc);
    __syncthreads();

    // Layer 3: 64 -> 4. 120 threads, one instance each.
    if (tid < 120) {
        const int smp = tid / 30, n = tid - smp*30;
        const float* hr = &S.buf[(tid>>3)*GS + (tid&7)*AST];
        ulonglong2 b3q = *reinterpret_cast<const ulonglong2*>(&S.sb3[0]);
        ull a01 = b3q.x, a23 = b3q.y;
        #pragma unroll 4
        for (int k4 = 0; k4 < 64; k4 += 4) {
            float4 hv = *reinterpret_cast<const float4*>(hr + k4);
            float ha[4] = {hv.x, hv.y, hv.z, hv.w};
            #pragma unroll
            for (int kk = 0; kk < 4; kk++) {
                ulonglong2 w = *reinterpret_cast<const ulonglong2*>(&S.sW3[(k4+kk)*4]);
                ull hd; PACKDUP(hd, ha[kk]);
                FFMA2(a01, hd, w.x);
                FFMA2(a23, hd, w.y);
            }
        }
        float v0,v1,v2,v3;
        UNPACK2(v0,v1,a01); UNPACK2(v2,v3,a23);
        float v[4] = {v0,v1,v2,v3};
        if (is_var) {
            #pragma unroll
            for (int q = 0; q < 4; q++) {
                float x = v[q];
                float sp = (x > 20.f) ? x : log1pf(expf(x));
                v[q] = fminf(fmaxf(sp, 1e-8f), 100.f);
            }
        }
        const int c = c0 + 16*smp;
        const int s = bs*64 + c;
        if (!is_var && t == 0)
            *reinterpret_cast<float4*>(&g_mu[(size_t)s*120 + n*4]) =
                make_float4(v[0],v[1],v[2],v[3]);
        const int kt = 2*c + t;
        if (kt < TOUT) {
            size_t o = (((size_t)bs*TOUT + kt)*NN + n)*FF;
            *reinterpret_cast<float4*>(&out[o + (is_var ? (size_t)VAROFF : 0)]) =
                make_float4(v[0],v[1],v[2],v[3]);
        }
    }
}

// ---------------------------------------------------------------------------
extern "C" void kernel_launch(void* const* d_in, const int* in_sizes, int n_in,
                              void* d_out, int out_size) {
    const float* data    = (const float*)d_in[0];
    const float* graph   = (const float*)d_in[1];
    const float* msg_W1  = (const float*)d_in[2];
    const float* msg_b1  = (const float*)d_in[3];
    const float* msg_W2  = (const float*)d_in[4];
    const float* msg_b2  = (const float*)d_in[5];
    const float* mean_W1 = (const float*)d_in[6];
    const float* mean_b1 = (const float*)d_in[7];
    const float* mean_W2 = (const float*)d_in[8];
    const float* mean_b2 = (const float*)d_in[9];
    const float* mean_W3 = (const float*)d_in[10];
    const float* mean_b3 = (const float*)d_in[11];
    const float* var_W1  = (const float*)d_in[12];
    const float* var_b1  = (const float*)d_in[13];
    const float* var_W2  = (const float*)d_in[14];
    const float* var_b2  = (const float*)d_in[15];
    const float* var_W3  = (const float*)d_in[16];
    const float* var_b3  = (const float*)d_in[17];
    float* out = (float*)d_out;

    cudaFuncSetAttribute(edge_kernel, cudaFuncAttributeMaxDynamicSharedMemorySize,
                         (int)sizeof(EdgeSmem));
    cudaFuncSetAttribute(node_kernel, cudaFuncAttributeMaxDynamicSharedMemorySize,
                         (int)sizeof(NodeSmem));

    dim3 ngrid(NSAMP/4, 2);
    for (int t = 0; t < 2; t++) {
        edge_kernel<<<NSAMP/2, 128, sizeof(EdgeSmem)>>>(data, t, graph,
                                    msg_W1, msg_b1, msg_W2, msg_b2);
        node_kernel<<<ngrid, 128, sizeof(NodeSmem)>>>(
            mean_W1, mean_b1, mean_W2, mean_b2, mean_W3, mean_b3,
            var_W1,  var_b1,  var_W2,  var_b2,  var_W3,  var_b3,
            out, t);
    }
}